// round 5
// baseline (speedup 1.0000x reference)
#include <cuda_runtime.h>
#include <cuda_bf16.h>
#include <stdint.h>
#include <math.h>

// ---------------------------------------------------------------------------
// Problem constants: B=4, S=1024, H=1024, HEADS=16, HEAD_D=64, K=2048
// ---------------------------------------------------------------------------
#define PLANE 2097152ull   // 1024*2048

// ---------------- scratch ----------------
__device__ float        g_SC  [(size_t)64 * PLANE];           // fused scores [z][i][j]
__device__ __nv_bfloat16 g_ATTh[(size_t)64 * PLANE];          // attn weights (single bf16)

__device__ __nv_bfloat16 g_TEh [(size_t)4096*1024], g_TEl [(size_t)4096*1024];
__device__ __nv_bfloat16 g_KVh [(size_t)8192*1024], g_KVl [(size_t)8192*1024];
__device__ __nv_bfloat16 g_RELh[(size_t)2048*1024], g_RELl[(size_t)2048*1024];
__device__ __nv_bfloat16 g_Wh  [(size_t)5*1024*1024], g_Wl [(size_t)5*1024*1024];
__device__ __nv_bfloat16 g_QUh [(size_t)4096*1024], g_QUl [(size_t)4096*1024];
__device__ __nv_bfloat16 g_QVh [(size_t)4096*1024], g_QVl [(size_t)4096*1024];
__device__ __nv_bfloat16 g_Kh  [(size_t)8192*1024], g_Kl  [(size_t)8192*1024];
__device__ __nv_bfloat16 g_Rh  [(size_t)2048*1024], g_Rl  [(size_t)2048*1024];
__device__ __nv_bfloat16 g_Vh  [(size_t)8192*1024], g_Vl  [(size_t)8192*1024];
__device__ __nv_bfloat16 g_O1h [(size_t)4096*1024], g_O1l [(size_t)4096*1024];

// ---------------------------------------------------------------------------
// Low-level helpers (sm_80-compatible: ldmatrix / mma.sync / cp.async)
// ---------------------------------------------------------------------------
__device__ __forceinline__ uint32_t smem_u32(const void* p) {
    uint32_t a;
    asm("{ .reg .u64 t; cvta.to.shared.u64 t, %1; cvt.u32.u64 %0, t; }"
        : "=r"(a) : "l"(p));
    return a;
}
__device__ __forceinline__ void ldsm4(uint32_t* r, uint32_t a) {
    asm volatile("ldmatrix.sync.aligned.m8n8.x4.shared.b16 {%0,%1,%2,%3}, [%4];"
        : "=r"(r[0]), "=r"(r[1]), "=r"(r[2]), "=r"(r[3]) : "r"(a));
}
__device__ __forceinline__ void ldsm4t(uint32_t* r, uint32_t a) {
    asm volatile("ldmatrix.sync.aligned.m8n8.x4.trans.shared.b16 {%0,%1,%2,%3}, [%4];"
        : "=r"(r[0]), "=r"(r[1]), "=r"(r[2]), "=r"(r[3]) : "r"(a));
}
__device__ __forceinline__ void mma16816(float* c, const uint32_t* a, const uint32_t* b) {
    asm volatile(
        "mma.sync.aligned.m16n8k16.row.col.f32.bf16.bf16.f32 "
        "{%0,%1,%2,%3}, {%4,%5,%6,%7}, {%8,%9}, {%0,%1,%2,%3};"
        : "+f"(c[0]), "+f"(c[1]), "+f"(c[2]), "+f"(c[3])
        : "r"(a[0]), "r"(a[1]), "r"(a[2]), "r"(a[3]), "r"(b[0]), "r"(b[1]));
}
#define CP_ASYNC(dst, src) \
    asm volatile("cp.async.cg.shared.global [%0], [%1], 16;" :: "r"(dst), "l"(src))
#define CP_COMMIT() asm volatile("cp.async.commit_group;" ::: "memory")
#define CP_WAIT1()  asm volatile("cp.async.wait_group 1;" ::: "memory")
#define CP_WAIT0()  asm volatile("cp.async.wait_group 0;" ::: "memory")

__device__ __forceinline__ void split2(float x, float y,
                                       __nv_bfloat162& h, __nv_bfloat162& l) {
    __nv_bfloat16 hx = __float2bfloat16(x), hy = __float2bfloat16(y);
    h = __halves2bfloat162(hx, hy);
    l = __halves2bfloat162(__float2bfloat16(x - __bfloat162float(hx)),
                           __float2bfloat16(y - __bfloat162float(hy)));
}

// ---------------------------------------------------------------------------
// split fp32 -> bf16 hi/lo (generic)
// ---------------------------------------------------------------------------
__global__ void split_bf16(const float4* __restrict__ in,
                           __nv_bfloat162* __restrict__ hi,
                           __nv_bfloat162* __restrict__ lo, int n4)
{
    int i = blockIdx.x * blockDim.x + threadIdx.x;
    if (i >= n4) return;
    float4 x = in[i];
    __nv_bfloat162 h0, l0, h1, l1;
    split2(x.x, x.y, h0, l0);
    split2(x.z, x.w, h1, l1);
    hi[i*2+0] = h0; hi[i*2+1] = h1;
    lo[i*2+0] = l0; lo[i*2+1] = l1;
}

// split 5 weight matrices in one launch
__global__ void split5_w(const float4* w0, const float4* w1, const float4* w2,
                         const float4* w3, const float4* w4,
                         __nv_bfloat162* __restrict__ hi,
                         __nv_bfloat162* __restrict__ lo)
{
    const float4* srcs[5] = {w0, w1, w2, w3, w4};
    int which = blockIdx.y;
    int i = blockIdx.x * blockDim.x + threadIdx.x;      // 0..262143
    float4 x = srcs[which][i];
    size_t d = (size_t)which * 524288 + (size_t)i * 2;
    __nv_bfloat162 h0, l0, h1, l1;
    split2(x.x, x.y, h0, l0);
    split2(x.z, x.w, h1, l1);
    hi[d] = h0; hi[d+1] = h1;
    lo[d] = l0; lo[d+1] = l1;
}

// gather kv_in (natural flat order row = b*2048+j) + split to bf16 hi/lo
__global__ void gather_split_kv(const float4* __restrict__ te,
                                const float4* __restrict__ mems)
{
    int idx = blockIdx.x * blockDim.x + threadIdx.x;    // 8192*256
    int row = idx >> 8, c = idx & 255;
    int b = row >> 11, j = row & 2047;
    float4 x;
    if (j < 1024) x = te  [((size_t)b * 1024 + j) * 256 + c];
    else          x = mems[((size_t)b * 2048 + (j - 1024)) * 256 + c];
    __nv_bfloat162 h0, l0, h1, l1;
    split2(x.x, x.y, h0, l0);
    split2(x.z, x.w, h1, l1);
    ((__nv_bfloat162*)g_KVh)[idx*2]   = h0;
    ((__nv_bfloat162*)g_KVh)[idx*2+1] = h1;
    ((__nv_bfloat162*)g_KVl)[idx*2]   = l0;
    ((__nv_bfloat162*)g_KVl)[idx*2+1] = l1;
}

// ---------------------------------------------------------------------------
// HMMA GEMM: C[M,1024] = A[M,1024] @ W[1024,1024]^T + bias, bf16-split 3-term.
// 128x128 CTA tile, BK=32, 8 warps (64x32), cp.async double-buffer.
// Epilogue modes: 0 = fp32+bias -> C; 1 = bias+split -> o1; 2 = dual split
// (bias+u -> o1, bias+v -> o2).
// ---------------------------------------------------------------------------
#define GLD 40
#define GTB 10240

__device__ __forceinline__ void gemm_issue(
    uint32_t sb, int buf, int c, int tid,
    const __nv_bfloat16* Ah, const __nv_bfloat16* Al,
    const __nv_bfloat16* Wh, const __nv_bfloat16* Wl, int m0, int n0)
{
    const int k0 = c * 32;
    const uint32_t base = sb + buf * 4 * GTB;
#pragma unroll
    for (int p = 0; p < 2; p++) {
        int ch = tid + p * 256;
        int r = ch >> 2, s = ch & 3;
        uint32_t d = base + (uint32_t)(r * GLD + s * 8) * 2;
        size_t ga = (size_t)(m0 + r) * 1024 + k0 + s * 8;
        size_t gw = (size_t)(n0 + r) * 1024 + k0 + s * 8;
        CP_ASYNC(d,         Ah + ga);
        CP_ASYNC(d + GTB,   Al + ga);
        CP_ASYNC(d + 2*GTB, Wh + gw);
        CP_ASYNC(d + 3*GTB, Wl + gw);
    }
}

__global__ void __launch_bounds__(256) hm_gemm(
    const __nv_bfloat16* __restrict__ Ah, const __nv_bfloat16* __restrict__ Al,
    const __nv_bfloat16* __restrict__ Wh, const __nv_bfloat16* __restrict__ Wl,
    const float* __restrict__ bias, float* __restrict__ C,
    __nv_bfloat162* __restrict__ o1h, __nv_bfloat162* __restrict__ o1l,
    __nv_bfloat162* __restrict__ o2h, __nv_bfloat162* __restrict__ o2l,
    const float* __restrict__ addu, const float* __restrict__ addv, int mode)
{
    extern __shared__ __nv_bfloat16 sm[];
    const int tid = threadIdx.x, w = tid >> 5, lane = tid & 31;
    const int n0 = blockIdx.x * 128, m0 = blockIdx.y * 128;
    const int wm = (w & 1) * 64, wn = (w >> 1) * 32;
    const uint32_t sb = smem_u32(sm);
    const int lr = lane & 7, li = lane >> 3;

    float acc[4][4][4];
#pragma unroll
    for (int a = 0; a < 4; a++)
#pragma unroll
        for (int b = 0; b < 4; b++)
#pragma unroll
            for (int k = 0; k < 4; k++) acc[a][b][k] = 0.f;

    gemm_issue(sb, 0, 0, tid, Ah, Al, Wh, Wl, m0, n0);
    CP_COMMIT();

    for (int c = 0; c < 32; c++) {
        if (c < 31) {
            gemm_issue(sb, (c + 1) & 1, c + 1, tid, Ah, Al, Wh, Wl, m0, n0);
            CP_COMMIT();
            CP_WAIT1();
        } else {
            CP_WAIT0();
        }
        __syncthreads();

        const uint32_t bb = sb + (c & 1) * 4 * GTB;
#pragma unroll
        for (int ks = 0; ks < 2; ks++) {
            uint32_t ahf[4][4], alf[4][4];
            const uint32_t acol = (uint32_t)(ks * 16 + (li >> 1) * 8) * 2;
            const uint32_t arow0 = (uint32_t)(wm + (li & 1) * 8 + lr);
#pragma unroll
            for (int mt = 0; mt < 4; mt++) {
                uint32_t ao = bb + (arow0 + mt * 16) * (GLD * 2) + acol;
                ldsm4(ahf[mt], ao);
                ldsm4(alf[mt], ao + GTB);
            }
            uint32_t bhf[2][4], blf[2][4];
            const uint32_t bcol = (uint32_t)(ks * 16 + (li & 1) * 8) * 2;
            const uint32_t brow0 = (uint32_t)(wn + (li >> 1) * 8 + lr);
#pragma unroll
            for (int nb = 0; nb < 2; nb++) {
                uint32_t bo = bb + 2*GTB + (brow0 + nb * 16) * (GLD * 2) + bcol;
                ldsm4(bhf[nb], bo);
                ldsm4(blf[nb], bo + GTB);
            }
#pragma unroll
            for (int mt = 0; mt < 4; mt++)
#pragma unroll
                for (int nt = 0; nt < 4; nt++) {
                    const uint32_t* bh = &bhf[nt >> 1][(nt & 1) * 2];
                    const uint32_t* bl = &blf[nt >> 1][(nt & 1) * 2];
                    mma16816(acc[mt][nt], ahf[mt], bh);
                    mma16816(acc[mt][nt], ahf[mt], bl);
                    mma16816(acc[mt][nt], alf[mt], bh);
                }
        }
        __syncthreads();
    }

#pragma unroll
    for (int mt = 0; mt < 4; mt++) {
        int m = m0 + wm + mt * 16 + (lane >> 2);
#pragma unroll
        for (int half = 0; half < 2; half++) {
            size_t mrow = (size_t)(m + half * 8);
#pragma unroll
            for (int nt = 0; nt < 4; nt++) {
                int col = wn + nt * 8 + (lane & 3) * 2;
                int cg = n0 + col;
                float x = acc[mt][nt][half*2+0] + bias[cg];
                float y = acc[mt][nt][half*2+1] + bias[cg+1];
                if (mode == 0) {
                    *(float2*)(C + mrow * 1024 + cg) = make_float2(x, y);
                } else if (mode == 1) {
                    __nv_bfloat162 h, l;
                    split2(x, y, h, l);
                    size_t d = (mrow * 1024 + cg) >> 1;
                    o1h[d] = h; o1l[d] = l;
                } else {
                    __nv_bfloat162 h, l;
                    size_t d = (mrow * 1024 + cg) >> 1;
                    split2(x + addu[cg], y + addu[cg+1], h, l);
                    o1h[d] = h; o1l[d] = l;
                    split2(x + addv[cg], y + addv[cg+1], h, l);
                    o2h[d] = h; o2l[d] = l;
                }
            }
        }
    }
}

// ---------------------------------------------------------------------------
// Fused scores kernel, z = b*16+n.
// Phase A: BD band = (q+v)·kr over two 128-wide l-tiles -> SMEM band.
// Phase B: AC = (q+u)·k; epilogue SC = (AC + band)/8 - mask  -> g_SC.
// smem: 4 GEMM tiles (73728) + band 128x257 fp32 (131584) = 205312 B
// ---------------------------------------------------------------------------
#define SLD 72
#define STB 18432
#define BSTR 257
#define BAND_OFF (4 * STB)       // byte offset of band in smem

__device__ __forceinline__ void sc_load_pair(
    uint32_t dst, const __nv_bfloat16* __restrict__ srcH,
    const __nv_bfloat16* __restrict__ srcL, size_t rowStride, int tid)
{
#pragma unroll
    for (int p = 0; p < 4; p++) {
        int ch = tid + p * 256;            // 0..1023
        int r = ch >> 3, s = ch & 7;
        uint32_t d = dst + (uint32_t)(r * SLD + s * 8) * 2;
        size_t g = (size_t)r * rowStride + s * 8;
        CP_ASYNC(d,       srcH + g);
        CP_ASYNC(d + STB, srcL + g);
    }
}

__device__ __forceinline__ void sc_mma_k64(
    float acc[4][4][4], uint32_t aBase, uint32_t bBase, int wm, int wn, int lane)
{
    const int lr = lane & 7, li = lane >> 3;
#pragma unroll
    for (int ks = 0; ks < 4; ks++) {
        uint32_t ahf[4][4], alf[4][4];
        const uint32_t acol = (uint32_t)(ks * 16 + (li >> 1) * 8) * 2;
        const uint32_t arow0 = (uint32_t)(wm + (li & 1) * 8 + lr);
#pragma unroll
        for (int mt = 0; mt < 4; mt++) {
            uint32_t ao = aBase + (arow0 + mt * 16) * (SLD * 2) + acol;
            ldsm4(ahf[mt], ao);
            ldsm4(alf[mt], ao + STB);
        }
        uint32_t bhf[2][4], blf[2][4];
        const uint32_t bcol = (uint32_t)(ks * 16 + (li & 1) * 8) * 2;
        const uint32_t brow0 = (uint32_t)(wn + (li >> 1) * 8 + lr);
#pragma unroll
        for (int nb = 0; nb < 2; nb++) {
            uint32_t bo = bBase + (brow0 + nb * 16) * (SLD * 2) + bcol;
            ldsm4(bhf[nb], bo);
            ldsm4(blf[nb], bo + STB);
        }
#pragma unroll
        for (int mt = 0; mt < 4; mt++)
#pragma unroll
            for (int nt = 0; nt < 4; nt++) {
                const uint32_t* bh = &bhf[nt >> 1][(nt & 1) * 2];
                const uint32_t* bl = &blf[nt >> 1][(nt & 1) * 2];
                mma16816(acc[mt][nt], ahf[mt], bh);
                mma16816(acc[mt][nt], ahf[mt], bl);
                mma16816(acc[mt][nt], alf[mt], bh);
            }
    }
}

__global__ void __launch_bounds__(256) hm_scores_fused(const float* __restrict__ amask)
{
    extern __shared__ __nv_bfloat16 sm[];
    float* band = (float*)((char*)sm + BAND_OFF);
    const int tid = threadIdx.x, w = tid >> 5, lane = tid & 31;
    const int z = blockIdx.z, b = z >> 4, n = z & 15;
    const int j0 = blockIdx.x * 128, i0 = blockIdx.y * 128;
    const int wm = (w & 1) * 64, wn = (w >> 1) * 32;
    const uint32_t sb = smem_u32(sm);
    const uint32_t aB = sb, bB = sb + 2 * STB;

    const size_t aoff = ((size_t)i0 * 4 + b) * 1024 + n * 64;
    const int l0a = j0 - i0 + 896;          // always >= 0, multiple of 128

    float acc[4][4][4];
#pragma unroll
    for (int a = 0; a < 4; a++)
#pragma unroll
        for (int c = 0; c < 4; c++)
#pragma unroll
            for (int k = 0; k < 4; k++) acc[a][c][k] = 0.f;

    // ---- Phase A: BD band tiles ----
    const bool t0v = (l0a < 2048), t1v = (l0a + 128 < 2048);
    if (t0v) {
        sc_load_pair(aB, g_QVh + aoff, g_QVl + aoff, 4096, tid);
        sc_load_pair(bB, g_Rh + (size_t)l0a * 1024 + n * 64,
                         g_Rl + (size_t)l0a * 1024 + n * 64, 1024, tid);
        CP_COMMIT(); CP_WAIT0();
        __syncthreads();
        sc_mma_k64(acc, aB, bB, wm, wn, lane);
        // store band tile 0
#pragma unroll
        for (int mt = 0; mt < 4; mt++) {
            int r = wm + mt * 16 + (lane >> 2);
#pragma unroll
            for (int nt = 0; nt < 4; nt++) {
                int c = wn + nt * 8 + (lane & 3) * 2;
                band[r * BSTR + c]       = acc[mt][nt][0];
                band[r * BSTR + c + 1]   = acc[mt][nt][1];
                band[(r+8) * BSTR + c]   = acc[mt][nt][2];
                band[(r+8) * BSTR + c+1] = acc[mt][nt][3];
            }
        }
        __syncthreads();
        if (t1v) {
#pragma unroll
            for (int a = 0; a < 4; a++)
#pragma unroll
                for (int c = 0; c < 4; c++)
#pragma unroll
                    for (int k = 0; k < 4; k++) acc[a][c][k] = 0.f;
            sc_load_pair(bB, g_Rh + (size_t)(l0a+128) * 1024 + n * 64,
                             g_Rl + (size_t)(l0a+128) * 1024 + n * 64, 1024, tid);
            CP_COMMIT(); CP_WAIT0();
            __syncthreads();
            sc_mma_k64(acc, aB, bB, wm, wn, lane);
#pragma unroll
            for (int mt = 0; mt < 4; mt++) {
                int r = wm + mt * 16 + (lane >> 2);
#pragma unroll
                for (int nt = 0; nt < 4; nt++) {
                    int c = wn + nt * 8 + (lane & 3) * 2 + 128;
                    band[r * BSTR + c]       = acc[mt][nt][0];
                    band[r * BSTR + c + 1]   = acc[mt][nt][1];
                    band[(r+8) * BSTR + c]   = acc[mt][nt][2];
                    band[(r+8) * BSTR + c+1] = acc[mt][nt][3];
                }
            }
            __syncthreads();
        }
    }

    // ---- Phase B: AC ----
#pragma unroll
    for (int a = 0; a < 4; a++)
#pragma unroll
        for (int c = 0; c < 4; c++)
#pragma unroll
            for (int k = 0; k < 4; k++) acc[a][c][k] = 0.f;
    const size_t koff = ((size_t)j0 * 4 + b) * 1024 + n * 64;
    sc_load_pair(aB, g_QUh + aoff, g_QUl + aoff, 4096, tid);
    sc_load_pair(bB, g_Kh + koff,  g_Kl + koff,  4096, tid);
    CP_COMMIT(); CP_WAIT0();
    __syncthreads();
    sc_mma_k64(acc, aB, bB, wm, wn, lane);

    // ---- Epilogue: SC = (AC + band)/8 - mask ----
    const size_t obase = (size_t)z * PLANE;
#pragma unroll
    for (int mt = 0; mt < 4; mt++) {
        int ri0 = wm + mt * 16 + (lane >> 2);
#pragma unroll
        for (int half = 0; half < 2; half++) {
            int ri = ri0 + half * 8;
            int i = i0 + ri;
            const float* amrow = amask + (size_t)(i >> 8) * 1024;
            float* orow = g_SC + obase + (size_t)i * 2048 + j0;
#pragma unroll
            for (int nt = 0; nt < 4; nt++) {
                int rj = wn + nt * 8 + (lane & 3) * 2;
                float o[2];
#pragma unroll
                for (int e = 0; e < 2; e++) {
                    int rje = rj + e;
                    int j = j0 + rje;
                    int l = j + 1023 - i;
                    int lb = rje - ri + 127;
                    float bd = (l < 2048 && t0v) ? band[ri * BSTR + lb] : 0.f;
                    float val = (acc[mt][nt][half*2+e] + bd) * 0.125f;
                    int jp = ((j << 6) + (b << 4) + n) & 2047;
                    float m = (jp < 1024) ? 1.f : amrow[jp - 1024];
                    o[e] = val - (1.f - m) * 1e9f;
                }
                *(float2*)(orow + rj) = make_float2(o[0], o[1]);
            }
        }
    }
}

// ---------------------------------------------------------------------------
// Softmax over the 16-head axis: SC -> ATTh (single bf16). float4 per thread.
// ---------------------------------------------------------------------------
__global__ void softmax_heads()
{
    const int j4 = blockIdx.x * 256 + threadIdx.x;   // 0..511 (float4 col)
    const int i  = blockIdx.y;
    const int b  = blockIdx.z;

    const float4* SC4 = (const float4*)g_SC;
    const size_t base = (size_t)b * 16 * 524288 + (size_t)i * 512 + j4;

    float4 s[16];
    float4 mx = make_float4(-1e30f, -1e30f, -1e30f, -1e30f);
#pragma unroll
    for (int n = 0; n < 16; n++) {
        float4 v = SC4[base + (size_t)n * 524288];
        s[n] = v;
        mx.x = fmaxf(mx.x, v.x); mx.y = fmaxf(mx.y, v.y);
        mx.z = fmaxf(mx.z, v.z); mx.w = fmaxf(mx.w, v.w);
    }
    float4 sum = make_float4(0.f, 0.f, 0.f, 0.f);
#pragma unroll
    for (int n = 0; n < 16; n++) {
        s[n].x = __expf(s[n].x - mx.x); sum.x += s[n].x;
        s[n].y = __expf(s[n].y - mx.y); sum.y += s[n].y;
        s[n].z = __expf(s[n].z - mx.z); sum.z += s[n].z;
        s[n].w = __expf(s[n].w - mx.w); sum.w += s[n].w;
    }
    float4 inv = make_float4(1.f/sum.x, 1.f/sum.y, 1.f/sum.z, 1.f/sum.w);
#pragma unroll
    for (int n = 0; n < 16; n++) {
        __nv_bfloat162 p0 = __halves2bfloat162(__float2bfloat16(s[n].x * inv.x),
                                               __float2bfloat16(s[n].y * inv.y));
        __nv_bfloat162 p1 = __halves2bfloat162(__float2bfloat16(s[n].z * inv.z),
                                               __float2bfloat16(s[n].w * inv.w));
        size_t el = ((size_t)(b * 16 + n)) * PLANE + (size_t)i * 2048 + (size_t)j4 * 4;
        *(uint2*)(g_ATTh + el) = make_uint2(
            *(const uint32_t*)&p0, *(const uint32_t*)&p1);
    }
}

// ---------------------------------------------------------------------------
// HMMA attn@V (2-term: Ah*Vh + Ah*Vl), epilogue writes O1 hi/lo bf16 split.
// smem/buf: ATTh 18432 + Vh 9216 + Vl 9216 = 36864; x2 bufs = 73728
// ---------------------------------------------------------------------------
#define VTB 9216
#define ABUF 36864

__device__ __forceinline__ void attnv_issue(
    uint32_t sb, int buf, int c, int tid, int i0, int b, int n, size_t zbase)
{
    const uint32_t base = sb + buf * ABUF;
#pragma unroll
    for (int p = 0; p < 4; p++) {
        int ch = tid + p * 256;          // 0..1023
        int r = ch >> 3, s = ch & 7;
        uint32_t d = base + (uint32_t)(r * SLD + s * 8) * 2;
        size_t g = zbase + (size_t)(i0 + r) * 2048 + c * 64 + s * 8;
        CP_ASYNC(d, g_ATTh + g);
    }
#pragma unroll
    for (int p = 0; p < 2; p++) {
        int ch = tid + p * 256;          // 0..511
        int r = ch >> 3, s = ch & 7;
        uint32_t d = base + STB + (uint32_t)(r * SLD + s * 8) * 2;
        size_t g = ((size_t)(c * 64 + r) * 4 + b) * 1024 + n * 64 + s * 8;
        CP_ASYNC(d,       g_Vh + g);
        CP_ASYNC(d + VTB, g_Vl + g);
    }
}

__global__ void __launch_bounds__(256) hm_attnv()
{
    extern __shared__ __nv_bfloat16 sm[];
    const int tid = threadIdx.x, w = tid >> 5, lane = tid & 31;
    const int z = blockIdx.y, b = z >> 4, n = z & 15;
    const int i0 = blockIdx.x * 128;
    const int wm = (w & 3) * 32, wn = (w >> 2) * 32;
    const size_t zbase = (size_t)z * PLANE;
    const uint32_t sb = smem_u32(sm);
    const int lr = lane & 7, li = lane >> 3;

    float acc[2][4][4];
#pragma unroll
    for (int a = 0; a < 2; a++)
#pragma unroll
        for (int c = 0; c < 4; c++)
#pragma unroll
            for (int k = 0; k < 4; k++) acc[a][c][k] = 0.f;

    attnv_issue(sb, 0, 0, tid, i0, b, n, zbase);
    CP_COMMIT();

    for (int c = 0; c < 32; c++) {
        if (c < 31) {
            attnv_issue(sb, (c + 1) & 1, c + 1, tid, i0, b, n, zbase);
            CP_COMMIT();
            CP_WAIT1();
        } else {
            CP_WAIT0();
        }
        __syncthreads();

        const uint32_t bb = sb + (c & 1) * ABUF;
#pragma unroll
        for (int ks = 0; ks < 4; ks++) {
            uint32_t ahf[2][4];
            const uint32_t acol = (uint32_t)(ks * 16 + (li >> 1) * 8) * 2;
            const uint32_t arow0 = (uint32_t)(wm + (li & 1) * 8 + lr);
#pragma unroll
            for (int mt = 0; mt < 2; mt++) {
                uint32_t ao = bb + (arow0 + mt * 16) * (SLD * 2) + acol;
                ldsm4(ahf[mt], ao);
            }
            uint32_t bhf[2][4], blf[2][4];
            const uint32_t vrow0 = (uint32_t)(ks * 16 + (li & 1) * 8 + lr);
#pragma unroll
            for (int nb = 0; nb < 2; nb++) {
                uint32_t vcol = (uint32_t)(wn + nb * 16 + (li >> 1) * 8) * 2;
                uint32_t bo = bb + STB + vrow0 * (SLD * 2) + vcol;
                ldsm4t(bhf[nb], bo);
                ldsm4t(blf[nb], bo + VTB);
            }
#pragma unroll
            for (int mt = 0; mt < 2; mt++)
#pragma unroll
                for (int nt = 0; nt < 4; nt++) {
                    const uint32_t* bh = &bhf[nt >> 1][(nt & 1) * 2];
                    const uint32_t* bl = &blf[nt >> 1][(nt & 1) * 2];
                    mma16816(acc[mt][nt], ahf[mt], bh);
                    mma16816(acc[mt][nt], ahf[mt], bl);
                }
        }
        __syncthreads();
    }

#pragma unroll
    for (int mt = 0; mt < 2; mt++) {
        int i = i0 + wm + mt * 16 + (lane >> 2);
#pragma unroll
        for (int half = 0; half < 2; half++) {
            size_t rbase = ((size_t)(i + half * 8) * 4 + b) * 1024 + n * 64;
#pragma unroll
            for (int nt = 0; nt < 4; nt++) {
                int col = wn + nt * 8 + (lane & 3) * 2;
                __nv_bfloat162 h, l;
                split2(acc[mt][nt][half*2+0], acc[mt][nt][half*2+1], h, l);
                size_t d = (rbase + col) >> 1;
                ((__nv_bfloat162*)g_O1h)[d] = h;
                ((__nv_bfloat162*)g_O1l)[d] = l;
            }
        }
    }
}

// ---------------------------------------------------------------------------
__global__ void write_mems(const float4* __restrict__ mems,
                           const float4* __restrict__ out,
                           float4* __restrict__ dst)
{
    int idx = blockIdx.x * blockDim.x + threadIdx.x;
    int row = idx >> 8, c = idx & 255;
    int b = row >> 11, pos = row & 2047;
    float4 v;
    if (pos < 1024) v = mems[idx];
    else            v = out[(((size_t)b * 1024) + (pos - 1024)) * 256 + c];
    dst[idx] = v;
}

// ---------------------------------------------------------------------------
extern "C" void kernel_launch(void* const* d_in, const int* in_sizes, int n_in,
                              void* d_out, int out_size)
{
    const float* TE    = (const float*)d_in[0];
    const float* REL   = (const float*)d_in[1];
    const float* MEMS  = (const float*)d_in[2];
    const float* AMASK = (const float*)d_in[3];
    const float* Wq = (const float*)d_in[4],  *bq = (const float*)d_in[5];
    const float* Wk = (const float*)d_in[6],  *bk = (const float*)d_in[7];
    const float* Wv = (const float*)d_in[8],  *bv = (const float*)d_in[9];
    const float* Wr = (const float*)d_in[10], *br = (const float*)d_in[11];
    const float* Wo = (const float*)d_in[12], *bo = (const float*)d_in[13];
    const float* u  = (const float*)d_in[14];
    const float* v  = (const float*)d_in[15];
    float* out = (float*)d_out;

    const int G_SMEM  = 2 * 4 * GTB;                 // 81920
    const int SC_SMEM = 4 * STB + 128 * BSTR * 4;    // 205312
    const int A_SMEM  = 2 * ABUF;                    // 73728
    cudaFuncSetAttribute(hm_gemm,         cudaFuncAttributeMaxDynamicSharedMemorySize, G_SMEM);
    cudaFuncSetAttribute(hm_scores_fused, cudaFuncAttributeMaxDynamicSharedMemorySize, SC_SMEM);
    cudaFuncSetAttribute(hm_attnv,        cudaFuncAttributeMaxDynamicSharedMemorySize, A_SMEM);

    __nv_bfloat16 *pTEh, *pTEl, *pRELh, *pRELl, *pWh, *pWl;
    __nv_bfloat16 *pKVh, *pKVl, *pQUh, *pQUl, *pQVh, *pQVl;
    __nv_bfloat16 *pKh, *pKl, *pRh, *pRl, *pVh, *pVl, *pO1h, *pO1l;
    cudaGetSymbolAddress((void**)&pTEh,  g_TEh);  cudaGetSymbolAddress((void**)&pTEl,  g_TEl);
    cudaGetSymbolAddress((void**)&pRELh, g_RELh); cudaGetSymbolAddress((void**)&pRELl, g_RELl);
    cudaGetSymbolAddress((void**)&pWh,   g_Wh);   cudaGetSymbolAddress((void**)&pWl,   g_Wl);
    cudaGetSymbolAddress((void**)&pKVh,  g_KVh);  cudaGetSymbolAddress((void**)&pKVl,  g_KVl);
    cudaGetSymbolAddress((void**)&pQUh,  g_QUh);  cudaGetSymbolAddress((void**)&pQUl,  g_QUl);
    cudaGetSymbolAddress((void**)&pQVh,  g_QVh);  cudaGetSymbolAddress((void**)&pQVl,  g_QVl);
    cudaGetSymbolAddress((void**)&pKh,   g_Kh);   cudaGetSymbolAddress((void**)&pKl,   g_Kl);
    cudaGetSymbolAddress((void**)&pRh,   g_Rh);   cudaGetSymbolAddress((void**)&pRl,   g_Rl);
    cudaGetSymbolAddress((void**)&pVh,   g_Vh);   cudaGetSymbolAddress((void**)&pVl,   g_Vl);
    cudaGetSymbolAddress((void**)&pO1h,  g_O1h);  cudaGetSymbolAddress((void**)&pO1l,  g_O1l);

    const size_t WSZ = (size_t)1024 * 1024;

    // 1. input splits + fused gather/split of kv
    gather_split_kv<<<8192, 256>>>((const float4*)TE, (const float4*)MEMS);
    split_bf16<<<4096, 256>>>((const float4*)TE,  (__nv_bfloat162*)pTEh,  (__nv_bfloat162*)pTEl,  1048576);
    split_bf16<<<2048, 256>>>((const float4*)REL, (__nv_bfloat162*)pRELh, (__nv_bfloat162*)pRELl, 524288);
    split5_w<<<dim3(1024, 5), 256>>>((const float4*)Wq, (const float4*)Wk, (const float4*)Wv,
                                     (const float4*)Wr, (const float4*)Wo,
                                     (__nv_bfloat162*)pWh, (__nv_bfloat162*)pWl);

    // 2. projections (split epilogues — no fp32 intermediates)
    hm_gemm<<<dim3(8, 32), 256, G_SMEM>>>(pTEh, pTEl, pWh + 0*WSZ, pWl + 0*WSZ, bq, nullptr,
        (__nv_bfloat162*)pQUh, (__nv_bfloat162*)pQUl,
        (__nv_bfloat162*)pQVh, (__nv_bfloat162*)pQVl, u, v, 2);
    hm_gemm<<<dim3(8, 64), 256, G_SMEM>>>(pKVh, pKVl, pWh + 1*WSZ, pWl + 1*WSZ, bk, nullptr,
        (__nv_bfloat162*)pKh, (__nv_bfloat162*)pKl, nullptr, nullptr, nullptr, nullptr, 1);
    hm_gemm<<<dim3(8, 64), 256, G_SMEM>>>(pKVh, pKVl, pWh + 2*WSZ, pWl + 2*WSZ, bv, nullptr,
        (__nv_bfloat162*)pVh, (__nv_bfloat162*)pVl, nullptr, nullptr, nullptr, nullptr, 1);
    hm_gemm<<<dim3(8, 16), 256, G_SMEM>>>(pRELh, pRELl, pWh + 3*WSZ, pWl + 3*WSZ, br, nullptr,
        (__nv_bfloat162*)pRh, (__nv_bfloat162*)pRl, nullptr, nullptr, nullptr, nullptr, 1);

    // 3. fused scores (AC + rel-shifted BD + mask) -> SC
    hm_scores_fused<<<dim3(16, 8, 64), 256, SC_SMEM>>>(AMASK);

    // 4. softmax over heads -> ATT (single bf16)
    softmax_heads<<<dim3(2, 1024, 4), 256>>>();

    // 5. attn @ V -> O1 hi/lo split
    hm_attnv<<<dim3(8, 64), 256, A_SMEM>>>();

    // 6. O projection -> d_out (fp32)
    hm_gemm<<<dim3(8, 32), 256, G_SMEM>>>(pO1h, pO1l, pWh + 4*WSZ, pWl + 4*WSZ, bo, out,
        nullptr, nullptr, nullptr, nullptr, nullptr, nullptr, 0);

    // 7. mems_new
    if (out_size >= 12582912)
        write_mems<<<8192, 256>>>((const float4*)MEMS, (const float4*)out,
                                  (float4*)(out + 4194304));
}

// round 6
// speedup vs baseline: 1.0537x; 1.0537x over previous
#include <cuda_runtime.h>
#include <cuda_bf16.h>
#include <stdint.h>
#include <math.h>

// ---------------------------------------------------------------------------
// Problem constants: B=4, S=1024, H=1024, HEADS=16, HEAD_D=64, K=2048
// ---------------------------------------------------------------------------
#define PLANE 2097152ull   // 1024*2048

// ---------------- scratch ----------------
__device__ float         g_AC [(size_t)64 * PLANE];
__device__ float         g_BD [(size_t)64 * PLANE];
__device__ __nv_bfloat16 g_ATTh[(size_t)64 * PLANE];
__device__ __nv_bfloat16 g_ATTl[(size_t)64 * PLANE];

__device__ __nv_bfloat16 g_TEh [(size_t)4096*1024], g_TEl [(size_t)4096*1024];
__device__ __nv_bfloat16 g_KVh [(size_t)8192*1024], g_KVl [(size_t)8192*1024];
__device__ __nv_bfloat16 g_RELh[(size_t)2048*1024], g_RELl[(size_t)2048*1024];
__device__ __nv_bfloat16 g_Wh  [(size_t)5*1024*1024], g_Wl [(size_t)5*1024*1024];
__device__ __nv_bfloat16 g_QUh [(size_t)4096*1024], g_QUl [(size_t)4096*1024];
__device__ __nv_bfloat16 g_QVh [(size_t)4096*1024], g_QVl [(size_t)4096*1024];
__device__ __nv_bfloat16 g_Kh  [(size_t)8192*1024], g_Kl  [(size_t)8192*1024];
__device__ __nv_bfloat16 g_Rh  [(size_t)2048*1024], g_Rl  [(size_t)2048*1024];
__device__ __nv_bfloat16 g_Vh  [(size_t)8192*1024], g_Vl  [(size_t)8192*1024];
__device__ __nv_bfloat16 g_O1h [(size_t)4096*1024], g_O1l [(size_t)4096*1024];

// ---------------------------------------------------------------------------
// Low-level helpers (sm_80-compatible: ldmatrix / mma.sync / cp.async)
// ---------------------------------------------------------------------------
__device__ __forceinline__ uint32_t smem_u32(const void* p) {
    uint32_t a;
    asm("{ .reg .u64 t; cvta.to.shared.u64 t, %1; cvt.u32.u64 %0, t; }"
        : "=r"(a) : "l"(p));
    return a;
}
__device__ __forceinline__ void ldsm4(uint32_t* r, uint32_t a) {
    asm volatile("ldmatrix.sync.aligned.m8n8.x4.shared.b16 {%0,%1,%2,%3}, [%4];"
        : "=r"(r[0]), "=r"(r[1]), "=r"(r[2]), "=r"(r[3]) : "r"(a));
}
__device__ __forceinline__ void ldsm4t(uint32_t* r, uint32_t a) {
    asm volatile("ldmatrix.sync.aligned.m8n8.x4.trans.shared.b16 {%0,%1,%2,%3}, [%4];"
        : "=r"(r[0]), "=r"(r[1]), "=r"(r[2]), "=r"(r[3]) : "r"(a));
}
__device__ __forceinline__ void mma16816(float* c, const uint32_t* a, const uint32_t* b) {
    asm volatile(
        "mma.sync.aligned.m16n8k16.row.col.f32.bf16.bf16.f32 "
        "{%0,%1,%2,%3}, {%4,%5,%6,%7}, {%8,%9}, {%0,%1,%2,%3};"
        : "+f"(c[0]), "+f"(c[1]), "+f"(c[2]), "+f"(c[3])
        : "r"(a[0]), "r"(a[1]), "r"(a[2]), "r"(a[3]), "r"(b[0]), "r"(b[1]));
}
#define CP_ASYNC(dst, src) \
    asm volatile("cp.async.cg.shared.global [%0], [%1], 16;" :: "r"(dst), "l"(src))
#define CP_COMMIT() asm volatile("cp.async.commit_group;" ::: "memory")
#define CP_WAIT1()  asm volatile("cp.async.wait_group 1;" ::: "memory")
#define CP_WAIT0()  asm volatile("cp.async.wait_group 0;" ::: "memory")

__device__ __forceinline__ void split2(float x, float y,
                                       __nv_bfloat162& h, __nv_bfloat162& l) {
    __nv_bfloat16 hx = __float2bfloat16(x), hy = __float2bfloat16(y);
    h = __halves2bfloat162(hx, hy);
    l = __halves2bfloat162(__float2bfloat16(x - __bfloat162float(hx)),
                           __float2bfloat16(y - __bfloat162float(hy)));
}

// ---------------------------------------------------------------------------
// split fp32 -> bf16 hi/lo (generic)
// ---------------------------------------------------------------------------
__global__ void split_bf16(const float4* __restrict__ in,
                           __nv_bfloat162* __restrict__ hi,
                           __nv_bfloat162* __restrict__ lo, int n4)
{
    int i = blockIdx.x * blockDim.x + threadIdx.x;
    if (i >= n4) return;
    float4 x = in[i];
    __nv_bfloat162 h0, l0, h1, l1;
    split2(x.x, x.y, h0, l0);
    split2(x.z, x.w, h1, l1);
    hi[i*2+0] = h0; hi[i*2+1] = h1;
    lo[i*2+0] = l0; lo[i*2+1] = l1;
}

// split 5 weight matrices in one launch
__global__ void split5_w(const float4* w0, const float4* w1, const float4* w2,
                         const float4* w3, const float4* w4,
                         __nv_bfloat162* __restrict__ hi,
                         __nv_bfloat162* __restrict__ lo)
{
    const float4* srcs[5] = {w0, w1, w2, w3, w4};
    int which = blockIdx.y;
    int i = blockIdx.x * blockDim.x + threadIdx.x;      // 0..262143
    float4 x = srcs[which][i];
    size_t d = (size_t)which * 524288 + (size_t)i * 2;
    __nv_bfloat162 h0, l0, h1, l1;
    split2(x.x, x.y, h0, l0);
    split2(x.z, x.w, h1, l1);
    hi[d] = h0; hi[d+1] = h1;
    lo[d] = l0; lo[d+1] = l1;
}

// gather kv_in (natural flat order row = b*2048+j) + split to bf16 hi/lo
__global__ void gather_split_kv(const float4* __restrict__ te,
                                const float4* __restrict__ mems)
{
    int idx = blockIdx.x * blockDim.x + threadIdx.x;    // 8192*256
    int row = idx >> 8, c = idx & 255;
    int b = row >> 11, j = row & 2047;
    float4 x;
    if (j < 1024) x = te  [((size_t)b * 1024 + j) * 256 + c];
    else          x = mems[((size_t)b * 2048 + (j - 1024)) * 256 + c];
    __nv_bfloat162 h0, l0, h1, l1;
    split2(x.x, x.y, h0, l0);
    split2(x.z, x.w, h1, l1);
    ((__nv_bfloat162*)g_KVh)[idx*2]   = h0;
    ((__nv_bfloat162*)g_KVh)[idx*2+1] = h1;
    ((__nv_bfloat162*)g_KVl)[idx*2]   = l0;
    ((__nv_bfloat162*)g_KVl)[idx*2+1] = l1;
}

// ---------------------------------------------------------------------------
// HMMA GEMM: C[M,1024] = A[M,1024] @ W[1024,1024]^T + bias, bf16-split 3-term.
// 128x128 CTA tile, BK=32, 8 warps (64x32), cp.async double-buffer.
// Epilogue modes: 0 = fp32+bias -> C; 1 = bias+split -> o1; 2 = dual split
// (bias+u -> o1, bias+v -> o2).
// ---------------------------------------------------------------------------
#define GLD 40
#define GTB 10240

__device__ __forceinline__ void gemm_issue(
    uint32_t sb, int buf, int c, int tid,
    const __nv_bfloat16* Ah, const __nv_bfloat16* Al,
    const __nv_bfloat16* Wh, const __nv_bfloat16* Wl, int m0, int n0)
{
    const int k0 = c * 32;
    const uint32_t base = sb + buf * 4 * GTB;
#pragma unroll
    for (int p = 0; p < 2; p++) {
        int ch = tid + p * 256;
        int r = ch >> 2, s = ch & 3;
        uint32_t d = base + (uint32_t)(r * GLD + s * 8) * 2;
        size_t ga = (size_t)(m0 + r) * 1024 + k0 + s * 8;
        size_t gw = (size_t)(n0 + r) * 1024 + k0 + s * 8;
        CP_ASYNC(d,         Ah + ga);
        CP_ASYNC(d + GTB,   Al + ga);
        CP_ASYNC(d + 2*GTB, Wh + gw);
        CP_ASYNC(d + 3*GTB, Wl + gw);
    }
}

__global__ void __launch_bounds__(256) hm_gemm(
    const __nv_bfloat16* __restrict__ Ah, const __nv_bfloat16* __restrict__ Al,
    const __nv_bfloat16* __restrict__ Wh, const __nv_bfloat16* __restrict__ Wl,
    const float* __restrict__ bias, float* __restrict__ C,
    __nv_bfloat162* __restrict__ o1h, __nv_bfloat162* __restrict__ o1l,
    __nv_bfloat162* __restrict__ o2h, __nv_bfloat162* __restrict__ o2l,
    const float* __restrict__ addu, const float* __restrict__ addv, int mode)
{
    extern __shared__ __nv_bfloat16 sm[];
    const int tid = threadIdx.x, w = tid >> 5, lane = tid & 31;
    const int n0 = blockIdx.x * 128, m0 = blockIdx.y * 128;
    const int wm = (w & 1) * 64, wn = (w >> 1) * 32;
    const uint32_t sb = smem_u32(sm);
    const int lr = lane & 7, li = lane >> 3;

    float acc[4][4][4];
#pragma unroll
    for (int a = 0; a < 4; a++)
#pragma unroll
        for (int b = 0; b < 4; b++)
#pragma unroll
            for (int k = 0; k < 4; k++) acc[a][b][k] = 0.f;

    gemm_issue(sb, 0, 0, tid, Ah, Al, Wh, Wl, m0, n0);
    CP_COMMIT();

    for (int c = 0; c < 32; c++) {
        if (c < 31) {
            gemm_issue(sb, (c + 1) & 1, c + 1, tid, Ah, Al, Wh, Wl, m0, n0);
            CP_COMMIT();
            CP_WAIT1();
        } else {
            CP_WAIT0();
        }
        __syncthreads();

        const uint32_t bb = sb + (c & 1) * 4 * GTB;
#pragma unroll
        for (int ks = 0; ks < 2; ks++) {
            uint32_t ahf[4][4], alf[4][4];
            const uint32_t acol = (uint32_t)(ks * 16 + (li >> 1) * 8) * 2;
            const uint32_t arow0 = (uint32_t)(wm + (li & 1) * 8 + lr);
#pragma unroll
            for (int mt = 0; mt < 4; mt++) {
                uint32_t ao = bb + (arow0 + mt * 16) * (GLD * 2) + acol;
                ldsm4(ahf[mt], ao);
                ldsm4(alf[mt], ao + GTB);
            }
            uint32_t bhf[2][4], blf[2][4];
            const uint32_t bcol = (uint32_t)(ks * 16 + (li & 1) * 8) * 2;
            const uint32_t brow0 = (uint32_t)(wn + (li >> 1) * 8 + lr);
#pragma unroll
            for (int nb = 0; nb < 2; nb++) {
                uint32_t bo = bb + 2*GTB + (brow0 + nb * 16) * (GLD * 2) + bcol;
                ldsm4(bhf[nb], bo);
                ldsm4(blf[nb], bo + GTB);
            }
#pragma unroll
            for (int mt = 0; mt < 4; mt++)
#pragma unroll
                for (int nt = 0; nt < 4; nt++) {
                    const uint32_t* bh = &bhf[nt >> 1][(nt & 1) * 2];
                    const uint32_t* bl = &blf[nt >> 1][(nt & 1) * 2];
                    mma16816(acc[mt][nt], ahf[mt], bh);
                    mma16816(acc[mt][nt], ahf[mt], bl);
                    mma16816(acc[mt][nt], alf[mt], bh);
                }
        }
        __syncthreads();
    }

#pragma unroll
    for (int mt = 0; mt < 4; mt++) {
        int m = m0 + wm + mt * 16 + (lane >> 2);
#pragma unroll
        for (int half = 0; half < 2; half++) {
            size_t mrow = (size_t)(m + half * 8);
#pragma unroll
            for (int nt = 0; nt < 4; nt++) {
                int col = wn + nt * 8 + (lane & 3) * 2;
                int cg = n0 + col;
                float x = acc[mt][nt][half*2+0] + bias[cg];
                float y = acc[mt][nt][half*2+1] + bias[cg+1];
                if (mode == 0) {
                    *(float2*)(C + mrow * 1024 + cg) = make_float2(x, y);
                } else if (mode == 1) {
                    __nv_bfloat162 h, l;
                    split2(x, y, h, l);
                    size_t d = (mrow * 1024 + cg) >> 1;
                    o1h[d] = h; o1l[d] = l;
                } else {
                    __nv_bfloat162 h, l;
                    size_t d = (mrow * 1024 + cg) >> 1;
                    split2(x + addu[cg], y + addu[cg+1], h, l);
                    o1h[d] = h; o1l[d] = l;
                    split2(x + addv[cg], y + addv[cg+1], h, l);
                    o2h[d] = h; o2l[d] = l;
                }
            }
        }
    }
}

// ---------------------------------------------------------------------------
// HMMA batched scores, z = b*16+n.  K=64 single shot. LD=72 pad.
//   mode0 (AC): C[i,j] = (q+u)[i,b,n,:]·k[j,b,n,:]
//   mode1 (BD): C[i,l] = (q+v)[i,b,n,:]·kr[l,n,:]
// smem: 4 tiles x 128x72x2 = 73728 B (2 CTA/SM)
// ---------------------------------------------------------------------------
#define SLD 72
#define STB 18432

__global__ void __launch_bounds__(256) hm_scores(
    const __nv_bfloat16* __restrict__ Ah, const __nv_bfloat16* __restrict__ Al,
    const __nv_bfloat16* __restrict__ Bh, const __nv_bfloat16* __restrict__ Bl,
    float* __restrict__ Out, int mode)
{
    extern __shared__ __nv_bfloat16 sm[];
    const int tid = threadIdx.x, w = tid >> 5, lane = tid & 31;
    const int z = blockIdx.z, b = z >> 4, n = z & 15;
    const int j0 = blockIdx.x * 128, i0 = blockIdx.y * 128;
    const int wm = (w & 1) * 64, wn = (w >> 1) * 32;
    const uint32_t sb = smem_u32(sm);
    const int lr = lane & 7, li = lane >> 3;

#pragma unroll
    for (int p = 0; p < 4; p++) {
        int ch = tid + p * 256;          // 0..1023
        int r = ch >> 3, s = ch & 7;
        uint32_t d = sb + (uint32_t)(r * SLD + s * 8) * 2;
        size_t ga = ((size_t)(i0 + r) * 4 + b) * 1024 + n * 64 + s * 8;
        size_t gb = mode ? ((size_t)(j0 + r) * 1024 + n * 64 + s * 8)
                         : (((size_t)(j0 + r) * 4 + b) * 1024 + n * 64 + s * 8);
        CP_ASYNC(d,           Ah + ga);
        CP_ASYNC(d + STB,     Al + ga);
        CP_ASYNC(d + 2*STB,   Bh + gb);
        CP_ASYNC(d + 3*STB,   Bl + gb);
    }
    CP_COMMIT();
    CP_WAIT0();
    __syncthreads();

    float acc[4][4][4];
#pragma unroll
    for (int a = 0; a < 4; a++)
#pragma unroll
        for (int c = 0; c < 4; c++)
#pragma unroll
            for (int k = 0; k < 4; k++) acc[a][c][k] = 0.f;

#pragma unroll
    for (int ks = 0; ks < 4; ks++) {
        uint32_t ahf[4][4], alf[4][4];
        const uint32_t acol = (uint32_t)(ks * 16 + (li >> 1) * 8) * 2;
        const uint32_t arow0 = (uint32_t)(wm + (li & 1) * 8 + lr);
#pragma unroll
        for (int mt = 0; mt < 4; mt++) {
            uint32_t ao = sb + (arow0 + mt * 16) * (SLD * 2) + acol;
            ldsm4(ahf[mt], ao);
            ldsm4(alf[mt], ao + STB);
        }
        uint32_t bhf[2][4], blf[2][4];
        const uint32_t bcol = (uint32_t)(ks * 16 + (li & 1) * 8) * 2;
        const uint32_t brow0 = (uint32_t)(wn + (li >> 1) * 8 + lr);
#pragma unroll
        for (int nb = 0; nb < 2; nb++) {
            uint32_t bo = sb + 2*STB + (brow0 + nb * 16) * (SLD * 2) + bcol;
            ldsm4(bhf[nb], bo);
            ldsm4(blf[nb], bo + STB);
        }
#pragma unroll
        for (int mt = 0; mt < 4; mt++)
#pragma unroll
            for (int nt = 0; nt < 4; nt++) {
                const uint32_t* bh = &bhf[nt >> 1][(nt & 1) * 2];
                const uint32_t* bl = &blf[nt >> 1][(nt & 1) * 2];
                mma16816(acc[mt][nt], ahf[mt], bh);
                mma16816(acc[mt][nt], ahf[mt], bl);
                mma16816(acc[mt][nt], alf[mt], bh);
            }
    }

    const size_t obase = (size_t)z * PLANE;
#pragma unroll
    for (int mt = 0; mt < 4; mt++) {
        int row = i0 + wm + mt * 16 + (lane >> 2);
        float* r0 = Out + obase + (size_t)row * 2048 + j0 + wn;
        float* r8 = r0 + (size_t)8 * 2048;
#pragma unroll
        for (int nt = 0; nt < 4; nt++) {
            int col = nt * 8 + (lane & 3) * 2;
            *(float2*)(r0 + col) = make_float2(acc[mt][nt][0], acc[mt][nt][1]);
            *(float2*)(r8 + col) = make_float2(acc[mt][nt][2], acc[mt][nt][3]);
        }
    }
}

// ---------------------------------------------------------------------------
// Softmax over the 16-head axis: AC + shifted BD + mask -> ATT (bf16 hi/lo)
// ---------------------------------------------------------------------------
__global__ void softmax_heads(const float* __restrict__ amask)
{
    const int j = blockIdx.x * 256 + threadIdx.x;   // 0..2047
    const int i = blockIdx.y;
    const int b = blockIdx.z;
    const int l = j + 1023 - i;
    const bool lv = (l < 2048);
    const int bprime = i >> 8;

    const size_t base = ((size_t)b * 16 * 1024 + i) * 2048;
    float s[16];
    float mx = -1e30f;
#pragma unroll
    for (int n = 0; n < 16; n++) {
        float ac = g_AC[base + (size_t)n * PLANE + j];
        float bd = lv ? g_BD[base + (size_t)n * PLANE + l] : 0.f;
        float val = (ac + bd) * 0.125f;
        int jp = (j * 64 + b * 16 + n) & 2047;
        float m = (jp < 1024) ? 1.f : amask[(size_t)bprime * 1024 + (jp - 1024)];
        val -= (1.f - m) * 1e9f;
        s[n] = val;
        mx = fmaxf(mx, val);
    }
    float sum = 0.f;
#pragma unroll
    for (int n = 0; n < 16; n++) { s[n] = __expf(s[n] - mx); sum += s[n]; }
    float inv = 1.f / sum;
#pragma unroll
    for (int n = 0; n < 16; n++) {
        float a = s[n] * inv;
        __nv_bfloat16 ah = __float2bfloat16(a);
        __nv_bfloat16 al = __float2bfloat16(a - __bfloat162float(ah));
        g_ATTh[base + (size_t)n * PLANE + j] = ah;
        g_ATTl[base + (size_t)n * PLANE + j] = al;
    }
}

// ---------------------------------------------------------------------------
// HMMA attn@V (3-term: Ah·Vh + Ah·Vl + Al·Vh), writes O1 hi/lo bf16 split.
// smem/buf: ATTh/l 2x18432 + Vh/l 2x9216 = 55296; x2 bufs = 110592 B
// ---------------------------------------------------------------------------
#define VTB 9216
#define ABUF 55296

__device__ __forceinline__ void attnv_issue(
    uint32_t sb, int buf, int c, int tid, int i0, int b, int n, size_t zbase)
{
    const uint32_t base = sb + buf * ABUF;
#pragma unroll
    for (int p = 0; p < 4; p++) {
        int ch = tid + p * 256;          // 0..1023
        int r = ch >> 3, s = ch & 7;
        uint32_t d = base + (uint32_t)(r * SLD + s * 8) * 2;
        size_t g = zbase + (size_t)(i0 + r) * 2048 + c * 64 + s * 8;
        CP_ASYNC(d,       g_ATTh + g);
        CP_ASYNC(d + STB, g_ATTl + g);
    }
#pragma unroll
    for (int p = 0; p < 2; p++) {
        int ch = tid + p * 256;          // 0..511
        int r = ch >> 3, s = ch & 7;
        uint32_t d = base + 2*STB + (uint32_t)(r * SLD + s * 8) * 2;
        size_t g = ((size_t)(c * 64 + r) * 4 + b) * 1024 + n * 64 + s * 8;
        CP_ASYNC(d,       g_Vh + g);
        CP_ASYNC(d + VTB, g_Vl + g);
    }
}

__global__ void __launch_bounds__(256) hm_attnv()
{
    extern __shared__ __nv_bfloat16 sm[];
    const int tid = threadIdx.x, w = tid >> 5, lane = tid & 31;
    const int z = blockIdx.y, b = z >> 4, n = z & 15;
    const int i0 = blockIdx.x * 128;
    const int wm = (w & 3) * 32, wn = (w >> 2) * 32;
    const size_t zbase = (size_t)z * PLANE;
    const uint32_t sb = smem_u32(sm);
    const int lr = lane & 7, li = lane >> 3;

    float acc[2][4][4];
#pragma unroll
    for (int a = 0; a < 2; a++)
#pragma unroll
        for (int c = 0; c < 4; c++)
#pragma unroll
            for (int k = 0; k < 4; k++) acc[a][c][k] = 0.f;

    attnv_issue(sb, 0, 0, tid, i0, b, n, zbase);
    CP_COMMIT();

    for (int c = 0; c < 32; c++) {
        if (c < 31) {
            attnv_issue(sb, (c + 1) & 1, c + 1, tid, i0, b, n, zbase);
            CP_COMMIT();
            CP_WAIT1();
        } else {
            CP_WAIT0();
        }
        __syncthreads();

        const uint32_t bb = sb + (c & 1) * ABUF;
#pragma unroll
        for (int ks = 0; ks < 4; ks++) {
            uint32_t ahf[2][4], alf[2][4];
            const uint32_t acol = (uint32_t)(ks * 16 + (li >> 1) * 8) * 2;
            const uint32_t arow0 = (uint32_t)(wm + (li & 1) * 8 + lr);
#pragma unroll
            for (int mt = 0; mt < 2; mt++) {
                uint32_t ao = bb + (arow0 + mt * 16) * (SLD * 2) + acol;
                ldsm4(ahf[mt], ao);
                ldsm4(alf[mt], ao + STB);
            }
            uint32_t bhf[2][4], blf[2][4];
            const uint32_t vrow0 = (uint32_t)(ks * 16 + (li & 1) * 8 + lr);
#pragma unroll
            for (int nb = 0; nb < 2; nb++) {
                uint32_t vcol = (uint32_t)(wn + nb * 16 + (li >> 1) * 8) * 2;
                uint32_t bo = bb + 2*STB + vrow0 * (SLD * 2) + vcol;
                ldsm4t(bhf[nb], bo);
                ldsm4t(blf[nb], bo + VTB);
            }
#pragma unroll
            for (int mt = 0; mt < 2; mt++)
#pragma unroll
                for (int nt = 0; nt < 4; nt++) {
                    const uint32_t* bh = &bhf[nt >> 1][(nt & 1) * 2];
                    const uint32_t* bl = &blf[nt >> 1][(nt & 1) * 2];
                    mma16816(acc[mt][nt], ahf[mt], bh);
                    mma16816(acc[mt][nt], ahf[mt], bl);
                    mma16816(acc[mt][nt], alf[mt], bh);
                }
        }
        __syncthreads();
    }

#pragma unroll
    for (int mt = 0; mt < 2; mt++) {
        int i = i0 + wm + mt * 16 + (lane >> 2);
#pragma unroll
        for (int half = 0; half < 2; half++) {
            size_t rbase = ((size_t)(i + half * 8) * 4 + b) * 1024 + n * 64;
#pragma unroll
            for (int nt = 0; nt < 4; nt++) {
                int col = wn + nt * 8 + (lane & 3) * 2;
                __nv_bfloat162 h, l;
                split2(acc[mt][nt][half*2+0], acc[mt][nt][half*2+1], h, l);
                size_t d = (rbase + col) >> 1;
                ((__nv_bfloat162*)g_O1h)[d] = h;
                ((__nv_bfloat162*)g_O1l)[d] = l;
            }
        }
    }
}

// ---------------------------------------------------------------------------
__global__ void write_mems(const float4* __restrict__ mems,
                           const float4* __restrict__ out,
                           float4* __restrict__ dst)
{
    int idx = blockIdx.x * blockDim.x + threadIdx.x;
    int row = idx >> 8, c = idx & 255;
    int b = row >> 11, pos = row & 2047;
    float4 v;
    if (pos < 1024) v = mems[idx];
    else            v = out[(((size_t)b * 1024) + (pos - 1024)) * 256 + c];
    dst[idx] = v;
}

// ---------------------------------------------------------------------------
extern "C" void kernel_launch(void* const* d_in, const int* in_sizes, int n_in,
                              void* d_out, int out_size)
{
    const float* TE    = (const float*)d_in[0];
    const float* REL   = (const float*)d_in[1];
    const float* MEMS  = (const float*)d_in[2];
    const float* AMASK = (const float*)d_in[3];
    const float* Wq = (const float*)d_in[4],  *bq = (const float*)d_in[5];
    const float* Wk = (const float*)d_in[6],  *bk = (const float*)d_in[7];
    const float* Wv = (const float*)d_in[8],  *bv = (const float*)d_in[9];
    const float* Wr = (const float*)d_in[10], *br = (const float*)d_in[11];
    const float* Wo = (const float*)d_in[12], *bo = (const float*)d_in[13];
    const float* u  = (const float*)d_in[14];
    const float* v  = (const float*)d_in[15];
    float* out = (float*)d_out;

    const int G_SMEM = 2 * 4 * GTB;   // 81920
    const int S_SMEM = 4 * STB;       // 73728
    const int A_SMEM = 2 * ABUF;      // 110592
    cudaFuncSetAttribute(hm_gemm,   cudaFuncAttributeMaxDynamicSharedMemorySize, G_SMEM);
    cudaFuncSetAttribute(hm_scores, cudaFuncAttributeMaxDynamicSharedMemorySize, S_SMEM);
    cudaFuncSetAttribute(hm_attnv,  cudaFuncAttributeMaxDynamicSharedMemorySize, A_SMEM);

    float *pAC, *pBD;
    cudaGetSymbolAddress((void**)&pAC, g_AC);
    cudaGetSymbolAddress((void**)&pBD, g_BD);

    __nv_bfloat16 *pTEh, *pTEl, *pRELh, *pRELl, *pWh, *pWl;
    __nv_bfloat16 *pKVh, *pKVl, *pQUh, *pQUl, *pQVh, *pQVl;
    __nv_bfloat16 *pKh, *pKl, *pRh, *pRl, *pVh, *pVl, *pO1h, *pO1l;
    cudaGetSymbolAddress((void**)&pTEh,  g_TEh);  cudaGetSymbolAddress((void**)&pTEl,  g_TEl);
    cudaGetSymbolAddress((void**)&pRELh, g_RELh); cudaGetSymbolAddress((void**)&pRELl, g_RELl);
    cudaGetSymbolAddress((void**)&pWh,   g_Wh);   cudaGetSymbolAddress((void**)&pWl,   g_Wl);
    cudaGetSymbolAddress((void**)&pKVh,  g_KVh);  cudaGetSymbolAddress((void**)&pKVl,  g_KVl);
    cudaGetSymbolAddress((void**)&pQUh,  g_QUh);  cudaGetSymbolAddress((void**)&pQUl,  g_QUl);
    cudaGetSymbolAddress((void**)&pQVh,  g_QVh);  cudaGetSymbolAddress((void**)&pQVl,  g_QVl);
    cudaGetSymbolAddress((void**)&pKh,   g_Kh);   cudaGetSymbolAddress((void**)&pKl,   g_Kl);
    cudaGetSymbolAddress((void**)&pRh,   g_Rh);   cudaGetSymbolAddress((void**)&pRl,   g_Rl);
    cudaGetSymbolAddress((void**)&pVh,   g_Vh);   cudaGetSymbolAddress((void**)&pVl,   g_Vl);
    cudaGetSymbolAddress((void**)&pO1h,  g_O1h);  cudaGetSymbolAddress((void**)&pO1l,  g_O1l);

    const size_t WSZ = (size_t)1024 * 1024;

    // 1. input splits + fused gather/split of kv
    gather_split_kv<<<8192, 256>>>((const float4*)TE, (const float4*)MEMS);
    split_bf16<<<4096, 256>>>((const float4*)TE,  (__nv_bfloat162*)pTEh,  (__nv_bfloat162*)pTEl,  1048576);
    split_bf16<<<2048, 256>>>((const float4*)REL, (__nv_bfloat162*)pRELh, (__nv_bfloat162*)pRELl, 524288);
    split5_w<<<dim3(1024, 5), 256>>>((const float4*)Wq, (const float4*)Wk, (const float4*)Wv,
                                     (const float4*)Wr, (const float4*)Wo,
                                     (__nv_bfloat162*)pWh, (__nv_bfloat162*)pWl);

    // 2. projections (split epilogues — no fp32 intermediates)
    hm_gemm<<<dim3(8, 32), 256, G_SMEM>>>(pTEh, pTEl, pWh + 0*WSZ, pWl + 0*WSZ, bq, nullptr,
        (__nv_bfloat162*)pQUh, (__nv_bfloat162*)pQUl,
        (__nv_bfloat162*)pQVh, (__nv_bfloat162*)pQVl, u, v, 2);
    hm_gemm<<<dim3(8, 64), 256, G_SMEM>>>(pKVh, pKVl, pWh + 1*WSZ, pWl + 1*WSZ, bk, nullptr,
        (__nv_bfloat162*)pKh, (__nv_bfloat162*)pKl, nullptr, nullptr, nullptr, nullptr, 1);
    hm_gemm<<<dim3(8, 64), 256, G_SMEM>>>(pKVh, pKVl, pWh + 2*WSZ, pWl + 2*WSZ, bv, nullptr,
        (__nv_bfloat162*)pVh, (__nv_bfloat162*)pVl, nullptr, nullptr, nullptr, nullptr, 1);
    hm_gemm<<<dim3(8, 16), 256, G_SMEM>>>(pRELh, pRELl, pWh + 3*WSZ, pWl + 3*WSZ, br, nullptr,
        (__nv_bfloat162*)pRh, (__nv_bfloat162*)pRl, nullptr, nullptr, nullptr, nullptr, 1);

    // 3. score GEMMs -> AC / BD planes
    hm_scores<<<dim3(16, 8, 64), 256, S_SMEM>>>(pQUh, pQUl, pKh, pKl, pAC, 0);
    hm_scores<<<dim3(16, 8, 64), 256, S_SMEM>>>(pQVh, pQVl, pRh, pRl, pBD, 1);

    // 4. rel-shift + mask + softmax over heads -> ATT hi/lo
    softmax_heads<<<dim3(8, 1024, 4), 256>>>(AMASK);

    // 5. attn @ V (3-term) -> O1 hi/lo
    hm_attnv<<<dim3(8, 64), 256, A_SMEM>>>();

    // 6. O projection -> d_out (fp32)
    hm_gemm<<<dim3(8, 32), 256, G_SMEM>>>(pO1h, pO1l, pWh + 4*WSZ, pWl + 4*WSZ, bo, out,
        nullptr, nullptr, nullptr, nullptr, nullptr, nullptr, 0);

    // 7. mems_new
    if (out_size >= 12582912)
        write_mems<<<8192, 256>>>((const float4*)MEMS, (const float4*)out,
                                  (float4*)(out + 4194304));
}

// round 8
// speedup vs baseline: 1.1295x; 1.0720x over previous
#include <cuda_runtime.h>
#include <cuda_bf16.h>
#include <cuda_fp16.h>
#include <stdint.h>
#include <math.h>

// ---------------------------------------------------------------------------
// Problem constants: B=4, S=1024, H=1024, HEADS=16, HEAD_D=64, K=2048
// ---------------------------------------------------------------------------
#define PLANE 2097152ull   // 1024*2048

// ---------------- scratch ----------------
__device__ float         g_AC [(size_t)64 * PLANE];
__device__ float         g_BD [(size_t)64 * PLANE];
__device__ __half        g_ATT[(size_t)64 * PLANE];          // attn, single fp16

__device__ __nv_bfloat16 g_KVh [(size_t)8192*1024], g_KVl [(size_t)8192*1024];
__device__ __nv_bfloat16 g_RELh[(size_t)2048*1024], g_RELl[(size_t)2048*1024];
__device__ __nv_bfloat16 g_Wh  [(size_t)5*1024*1024], g_Wl [(size_t)5*1024*1024];
__device__ __nv_bfloat16 g_QUh [(size_t)4096*1024], g_QUl [(size_t)4096*1024];
__device__ __nv_bfloat16 g_QVh [(size_t)4096*1024], g_QVl [(size_t)4096*1024];
__device__ __nv_bfloat16 g_Kh  [(size_t)8192*1024], g_Kl  [(size_t)8192*1024];
__device__ __nv_bfloat16 g_Rh  [(size_t)2048*1024], g_Rl  [(size_t)2048*1024];
__device__ __half        g_Vh  [(size_t)8192*1024], g_Vl  [(size_t)8192*1024];  // fp16
__device__ __nv_bfloat16 g_O1h [(size_t)4096*1024], g_O1l [(size_t)4096*1024];

// ---------------------------------------------------------------------------
// Low-level helpers (sm_80-compatible: ldmatrix / mma.sync / cp.async)
// ---------------------------------------------------------------------------
__device__ __forceinline__ uint32_t smem_u32(const void* p) {
    uint32_t a;
    asm("{ .reg .u64 t; cvta.to.shared.u64 t, %1; cvt.u32.u64 %0, t; }"
        : "=r"(a) : "l"(p));
    return a;
}
__device__ __forceinline__ void ldsm4(uint32_t* r, uint32_t a) {
    asm volatile("ldmatrix.sync.aligned.m8n8.x4.shared.b16 {%0,%1,%2,%3}, [%4];"
        : "=r"(r[0]), "=r"(r[1]), "=r"(r[2]), "=r"(r[3]) : "r"(a));
}
__device__ __forceinline__ void ldsm4t(uint32_t* r, uint32_t a) {
    asm volatile("ldmatrix.sync.aligned.m8n8.x4.trans.shared.b16 {%0,%1,%2,%3}, [%4];"
        : "=r"(r[0]), "=r"(r[1]), "=r"(r[2]), "=r"(r[3]) : "r"(a));
}
__device__ __forceinline__ void mma16816(float* c, const uint32_t* a, const uint32_t* b) {
    asm volatile(
        "mma.sync.aligned.m16n8k16.row.col.f32.bf16.bf16.f32 "
        "{%0,%1,%2,%3}, {%4,%5,%6,%7}, {%8,%9}, {%0,%1,%2,%3};"
        : "+f"(c[0]), "+f"(c[1]), "+f"(c[2]), "+f"(c[3])
        : "r"(a[0]), "r"(a[1]), "r"(a[2]), "r"(a[3]), "r"(b[0]), "r"(b[1]));
}
__device__ __forceinline__ void mma16816h(float* c, const uint32_t* a, const uint32_t* b) {
    asm volatile(
        "mma.sync.aligned.m16n8k16.row.col.f32.f16.f16.f32 "
        "{%0,%1,%2,%3}, {%4,%5,%6,%7}, {%8,%9}, {%0,%1,%2,%3};"
        : "+f"(c[0]), "+f"(c[1]), "+f"(c[2]), "+f"(c[3])
        : "r"(a[0]), "r"(a[1]), "r"(a[2]), "r"(a[3]), "r"(b[0]), "r"(b[1]));
}
#define CP_ASYNC(dst, src) \
    asm volatile("cp.async.cg.shared.global [%0], [%1], 16;" :: "r"(dst), "l"(src))
#define CP_COMMIT() asm volatile("cp.async.commit_group;" ::: "memory")
#define CP_WAIT1()  asm volatile("cp.async.wait_group 1;" ::: "memory")
#define CP_WAIT0()  asm volatile("cp.async.wait_group 0;" ::: "memory")

__device__ __forceinline__ void split2(float x, float y,
                                       __nv_bfloat162& h, __nv_bfloat162& l) {
    __nv_bfloat16 hx = __float2bfloat16(x), hy = __float2bfloat16(y);
    h = __halves2bfloat162(hx, hy);
    l = __halves2bfloat162(__float2bfloat16(x - __bfloat162float(hx)),
                           __float2bfloat16(y - __bfloat162float(hy)));
}
__device__ __forceinline__ void split2h(float x, float y,
                                        __half2& h, __half2& l) {
    __half hx = __float2half_rn(x), hy = __float2half_rn(y);
    h = __halves2half2(hx, hy);
    l = __halves2half2(__float2half_rn(x - __half2float(hx)),
                       __float2half_rn(y - __half2float(hy)));
}

// ---------------------------------------------------------------------------
// split fp32 -> bf16 hi/lo (generic)
// ---------------------------------------------------------------------------
__global__ void split_bf16(const float4* __restrict__ in,
                           __nv_bfloat162* __restrict__ hi,
                           __nv_bfloat162* __restrict__ lo, int n4)
{
    int i = blockIdx.x * blockDim.x + threadIdx.x;
    if (i >= n4) return;
    float4 x = in[i];
    __nv_bfloat162 h0, l0, h1, l1;
    split2(x.x, x.y, h0, l0);
    split2(x.z, x.w, h1, l1);
    hi[i*2+0] = h0; hi[i*2+1] = h1;
    lo[i*2+0] = l0; lo[i*2+1] = l1;
}

// split 5 weight matrices in one launch
__global__ void split5_w(const float4* w0, const float4* w1, const float4* w2,
                         const float4* w3, const float4* w4,
                         __nv_bfloat162* __restrict__ hi,
                         __nv_bfloat162* __restrict__ lo)
{
    const float4* srcs[5] = {w0, w1, w2, w3, w4};
    int which = blockIdx.y;
    int i = blockIdx.x * blockDim.x + threadIdx.x;      // 0..262143
    float4 x = srcs[which][i];
    size_t d = (size_t)which * 524288 + (size_t)i * 2;
    __nv_bfloat162 h0, l0, h1, l1;
    split2(x.x, x.y, h0, l0);
    split2(x.z, x.w, h1, l1);
    hi[d] = h0; hi[d+1] = h1;
    lo[d] = l0; lo[d+1] = l1;
}

// gather kv_in (natural flat order row = b*2048+j) + split to bf16 hi/lo
__global__ void gather_split_kv(const float4* __restrict__ te,
                                const float4* __restrict__ mems)
{
    int idx = blockIdx.x * blockDim.x + threadIdx.x;    // 8192*256
    int row = idx >> 8, c = idx & 255;
    int b = row >> 11, j = row & 2047;
    float4 x;
    if (j < 1024) x = te  [((size_t)b * 1024 + j) * 256 + c];
    else          x = mems[((size_t)b * 2048 + (j - 1024)) * 256 + c];
    __nv_bfloat162 h0, l0, h1, l1;
    split2(x.x, x.y, h0, l0);
    split2(x.z, x.w, h1, l1);
    ((__nv_bfloat162*)g_KVh)[idx*2]   = h0;
    ((__nv_bfloat162*)g_KVh)[idx*2+1] = h1;
    ((__nv_bfloat162*)g_KVl)[idx*2]   = l0;
    ((__nv_bfloat162*)g_KVl)[idx*2+1] = l1;
}

// ---------------------------------------------------------------------------
// HMMA GEMM: C[M,1024] = A[M,1024] @ W[1024,1024]^T + bias, bf16-split 3-term.
// 128x128 CTA tile, BK=32, 8 warps (64x32), cp.async double-buffer.
// Epilogue modes: 0 = fp32+bias -> C; 1 = bias+split(bf16) -> o1;
//                 2 = dual split (bias+u -> o1, bias+v -> o2);
//                 3 = bias+split(fp16) -> o1.
// remapA: A rows remapped r -> r + (r>>10)*1024 (read TE rows out of KV buffer)
// ---------------------------------------------------------------------------
#define GLD 40
#define GTB 10240

__device__ __forceinline__ void gemm_issue(
    uint32_t sb, int buf, int c, int tid,
    const __nv_bfloat16* Ah, const __nv_bfloat16* Al,
    const __nv_bfloat16* Wh, const __nv_bfloat16* Wl, int m0, int n0, int remapA)
{
    const int k0 = c * 32;
    const uint32_t base = sb + buf * 4 * GTB;
#pragma unroll
    for (int p = 0; p < 2; p++) {
        int ch = tid + p * 256;
        int r = ch >> 2, s = ch & 3;
        uint32_t d = base + (uint32_t)(r * GLD + s * 8) * 2;
        int arow = m0 + r;
        if (remapA) arow += (arow >> 10) << 10;
        size_t ga = (size_t)arow * 1024 + k0 + s * 8;
        size_t gw = (size_t)(n0 + r) * 1024 + k0 + s * 8;
        CP_ASYNC(d,         Ah + ga);
        CP_ASYNC(d + GTB,   Al + ga);
        CP_ASYNC(d + 2*GTB, Wh + gw);
        CP_ASYNC(d + 3*GTB, Wl + gw);
    }
}

__global__ void __launch_bounds__(256) hm_gemm(
    const __nv_bfloat16* __restrict__ Ah, const __nv_bfloat16* __restrict__ Al,
    const __nv_bfloat16* __restrict__ Wh, const __nv_bfloat16* __restrict__ Wl,
    const float* __restrict__ bias, float* __restrict__ C,
    void* __restrict__ o1h, void* __restrict__ o1l,
    void* __restrict__ o2h, void* __restrict__ o2l,
    const float* __restrict__ addu, const float* __restrict__ addv,
    int mode, int remapA)
{
    extern __shared__ __nv_bfloat16 sm[];
    const int tid = threadIdx.x, w = tid >> 5, lane = tid & 31;
    const int n0 = blockIdx.x * 128, m0 = blockIdx.y * 128;
    const int wm = (w & 1) * 64, wn = (w >> 1) * 32;
    const uint32_t sb = smem_u32(sm);
    const int lr = lane & 7, li = lane >> 3;

    float acc[4][4][4];
#pragma unroll
    for (int a = 0; a < 4; a++)
#pragma unroll
        for (int b = 0; b < 4; b++)
#pragma unroll
            for (int k = 0; k < 4; k++) acc[a][b][k] = 0.f;

    gemm_issue(sb, 0, 0, tid, Ah, Al, Wh, Wl, m0, n0, remapA);
    CP_COMMIT();

    for (int c = 0; c < 32; c++) {
        if (c < 31) {
            gemm_issue(sb, (c + 1) & 1, c + 1, tid, Ah, Al, Wh, Wl, m0, n0, remapA);
            CP_COMMIT();
            CP_WAIT1();
        } else {
            CP_WAIT0();
        }
        __syncthreads();

        const uint32_t bb = sb + (c & 1) * 4 * GTB;
#pragma unroll
        for (int ks = 0; ks < 2; ks++) {
            uint32_t ahf[4][4], alf[4][4];
            const uint32_t acol = (uint32_t)(ks * 16 + (li >> 1) * 8) * 2;
            const uint32_t arow0 = (uint32_t)(wm + (li & 1) * 8 + lr);
#pragma unroll
            for (int mt = 0; mt < 4; mt++) {
                uint32_t ao = bb + (arow0 + mt * 16) * (GLD * 2) + acol;
                ldsm4(ahf[mt], ao);
                ldsm4(alf[mt], ao + GTB);
            }
            uint32_t bhf[2][4], blf[2][4];
            const uint32_t bcol = (uint32_t)(ks * 16 + (li & 1) * 8) * 2;
            const uint32_t brow0 = (uint32_t)(wn + (li >> 1) * 8 + lr);
#pragma unroll
            for (int nb = 0; nb < 2; nb++) {
                uint32_t bo = bb + 2*GTB + (brow0 + nb * 16) * (GLD * 2) + bcol;
                ldsm4(bhf[nb], bo);
                ldsm4(blf[nb], bo + GTB);
            }
#pragma unroll
            for (int mt = 0; mt < 4; mt++)
#pragma unroll
                for (int nt = 0; nt < 4; nt++) {
                    const uint32_t* bh = &bhf[nt >> 1][(nt & 1) * 2];
                    const uint32_t* bl = &blf[nt >> 1][(nt & 1) * 2];
                    mma16816(acc[mt][nt], ahf[mt], bh);
                    mma16816(acc[mt][nt], ahf[mt], bl);
                    mma16816(acc[mt][nt], alf[mt], bh);
                }
        }
        __syncthreads();
    }

#pragma unroll
    for (int mt = 0; mt < 4; mt++) {
        int m = m0 + wm + mt * 16 + (lane >> 2);
#pragma unroll
        for (int half = 0; half < 2; half++) {
            size_t mrow = (size_t)(m + half * 8);
#pragma unroll
            for (int nt = 0; nt < 4; nt++) {
                int col = wn + nt * 8 + (lane & 3) * 2;
                int cg = n0 + col;
                float x = acc[mt][nt][half*2+0] + bias[cg];
                float y = acc[mt][nt][half*2+1] + bias[cg+1];
                size_t d = (mrow * 1024 + cg) >> 1;
                if (mode == 0) {
                    *(float2*)(C + mrow * 1024 + cg) = make_float2(x, y);
                } else if (mode == 1) {
                    __nv_bfloat162 h, l;
                    split2(x, y, h, l);
                    ((__nv_bfloat162*)o1h)[d] = h; ((__nv_bfloat162*)o1l)[d] = l;
                } else if (mode == 2) {
                    __nv_bfloat162 h, l;
                    split2(x + addu[cg], y + addu[cg+1], h, l);
                    ((__nv_bfloat162*)o1h)[d] = h; ((__nv_bfloat162*)o1l)[d] = l;
                    split2(x + addv[cg], y + addv[cg+1], h, l);
                    ((__nv_bfloat162*)o2h)[d] = h; ((__nv_bfloat162*)o2l)[d] = l;
                } else {
                    __half2 h, l;
                    split2h(x, y, h, l);
                    ((__half2*)o1h)[d] = h; ((__half2*)o1l)[d] = l;
                }
            }
        }
    }
}

// ---------------------------------------------------------------------------
// HMMA batched scores, one launch. blockIdx.z in [0,128): mode = z>=64.
//   mode0 (AC): C[i,j] = (q+u)[i,b,n,:]·k[j,b,n,:]
//   mode1 (BD): C[i,l] = (q+v)[i,b,n,:]·kr[l,n,:]
// K=64 single shot. smem: 4 tiles x 128x72x2 = 73728 B (2 CTA/SM)
// ---------------------------------------------------------------------------
#define SLD 72
#define STB 18432

__global__ void __launch_bounds__(256) hm_scores(
    const __nv_bfloat16* __restrict__ QUh, const __nv_bfloat16* __restrict__ QUl,
    const __nv_bfloat16* __restrict__ Kh,  const __nv_bfloat16* __restrict__ Kl,
    const __nv_bfloat16* __restrict__ QVh, const __nv_bfloat16* __restrict__ QVl,
    const __nv_bfloat16* __restrict__ Rh,  const __nv_bfloat16* __restrict__ Rl,
    float* __restrict__ AC, float* __restrict__ BD)
{
    extern __shared__ __nv_bfloat16 sm[];
    const int tid = threadIdx.x, w = tid >> 5, lane = tid & 31;
    const int zz = blockIdx.z;
    const int mode = zz >= 64;
    const int z = zz & 63, b = z >> 4, n = z & 15;
    const int j0 = blockIdx.x * 128, i0 = blockIdx.y * 128;
    const int wm = (w & 1) * 64, wn = (w >> 1) * 32;
    const uint32_t sb = smem_u32(sm);
    const int lr = lane & 7, li = lane >> 3;

    const __nv_bfloat16* Ah = mode ? QVh : QUh;
    const __nv_bfloat16* Al = mode ? QVl : QUl;
    const __nv_bfloat16* Bh = mode ? Rh  : Kh;
    const __nv_bfloat16* Bl = mode ? Rl  : Kl;
    float* Out = mode ? BD : AC;

#pragma unroll
    for (int p = 0; p < 4; p++) {
        int ch = tid + p * 256;          // 0..1023
        int r = ch >> 3, s = ch & 7;
        uint32_t d = sb + (uint32_t)(r * SLD + s * 8) * 2;
        size_t ga = ((size_t)(i0 + r) * 4 + b) * 1024 + n * 64 + s * 8;
        size_t gb = mode ? ((size_t)(j0 + r) * 1024 + n * 64 + s * 8)
                         : (((size_t)(j0 + r) * 4 + b) * 1024 + n * 64 + s * 8);
        CP_ASYNC(d,           Ah + ga);
        CP_ASYNC(d + STB,     Al + ga);
        CP_ASYNC(d + 2*STB,   Bh + gb);
        CP_ASYNC(d + 3*STB,   Bl + gb);
    }
    CP_COMMIT();
    CP_WAIT0();
    __syncthreads();

    float acc[4][4][4];
#pragma unroll
    for (int a = 0; a < 4; a++)
#pragma unroll
        for (int c = 0; c < 4; c++)
#pragma unroll
            for (int k = 0; k < 4; k++) acc[a][c][k] = 0.f;

#pragma unroll
    for (int ks = 0; ks < 4; ks++) {
        uint32_t ahf[4][4], alf[4][4];
        const uint32_t acol = (uint32_t)(ks * 16 + (li >> 1) * 8) * 2;
        const uint32_t arow0 = (uint32_t)(wm + (li & 1) * 8 + lr);
#pragma unroll
        for (int mt = 0; mt < 4; mt++) {
            uint32_t ao = sb + (arow0 + mt * 16) * (SLD * 2) + acol;
            ldsm4(ahf[mt], ao);
            ldsm4(alf[mt], ao + STB);
        }
        uint32_t bhf[2][4], blf[2][4];
        const uint32_t bcol = (uint32_t)(ks * 16 + (li & 1) * 8) * 2;
        const uint32_t brow0 = (uint32_t)(wn + (li >> 1) * 8 + lr);
#pragma unroll
        for (int nb = 0; nb < 2; nb++) {
            uint32_t bo = sb + 2*STB + (brow0 + nb * 16) * (SLD * 2) + bcol;
            ldsm4(bhf[nb], bo);
            ldsm4(blf[nb], bo + STB);
        }
#pragma unroll
        for (int mt = 0; mt < 4; mt++)
#pragma unroll
            for (int nt = 0; nt < 4; nt++) {
                const uint32_t* bh = &bhf[nt >> 1][(nt & 1) * 2];
                const uint32_t* bl = &blf[nt >> 1][(nt & 1) * 2];
                mma16816(acc[mt][nt], ahf[mt], bh);
                mma16816(acc[mt][nt], ahf[mt], bl);
                mma16816(acc[mt][nt], alf[mt], bh);
            }
    }

    const size_t obase = (size_t)z * PLANE;
#pragma unroll
    for (int mt = 0; mt < 4; mt++) {
        int row = i0 + wm + mt * 16 + (lane >> 2);
        float* r0 = Out + obase + (size_t)row * 2048 + j0 + wn;
        float* r8 = r0 + (size_t)8 * 2048;
#pragma unroll
        for (int nt = 0; nt < 4; nt++) {
            int col = nt * 8 + (lane & 3) * 2;
            *(float2*)(r0 + col) = make_float2(acc[mt][nt][0], acc[mt][nt][1]);
            *(float2*)(r8 + col) = make_float2(acc[mt][nt][2], acc[mt][nt][3]);
        }
    }
}

// ---------------------------------------------------------------------------
// Softmax over the 16-head axis: AC + shifted BD + mask -> ATT (single fp16)
// ---------------------------------------------------------------------------
__global__ void softmax_heads(const float* __restrict__ amask)
{
    const int j = blockIdx.x * 256 + threadIdx.x;   // 0..2047
    const int i = blockIdx.y;
    const int b = blockIdx.z;
    const int l = j + 1023 - i;
    const bool lv = (l < 2048);
    const int bprime = i >> 8;

    const size_t base = ((size_t)b * 16 * 1024 + i) * 2048;
    float s[16];
    float mx = -1e30f;
#pragma unroll
    for (int n = 0; n < 16; n++) {
        float ac = g_AC[base + (size_t)n * PLANE + j];
        float bd = lv ? g_BD[base + (size_t)n * PLANE + l] : 0.f;
        float val = (ac + bd) * 0.125f;
        int jp = (j * 64 + b * 16 + n) & 2047;
        float m = (jp < 1024) ? 1.f : amask[(size_t)bprime * 1024 + (jp - 1024)];
        val -= (1.f - m) * 1e9f;
        s[n] = val;
        mx = fmaxf(mx, val);
    }
    float sum = 0.f;
#pragma unroll
    for (int n = 0; n < 16; n++) { s[n] = __expf(s[n] - mx); sum += s[n]; }
    float inv = 1.f / sum;
#pragma unroll
    for (int n = 0; n < 16; n++)
        g_ATT[base + (size_t)n * PLANE + j] = __float2half_rn(s[n] * inv);
}

// ---------------------------------------------------------------------------
// HMMA attn@V, fp16 2-term: A·Vh + A·Vl. Writes O1 hi/lo bf16 split.
// smem/buf: ATT 18432 + Vh/l 2x9216 = 36864; x2 bufs = 73728 B (2 CTA/SM)
// ---------------------------------------------------------------------------
#define VTB 9216
#define ABUF 36864

__device__ __forceinline__ void attnv_issue(
    uint32_t sb, int buf, int c, int tid, int i0, int b, int n, size_t zbase)
{
    const uint32_t base = sb + buf * ABUF;
#pragma unroll
    for (int p = 0; p < 4; p++) {
        int ch = tid + p * 256;          // 0..1023
        int r = ch >> 3, s = ch & 7;
        uint32_t d = base + (uint32_t)(r * SLD + s * 8) * 2;
        size_t g = zbase + (size_t)(i0 + r) * 2048 + c * 64 + s * 8;
        CP_ASYNC(d, g_ATT + g);
    }
#pragma unroll
    for (int p = 0; p < 2; p++) {
        int ch = tid + p * 256;          // 0..511
        int r = ch >> 3, s = ch & 7;
        uint32_t d = base + STB + (uint32_t)(r * SLD + s * 8) * 2;
        size_t g = ((size_t)(c * 64 + r) * 4 + b) * 1024 + n * 64 + s * 8;
        CP_ASYNC(d,       g_Vh + g);
        CP_ASYNC(d + VTB, g_Vl + g);
    }
}

__global__ void __launch_bounds__(256) hm_attnv()
{
    extern __shared__ __nv_bfloat16 sm[];
    const int tid = threadIdx.x, w = tid >> 5, lane = tid & 31;
    const int z = blockIdx.y, b = z >> 4, n = z & 15;
    const int i0 = blockIdx.x * 128;
    const int wm = (w & 3) * 32, wn = (w >> 2) * 32;
    const size_t zbase = (size_t)z * PLANE;
    const uint32_t sb = smem_u32(sm);
    const int lr = lane & 7, li = lane >> 3;

    float acc[2][4][4];
#pragma unroll
    for (int a = 0; a < 2; a++)
#pragma unroll
        for (int c = 0; c < 4; c++)
#pragma unroll
            for (int k = 0; k < 4; k++) acc[a][c][k] = 0.f;

    attnv_issue(sb, 0, 0, tid, i0, b, n, zbase);
    CP_COMMIT();

    for (int c = 0; c < 32; c++) {
        if (c < 31) {
            attnv_issue(sb, (c + 1) & 1, c + 1, tid, i0, b, n, zbase);
            CP_COMMIT();
            CP_WAIT1();
        } else {
            CP_WAIT0();
        }
        __syncthreads();

        const uint32_t bb = sb + (c & 1) * ABUF;
#pragma unroll
        for (int ks = 0; ks < 4; ks++) {
            uint32_t ahf[2][4];
            const uint32_t acol = (uint32_t)(ks * 16 + (li >> 1) * 8) * 2;
            const uint32_t arow0 = (uint32_t)(wm + (li & 1) * 8 + lr);
#pragma unroll
            for (int mt = 0; mt < 2; mt++) {
                uint32_t ao = bb + (arow0 + mt * 16) * (SLD * 2) + acol;
                ldsm4(ahf[mt], ao);
            }
            uint32_t bhf[2][4], blf[2][4];
            const uint32_t vrow0 = (uint32_t)(ks * 16 + (li & 1) * 8 + lr);
#pragma unroll
            for (int nb = 0; nb < 2; nb++) {
                uint32_t vcol = (uint32_t)(wn + nb * 16 + (li >> 1) * 8) * 2;
                uint32_t bo = bb + STB + vrow0 * (SLD * 2) + vcol;
                ldsm4t(bhf[nb], bo);
                ldsm4t(blf[nb], bo + VTB);
            }
#pragma unroll
            for (int mt = 0; mt < 2; mt++)
#pragma unroll
                for (int nt = 0; nt < 4; nt++) {
                    const uint32_t* bh = &bhf[nt >> 1][(nt & 1) * 2];
                    const uint32_t* bl = &blf[nt >> 1][(nt & 1) * 2];
                    mma16816h(acc[mt][nt], ahf[mt], bh);
                    mma16816h(acc[mt][nt], ahf[mt], bl);
                }
        }
        __syncthreads();
    }

#pragma unroll
    for (int mt = 0; mt < 2; mt++) {
        int i = i0 + wm + mt * 16 + (lane >> 2);
#pragma unroll
        for (int half = 0; half < 2; half++) {
            size_t rbase = ((size_t)(i + half * 8) * 4 + b) * 1024 + n * 64;
#pragma unroll
            for (int nt = 0; nt < 4; nt++) {
                int col = wn + nt * 8 + (lane & 3) * 2;
                __nv_bfloat162 h, l;
                split2(acc[mt][nt][half*2+0], acc[mt][nt][half*2+1], h, l);
                size_t d = (rbase + col) >> 1;
                ((__nv_bfloat162*)g_O1h)[d] = h;
                ((__nv_bfloat162*)g_O1l)[d] = l;
            }
        }
    }
}

// ---------------------------------------------------------------------------
__global__ void write_mems(const float4* __restrict__ mems,
                           const float4* __restrict__ out,
                           float4* __restrict__ dst)
{
    int idx = blockIdx.x * blockDim.x + threadIdx.x;
    int row = idx >> 8, c = idx & 255;
    int b = row >> 11, pos = row & 2047;
    float4 v;
    if (pos < 1024) v = mems[idx];
    else            v = out[(((size_t)b * 1024) + (pos - 1024)) * 256 + c];
    dst[idx] = v;
}

// ---------------------------------------------------------------------------
extern "C" void kernel_launch(void* const* d_in, const int* in_sizes, int n_in,
                              void* d_out, int out_size)
{
    const float* TE    = (const float*)d_in[0];
    const float* REL   = (const float*)d_in[1];
    const float* MEMS  = (const float*)d_in[2];
    const float* AMASK = (const float*)d_in[3];
    const float* Wq = (const float*)d_in[4],  *bq = (const float*)d_in[5];
    const float* Wk = (const float*)d_in[6],  *bk = (const float*)d_in[7];
    const float* Wv = (const float*)d_in[8],  *bv = (const float*)d_in[9];
    const float* Wr = (const float*)d_in[10], *br = (const float*)d_in[11];
    const float* Wo = (const float*)d_in[12], *bo = (const float*)d_in[13];
    const float* u  = (const float*)d_in[14];
    const float* v  = (const float*)d_in[15];
    float* out = (float*)d_out;

    const int G_SMEM = 2 * 4 * GTB;   // 81920
    const int S_SMEM = 4 * STB;       // 73728
    const int A_SMEM = 2 * ABUF;      // 73728
    cudaFuncSetAttribute(hm_gemm,   cudaFuncAttributeMaxDynamicSharedMemorySize, G_SMEM);
    cudaFuncSetAttribute(hm_scores, cudaFuncAttributeMaxDynamicSharedMemorySize, S_SMEM);
    cudaFuncSetAttribute(hm_attnv,  cudaFuncAttributeMaxDynamicSharedMemorySize, A_SMEM);

    float *pAC, *pBD;
    cudaGetSymbolAddress((void**)&pAC, g_AC);
    cudaGetSymbolAddress((void**)&pBD, g_BD);

    __nv_bfloat16 *pRELh, *pRELl, *pWh, *pWl;
    __nv_bfloat16 *pKVh, *pKVl, *pQUh, *pQUl, *pQVh, *pQVl;
    __nv_bfloat16 *pKh, *pKl, *pRh, *pRl, *pO1h, *pO1l;
    __half *pVh, *pVl;
    cudaGetSymbolAddress((void**)&pRELh, g_RELh); cudaGetSymbolAddress((void**)&pRELl, g_RELl);
    cudaGetSymbolAddress((void**)&pWh,   g_Wh);   cudaGetSymbolAddress((void**)&pWl,   g_Wl);
    cudaGetSymbolAddress((void**)&pKVh,  g_KVh);  cudaGetSymbolAddress((void**)&pKVl,  g_KVl);
    cudaGetSymbolAddress((void**)&pQUh,  g_QUh);  cudaGetSymbolAddress((void**)&pQUl,  g_QUl);
    cudaGetSymbolAddress((void**)&pQVh,  g_QVh);  cudaGetSymbolAddress((void**)&pQVl,  g_QVl);
    cudaGetSymbolAddress((void**)&pKh,   g_Kh);   cudaGetSymbolAddress((void**)&pKl,   g_Kl);
    cudaGetSymbolAddress((void**)&pRh,   g_Rh);   cudaGetSymbolAddress((void**)&pRl,   g_Rl);
    cudaGetSymbolAddress((void**)&pVh,   g_Vh);   cudaGetSymbolAddress((void**)&pVl,   g_Vl);
    cudaGetSymbolAddress((void**)&pO1h,  g_O1h);  cudaGetSymbolAddress((void**)&pO1l,  g_O1l);

    const size_t WSZ = (size_t)1024 * 1024;

    // 1. input splits (TE split eliminated via remapA; see Q-proj)
    gather_split_kv<<<8192, 256>>>((const float4*)TE, (const float4*)MEMS);
    split_bf16<<<2048, 256>>>((const float4*)REL, (__nv_bfloat162*)pRELh, (__nv_bfloat162*)pRELl, 524288);
    split5_w<<<dim3(1024, 5), 256>>>((const float4*)Wq, (const float4*)Wk, (const float4*)Wv,
                                     (const float4*)Wr, (const float4*)Wo,
                                     (__nv_bfloat162*)pWh, (__nv_bfloat162*)pWl);

    // 2. projections
    hm_gemm<<<dim3(8, 32), 256, G_SMEM>>>(pKVh, pKVl, pWh + 0*WSZ, pWl + 0*WSZ, bq, nullptr,
        pQUh, pQUl, pQVh, pQVl, u, v, 2, 1);                       // Q (remapA)
    hm_gemm<<<dim3(8, 64), 256, G_SMEM>>>(pKVh, pKVl, pWh + 1*WSZ, pWl + 1*WSZ, bk, nullptr,
        pKh, pKl, nullptr, nullptr, nullptr, nullptr, 1, 0);       // K (bf16 split)
    hm_gemm<<<dim3(8, 64), 256, G_SMEM>>>(pKVh, pKVl, pWh + 2*WSZ, pWl + 2*WSZ, bv, nullptr,
        pVh, pVl, nullptr, nullptr, nullptr, nullptr, 3, 0);       // V (fp16 split)
    hm_gemm<<<dim3(8, 16), 256, G_SMEM>>>(pRELh, pRELl, pWh + 3*WSZ, pWl + 3*WSZ, br, nullptr,
        pRh, pRl, nullptr, nullptr, nullptr, nullptr, 1, 0);       // R

    // 3. score GEMMs (AC + BD in one launch)
    hm_scores<<<dim3(16, 8, 128), 256, S_SMEM>>>(pQUh, pQUl, pKh, pKl,
                                                 pQVh, pQVl, pRh, pRl, pAC, pBD);

    // 4. rel-shift + mask + softmax over heads -> ATT (fp16)
    softmax_heads<<<dim3(8, 1024, 4), 256>>>(AMASK);

    // 5. attn @ V (fp16 2-term) -> O1 hi/lo
    hm_attnv<<<dim3(8, 64), 256, A_SMEM>>>();

    // 6. O projection -> d_out (fp32)
    hm_gemm<<<dim3(8, 32), 256, G_SMEM>>>(pO1h, pO1l, pWh + 4*WSZ, pWl + 4*WSZ, bo, out,
        nullptr, nullptr, nullptr, nullptr, nullptr, nullptr, 0, 0);

    // 7. mems_new
    if (out_size >= 12582912)
        write_mems<<<8192, 256>>>((const float4*)MEMS, (const float4*)out,
                                  (float4*)(out + 4194304));
}

// round 9
// speedup vs baseline: 1.2302x; 1.0892x over previous
#include <cuda_runtime.h>
#include <cuda_bf16.h>
#include <cuda_fp16.h>
#include <stdint.h>
#include <math.h>

// ---------------------------------------------------------------------------
// Problem constants: B=4, S=1024, H=1024, HEADS=16, HEAD_D=64, K=2048
// ---------------------------------------------------------------------------
#define PLANE 2097152ull   // 1024*2048

// ---------------- scratch ----------------
__device__ float         g_AC [(size_t)64 * PLANE];
__device__ float         g_BD [(size_t)64 * PLANE];
__device__ __half        g_ATT[(size_t)64 * PLANE];          // attn, single fp16

__device__ __nv_bfloat16 g_KVh [(size_t)8192*1024], g_KVl [(size_t)8192*1024];
__device__ __nv_bfloat16 g_RELh[(size_t)2048*1024], g_RELl[(size_t)2048*1024];
__device__ __nv_bfloat16 g_Wh  [(size_t)5*1024*1024], g_Wl [(size_t)5*1024*1024];
__device__ __nv_bfloat16 g_QUh [(size_t)4096*1024], g_QUl [(size_t)4096*1024];
__device__ __nv_bfloat16 g_QVh [(size_t)4096*1024], g_QVl [(size_t)4096*1024];
__device__ __nv_bfloat16 g_Kh  [(size_t)8192*1024], g_Kl  [(size_t)8192*1024];
__device__ __nv_bfloat16 g_Rh  [(size_t)2048*1024], g_Rl  [(size_t)2048*1024];
__device__ __half        g_Vh  [(size_t)8192*1024], g_Vl  [(size_t)8192*1024];  // fp16
__device__ __nv_bfloat16 g_O1h [(size_t)4096*1024], g_O1l [(size_t)4096*1024];

// ---------------------------------------------------------------------------
// Low-level helpers (sm_80-compatible: ldmatrix / mma.sync / cp.async)
// ---------------------------------------------------------------------------
__device__ __forceinline__ uint32_t smem_u32(const void* p) {
    uint32_t a;
    asm("{ .reg .u64 t; cvta.to.shared.u64 t, %1; cvt.u32.u64 %0, t; }"
        : "=r"(a) : "l"(p));
    return a;
}
__device__ __forceinline__ void ldsm4(uint32_t* r, uint32_t a) {
    asm volatile("ldmatrix.sync.aligned.m8n8.x4.shared.b16 {%0,%1,%2,%3}, [%4];"
        : "=r"(r[0]), "=r"(r[1]), "=r"(r[2]), "=r"(r[3]) : "r"(a));
}
__device__ __forceinline__ void ldsm4t(uint32_t* r, uint32_t a) {
    asm volatile("ldmatrix.sync.aligned.m8n8.x4.trans.shared.b16 {%0,%1,%2,%3}, [%4];"
        : "=r"(r[0]), "=r"(r[1]), "=r"(r[2]), "=r"(r[3]) : "r"(a));
}
__device__ __forceinline__ void mma16816(float* c, const uint32_t* a, const uint32_t* b) {
    asm volatile(
        "mma.sync.aligned.m16n8k16.row.col.f32.bf16.bf16.f32 "
        "{%0,%1,%2,%3}, {%4,%5,%6,%7}, {%8,%9}, {%0,%1,%2,%3};"
        : "+f"(c[0]), "+f"(c[1]), "+f"(c[2]), "+f"(c[3])
        : "r"(a[0]), "r"(a[1]), "r"(a[2]), "r"(a[3]), "r"(b[0]), "r"(b[1]));
}
__device__ __forceinline__ void mma16816h(float* c, const uint32_t* a, const uint32_t* b) {
    asm volatile(
        "mma.sync.aligned.m16n8k16.row.col.f32.f16.f16.f32 "
        "{%0,%1,%2,%3}, {%4,%5,%6,%7}, {%8,%9}, {%0,%1,%2,%3};"
        : "+f"(c[0]), "+f"(c[1]), "+f"(c[2]), "+f"(c[3])
        : "r"(a[0]), "r"(a[1]), "r"(a[2]), "r"(a[3]), "r"(b[0]), "r"(b[1]));
}
#define CP_ASYNC(dst, src) \
    asm volatile("cp.async.cg.shared.global [%0], [%1], 16;" :: "r"(dst), "l"(src))
#define CP_COMMIT() asm volatile("cp.async.commit_group;" ::: "memory")
#define CP_WAIT1()  asm volatile("cp.async.wait_group 1;" ::: "memory")
#define CP_WAIT0()  asm volatile("cp.async.wait_group 0;" ::: "memory")

__device__ __forceinline__ void split2(float x, float y,
                                       __nv_bfloat162& h, __nv_bfloat162& l) {
    __nv_bfloat16 hx = __float2bfloat16(x), hy = __float2bfloat16(y);
    h = __halves2bfloat162(hx, hy);
    l = __halves2bfloat162(__float2bfloat16(x - __bfloat162float(hx)),
                           __float2bfloat16(y - __bfloat162float(hy)));
}
__device__ __forceinline__ void split2h(float x, float y,
                                        __half2& h, __half2& l) {
    __half hx = __float2half_rn(x), hy = __float2half_rn(y);
    h = __halves2half2(hx, hy);
    l = __halves2half2(__float2half_rn(x - __half2float(hx)),
                       __float2half_rn(y - __half2float(hy)));
}

// ---------------------------------------------------------------------------
// split fp32 -> bf16 hi/lo (generic)
// ---------------------------------------------------------------------------
__global__ void split_bf16(const float4* __restrict__ in,
                           __nv_bfloat162* __restrict__ hi,
                           __nv_bfloat162* __restrict__ lo, int n4)
{
    int i = blockIdx.x * blockDim.x + threadIdx.x;
    if (i >= n4) return;
    float4 x = in[i];
    __nv_bfloat162 h0, l0, h1, l1;
    split2(x.x, x.y, h0, l0);
    split2(x.z, x.w, h1, l1);
    hi[i*2+0] = h0; hi[i*2+1] = h1;
    lo[i*2+0] = l0; lo[i*2+1] = l1;
}

// split 5 weight matrices in one launch
__global__ void split5_w(const float4* w0, const float4* w1, const float4* w2,
                         const float4* w3, const float4* w4,
                         __nv_bfloat162* __restrict__ hi,
                         __nv_bfloat162* __restrict__ lo)
{
    const float4* srcs[5] = {w0, w1, w2, w3, w4};
    int which = blockIdx.y;
    int i = blockIdx.x * blockDim.x + threadIdx.x;      // 0..262143
    float4 x = srcs[which][i];
    size_t d = (size_t)which * 524288 + (size_t)i * 2;
    __nv_bfloat162 h0, l0, h1, l1;
    split2(x.x, x.y, h0, l0);
    split2(x.z, x.w, h1, l1);
    hi[d] = h0; hi[d+1] = h1;
    lo[d] = l0; lo[d+1] = l1;
}

// gather kv_in (natural flat order row = b*2048+j) + split to bf16 hi/lo
__global__ void gather_split_kv(const float4* __restrict__ te,
                                const float4* __restrict__ mems)
{
    int idx = blockIdx.x * blockDim.x + threadIdx.x;    // 8192*256
    int row = idx >> 8, c = idx & 255;
    int b = row >> 11, j = row & 2047;
    float4 x;
    if (j < 1024) x = te  [((size_t)b * 1024 + j) * 256 + c];
    else          x = mems[((size_t)b * 2048 + (j - 1024)) * 256 + c];
    __nv_bfloat162 h0, l0, h1, l1;
    split2(x.x, x.y, h0, l0);
    split2(x.z, x.w, h1, l1);
    ((__nv_bfloat162*)g_KVh)[idx*2]   = h0;
    ((__nv_bfloat162*)g_KVh)[idx*2+1] = h1;
    ((__nv_bfloat162*)g_KVl)[idx*2]   = l0;
    ((__nv_bfloat162*)g_KVl)[idx*2+1] = l1;
}

// ---------------------------------------------------------------------------
// HMMA GEMM: C[M,1024] = A[M,1024] @ W[1024,1024]^T + bias, bf16-split 3-term.
// 128x128 CTA tile, BK=32, 8 warps (64x32), cp.async double-buffer.
// __launch_bounds__(256,2): cap regs at 128 so 2 CTAs/SM are resident.
// Epilogue modes: 0 = fp32+bias -> C; 1 = bias+split(bf16) -> o1;
//                 2 = dual split (bias+u -> o1, bias+v -> o2);
//                 3 = bias+split(fp16) -> o1.
// remapA: A rows remapped r -> r + (r>>10)*1024 (read TE rows out of KV buffer)
// ---------------------------------------------------------------------------
#define GLD 40
#define GTB 10240

__device__ __forceinline__ void gemm_issue(
    uint32_t sb, int buf, int c, int tid,
    const __nv_bfloat16* Ah, const __nv_bfloat16* Al,
    const __nv_bfloat16* Wh, const __nv_bfloat16* Wl, int m0, int n0, int remapA)
{
    const int k0 = c * 32;
    const uint32_t base = sb + buf * 4 * GTB;
#pragma unroll
    for (int p = 0; p < 2; p++) {
        int ch = tid + p * 256;
        int r = ch >> 2, s = ch & 3;
        uint32_t d = base + (uint32_t)(r * GLD + s * 8) * 2;
        int arow = m0 + r;
        if (remapA) arow += (arow >> 10) << 10;
        size_t ga = (size_t)arow * 1024 + k0 + s * 8;
        size_t gw = (size_t)(n0 + r) * 1024 + k0 + s * 8;
        CP_ASYNC(d,         Ah + ga);
        CP_ASYNC(d + GTB,   Al + ga);
        CP_ASYNC(d + 2*GTB, Wh + gw);
        CP_ASYNC(d + 3*GTB, Wl + gw);
    }
}

__global__ void __launch_bounds__(256, 2) hm_gemm(
    const __nv_bfloat16* __restrict__ Ah, const __nv_bfloat16* __restrict__ Al,
    const __nv_bfloat16* __restrict__ Wh, const __nv_bfloat16* __restrict__ Wl,
    const float* __restrict__ bias, float* __restrict__ C,
    void* __restrict__ o1h, void* __restrict__ o1l,
    void* __restrict__ o2h, void* __restrict__ o2l,
    const float* __restrict__ addu, const float* __restrict__ addv,
    int mode, int remapA)
{
    extern __shared__ __nv_bfloat16 sm[];
    const int tid = threadIdx.x, w = tid >> 5, lane = tid & 31;
    const int n0 = blockIdx.x * 128, m0 = blockIdx.y * 128;
    const int wm = (w & 1) * 64, wn = (w >> 1) * 32;
    const uint32_t sb = smem_u32(sm);
    const int lr = lane & 7, li = lane >> 3;

    float acc[4][4][4];
#pragma unroll
    for (int a = 0; a < 4; a++)
#pragma unroll
        for (int b = 0; b < 4; b++)
#pragma unroll
            for (int k = 0; k < 4; k++) acc[a][b][k] = 0.f;

    gemm_issue(sb, 0, 0, tid, Ah, Al, Wh, Wl, m0, n0, remapA);
    CP_COMMIT();

    for (int c = 0; c < 32; c++) {
        if (c < 31) {
            gemm_issue(sb, (c + 1) & 1, c + 1, tid, Ah, Al, Wh, Wl, m0, n0, remapA);
            CP_COMMIT();
            CP_WAIT1();
        } else {
            CP_WAIT0();
        }
        __syncthreads();

        const uint32_t bb = sb + (c & 1) * 4 * GTB;
#pragma unroll
        for (int ks = 0; ks < 2; ks++) {
            uint32_t ahf[4][4], alf[4][4];
            const uint32_t acol = (uint32_t)(ks * 16 + (li >> 1) * 8) * 2;
            const uint32_t arow0 = (uint32_t)(wm + (li & 1) * 8 + lr);
#pragma unroll
            for (int mt = 0; mt < 4; mt++) {
                uint32_t ao = bb + (arow0 + mt * 16) * (GLD * 2) + acol;
                ldsm4(ahf[mt], ao);
                ldsm4(alf[mt], ao + GTB);
            }
            uint32_t bhf[2][4], blf[2][4];
            const uint32_t bcol = (uint32_t)(ks * 16 + (li & 1) * 8) * 2;
            const uint32_t brow0 = (uint32_t)(wn + (li >> 1) * 8 + lr);
#pragma unroll
            for (int nb = 0; nb < 2; nb++) {
                uint32_t bo = bb + 2*GTB + (brow0 + nb * 16) * (GLD * 2) + bcol;
                ldsm4(bhf[nb], bo);
                ldsm4(blf[nb], bo + GTB);
            }
#pragma unroll
            for (int mt = 0; mt < 4; mt++)
#pragma unroll
                for (int nt = 0; nt < 4; nt++) {
                    const uint32_t* bh = &bhf[nt >> 1][(nt & 1) * 2];
                    const uint32_t* bl = &blf[nt >> 1][(nt & 1) * 2];
                    mma16816(acc[mt][nt], ahf[mt], bh);
                    mma16816(acc[mt][nt], ahf[mt], bl);
                    mma16816(acc[mt][nt], alf[mt], bh);
                }
        }
        __syncthreads();
    }

#pragma unroll
    for (int mt = 0; mt < 4; mt++) {
        int m = m0 + wm + mt * 16 + (lane >> 2);
#pragma unroll
        for (int half = 0; half < 2; half++) {
            size_t mrow = (size_t)(m + half * 8);
#pragma unroll
            for (int nt = 0; nt < 4; nt++) {
                int col = wn + nt * 8 + (lane & 3) * 2;
                int cg = n0 + col;
                float x = acc[mt][nt][half*2+0] + bias[cg];
                float y = acc[mt][nt][half*2+1] + bias[cg+1];
                size_t d = (mrow * 1024 + cg) >> 1;
                if (mode == 0) {
                    *(float2*)(C + mrow * 1024 + cg) = make_float2(x, y);
                } else if (mode == 1) {
                    __nv_bfloat162 h, l;
                    split2(x, y, h, l);
                    ((__nv_bfloat162*)o1h)[d] = h; ((__nv_bfloat162*)o1l)[d] = l;
                } else if (mode == 2) {
                    __nv_bfloat162 h, l;
                    split2(x + addu[cg], y + addu[cg+1], h, l);
                    ((__nv_bfloat162*)o1h)[d] = h; ((__nv_bfloat162*)o1l)[d] = l;
                    split2(x + addv[cg], y + addv[cg+1], h, l);
                    ((__nv_bfloat162*)o2h)[d] = h; ((__nv_bfloat162*)o2l)[d] = l;
                } else {
                    __half2 h, l;
                    split2h(x, y, h, l);
                    ((__half2*)o1h)[d] = h; ((__half2*)o1l)[d] = l;
                }
            }
        }
    }
}

// ---------------------------------------------------------------------------
// HMMA batched scores, one launch. blockIdx.z in [0,128): mode = z>=64.
//   mode0 (AC): C[i,j] = (q+u)[i,b,n,:]·k[j,b,n,:]
//   mode1 (BD): C[i,l] = (q+v)[i,b,n,:]·kr[l,n,:]
// K=64 single shot. smem: 4 tiles x 128x72x2 = 73728 B (2 CTA/SM)
// ---------------------------------------------------------------------------
#define SLD 72
#define STB 18432

__global__ void __launch_bounds__(256, 2) hm_scores(
    const __nv_bfloat16* __restrict__ QUh, const __nv_bfloat16* __restrict__ QUl,
    const __nv_bfloat16* __restrict__ Kh,  const __nv_bfloat16* __restrict__ Kl,
    const __nv_bfloat16* __restrict__ QVh, const __nv_bfloat16* __restrict__ QVl,
    const __nv_bfloat16* __restrict__ Rh,  const __nv_bfloat16* __restrict__ Rl,
    float* __restrict__ AC, float* __restrict__ BD)
{
    extern __shared__ __nv_bfloat16 sm[];
    const int tid = threadIdx.x, w = tid >> 5, lane = tid & 31;
    const int zz = blockIdx.z;
    const int mode = zz >= 64;
    const int z = zz & 63, b = z >> 4, n = z & 15;
    const int j0 = blockIdx.x * 128, i0 = blockIdx.y * 128;
    const int wm = (w & 1) * 64, wn = (w >> 1) * 32;
    const uint32_t sb = smem_u32(sm);
    const int lr = lane & 7, li = lane >> 3;

    const __nv_bfloat16* Ah = mode ? QVh : QUh;
    const __nv_bfloat16* Al = mode ? QVl : QUl;
    const __nv_bfloat16* Bh = mode ? Rh  : Kh;
    const __nv_bfloat16* Bl = mode ? Rl  : Kl;
    float* Out = mode ? BD : AC;

#pragma unroll
    for (int p = 0; p < 4; p++) {
        int ch = tid + p * 256;          // 0..1023
        int r = ch >> 3, s = ch & 7;
        uint32_t d = sb + (uint32_t)(r * SLD + s * 8) * 2;
        size_t ga = ((size_t)(i0 + r) * 4 + b) * 1024 + n * 64 + s * 8;
        size_t gb = mode ? ((size_t)(j0 + r) * 1024 + n * 64 + s * 8)
                         : (((size_t)(j0 + r) * 4 + b) * 1024 + n * 64 + s * 8);
        CP_ASYNC(d,           Ah + ga);
        CP_ASYNC(d + STB,     Al + ga);
        CP_ASYNC(d + 2*STB,   Bh + gb);
        CP_ASYNC(d + 3*STB,   Bl + gb);
    }
    CP_COMMIT();
    CP_WAIT0();
    __syncthreads();

    float acc[4][4][4];
#pragma unroll
    for (int a = 0; a < 4; a++)
#pragma unroll
        for (int c = 0; c < 4; c++)
#pragma unroll
            for (int k = 0; k < 4; k++) acc[a][c][k] = 0.f;

#pragma unroll
    for (int ks = 0; ks < 4; ks++) {
        uint32_t ahf[4][4], alf[4][4];
        const uint32_t acol = (uint32_t)(ks * 16 + (li >> 1) * 8) * 2;
        const uint32_t arow0 = (uint32_t)(wm + (li & 1) * 8 + lr);
#pragma unroll
        for (int mt = 0; mt < 4; mt++) {
            uint32_t ao = sb + (arow0 + mt * 16) * (SLD * 2) + acol;
            ldsm4(ahf[mt], ao);
            ldsm4(alf[mt], ao + STB);
        }
        uint32_t bhf[2][4], blf[2][4];
        const uint32_t bcol = (uint32_t)(ks * 16 + (li & 1) * 8) * 2;
        const uint32_t brow0 = (uint32_t)(wn + (li >> 1) * 8 + lr);
#pragma unroll
        for (int nb = 0; nb < 2; nb++) {
            uint32_t bo = sb + 2*STB + (brow0 + nb * 16) * (SLD * 2) + bcol;
            ldsm4(bhf[nb], bo);
            ldsm4(blf[nb], bo + STB);
        }
#pragma unroll
        for (int mt = 0; mt < 4; mt++)
#pragma unroll
            for (int nt = 0; nt < 4; nt++) {
                const uint32_t* bh = &bhf[nt >> 1][(nt & 1) * 2];
                const uint32_t* bl = &blf[nt >> 1][(nt & 1) * 2];
                mma16816(acc[mt][nt], ahf[mt], bh);
                mma16816(acc[mt][nt], ahf[mt], bl);
                mma16816(acc[mt][nt], alf[mt], bh);
            }
    }

    const size_t obase = (size_t)z * PLANE;
#pragma unroll
    for (int mt = 0; mt < 4; mt++) {
        int row = i0 + wm + mt * 16 + (lane >> 2);
        float* r0 = Out + obase + (size_t)row * 2048 + j0 + wn;
        float* r8 = r0 + (size_t)8 * 2048;
#pragma unroll
        for (int nt = 0; nt < 4; nt++) {
            int col = nt * 8 + (lane & 3) * 2;
            *(float2*)(r0 + col) = make_float2(acc[mt][nt][0], acc[mt][nt][1]);
            *(float2*)(r8 + col) = make_float2(acc[mt][nt][2], acc[mt][nt][3]);
        }
    }
}

// ---------------------------------------------------------------------------
// Softmax over the 16-head axis, 4 j per thread (float4):
//   AC + shifted BD + mask -> ATT (single fp16)
// ---------------------------------------------------------------------------
__global__ void softmax_heads(const float* __restrict__ amask)
{
    const int j4 = blockIdx.x * 128 + threadIdx.x;   // 0..511 (float4 col index)
    const int j  = j4 * 4;
    const int i  = blockIdx.y;
    const int b  = blockIdx.z;
    const int ioff = 1023 - i;                        // l = j + ioff
    const int bprime = i >> 8;
    const float* amrow = amask + (size_t)bprime * 1024;

    const size_t base = ((size_t)b * 16 * 1024 + i) * 2048;
    const float4* AC4 = (const float4*)(g_AC + base);

    float s[16][4];
    float mx[4] = {-1e30f, -1e30f, -1e30f, -1e30f};
#pragma unroll
    for (int n = 0; n < 16; n++) {
        float4 ac = AC4[(size_t)n * 524288 + j4];
        float a[4] = {ac.x, ac.y, ac.z, ac.w};
        const float* BDn = g_BD + base + (size_t)n * PLANE;
#pragma unroll
        for (int e = 0; e < 4; e++) {
            int l = j + e + ioff;
            float bd = (l < 2048) ? BDn[l] : 0.f;
            float val = (a[e] + bd) * 0.125f;
            int jp = ((j + e) * 64 + b * 16 + n) & 2047;
            float m = (jp < 1024) ? 1.f : amrow[jp - 1024];
            val -= (1.f - m) * 1e9f;
            s[n][e] = val;
            mx[e] = fmaxf(mx[e], val);
        }
    }
    float sum[4] = {0.f, 0.f, 0.f, 0.f};
#pragma unroll
    for (int n = 0; n < 16; n++)
#pragma unroll
        for (int e = 0; e < 4; e++) {
            s[n][e] = __expf(s[n][e] - mx[e]);
            sum[e] += s[n][e];
        }
    float inv[4] = {1.f/sum[0], 1.f/sum[1], 1.f/sum[2], 1.f/sum[3]};
#pragma unroll
    for (int n = 0; n < 16; n++) {
        __half2 p0 = __halves2half2(__float2half_rn(s[n][0] * inv[0]),
                                    __float2half_rn(s[n][1] * inv[1]));
        __half2 p1 = __halves2half2(__float2half_rn(s[n][2] * inv[2]),
                                    __float2half_rn(s[n][3] * inv[3]));
        size_t el = base + (size_t)n * PLANE + j;
        *(uint2*)(g_ATT + el) = make_uint2(*(const uint32_t*)&p0,
                                           *(const uint32_t*)&p1);
    }
}

// ---------------------------------------------------------------------------
// HMMA attn@V, fp16 2-term: A·Vh + A·Vl. Writes O1 hi/lo bf16 split.
// smem/buf: ATT 18432 + Vh/l 2x9216 = 36864; x2 bufs = 73728 B (2 CTA/SM)
// ---------------------------------------------------------------------------
#define VTB 9216
#define ABUF 36864

__device__ __forceinline__ void attnv_issue(
    uint32_t sb, int buf, int c, int tid, int i0, int b, int n, size_t zbase)
{
    const uint32_t base = sb + buf * ABUF;
#pragma unroll
    for (int p = 0; p < 4; p++) {
        int ch = tid + p * 256;          // 0..1023
        int r = ch >> 3, s = ch & 7;
        uint32_t d = base + (uint32_t)(r * SLD + s * 8) * 2;
        size_t g = zbase + (size_t)(i0 + r) * 2048 + c * 64 + s * 8;
        CP_ASYNC(d, g_ATT + g);
    }
#pragma unroll
    for (int p = 0; p < 2; p++) {
        int ch = tid + p * 256;          // 0..511
        int r = ch >> 3, s = ch & 7;
        uint32_t d = base + STB + (uint32_t)(r * SLD + s * 8) * 2;
        size_t g = ((size_t)(c * 64 + r) * 4 + b) * 1024 + n * 64 + s * 8;
        CP_ASYNC(d,       g_Vh + g);
        CP_ASYNC(d + VTB, g_Vl + g);
    }
}

__global__ void __launch_bounds__(256, 2) hm_attnv()
{
    extern __shared__ __nv_bfloat16 sm[];
    const int tid = threadIdx.x, w = tid >> 5, lane = tid & 31;
    const int z = blockIdx.y, b = z >> 4, n = z & 15;
    const int i0 = blockIdx.x * 128;
    const int wm = (w & 3) * 32, wn = (w >> 2) * 32;
    const size_t zbase = (size_t)z * PLANE;
    const uint32_t sb = smem_u32(sm);
    const int lr = lane & 7, li = lane >> 3;

    float acc[2][4][4];
#pragma unroll
    for (int a = 0; a < 2; a++)
#pragma unroll
        for (int c = 0; c < 4; c++)
#pragma unroll
            for (int k = 0; k < 4; k++) acc[a][c][k] = 0.f;

    attnv_issue(sb, 0, 0, tid, i0, b, n, zbase);
    CP_COMMIT();

    for (int c = 0; c < 32; c++) {
        if (c < 31) {
            attnv_issue(sb, (c + 1) & 1, c + 1, tid, i0, b, n, zbase);
            CP_COMMIT();
            CP_WAIT1();
        } else {
            CP_WAIT0();
        }
        __syncthreads();

        const uint32_t bb = sb + (c & 1) * ABUF;
#pragma unroll
        for (int ks = 0; ks < 4; ks++) {
            uint32_t ahf[2][4];
            const uint32_t acol = (uint32_t)(ks * 16 + (li >> 1) * 8) * 2;
            const uint32_t arow0 = (uint32_t)(wm + (li & 1) * 8 + lr);
#pragma unroll
            for (int mt = 0; mt < 2; mt++) {
                uint32_t ao = bb + (arow0 + mt * 16) * (SLD * 2) + acol;
                ldsm4(ahf[mt], ao);
            }
            uint32_t bhf[2][4], blf[2][4];
            const uint32_t vrow0 = (uint32_t)(ks * 16 + (li & 1) * 8 + lr);
#pragma unroll
            for (int nb = 0; nb < 2; nb++) {
                uint32_t vcol = (uint32_t)(wn + nb * 16 + (li >> 1) * 8) * 2;
                uint32_t bo = bb + STB + vrow0 * (SLD * 2) + vcol;
                ldsm4t(bhf[nb], bo);
                ldsm4t(blf[nb], bo + VTB);
            }
#pragma unroll
            for (int mt = 0; mt < 2; mt++)
#pragma unroll
                for (int nt = 0; nt < 4; nt++) {
                    const uint32_t* bh = &bhf[nt >> 1][(nt & 1) * 2];
                    const uint32_t* bl = &blf[nt >> 1][(nt & 1) * 2];
                    mma16816h(acc[mt][nt], ahf[mt], bh);
                    mma16816h(acc[mt][nt], ahf[mt], bl);
                }
        }
        __syncthreads();
    }

#pragma unroll
    for (int mt = 0; mt < 2; mt++) {
        int i = i0 + wm + mt * 16 + (lane >> 2);
#pragma unroll
        for (int half = 0; half < 2; half++) {
            size_t rbase = ((size_t)(i + half * 8) * 4 + b) * 1024 + n * 64;
#pragma unroll
            for (int nt = 0; nt < 4; nt++) {
                int col = wn + nt * 8 + (lane & 3) * 2;
                __nv_bfloat162 h, l;
                split2(acc[mt][nt][half*2+0], acc[mt][nt][half*2+1], h, l);
                size_t d = (rbase + col) >> 1;
                ((__nv_bfloat162*)g_O1h)[d] = h;
                ((__nv_bfloat162*)g_O1l)[d] = l;
            }
        }
    }
}

// ---------------------------------------------------------------------------
__global__ void write_mems(const float4* __restrict__ mems,
                           const float4* __restrict__ out,
                           float4* __restrict__ dst)
{
    int idx = blockIdx.x * blockDim.x + threadIdx.x;
    int row = idx >> 8, c = idx & 255;
    int b = row >> 11, pos = row & 2047;
    float4 v;
    if (pos < 1024) v = mems[idx];
    else            v = out[(((size_t)b * 1024) + (pos - 1024)) * 256 + c];
    dst[idx] = v;
}

// ---------------------------------------------------------------------------
extern "C" void kernel_launch(void* const* d_in, const int* in_sizes, int n_in,
                              void* d_out, int out_size)
{
    const float* TE    = (const float*)d_in[0];
    const float* REL   = (const float*)d_in[1];
    const float* MEMS  = (const float*)d_in[2];
    const float* AMASK = (const float*)d_in[3];
    const float* Wq = (const float*)d_in[4],  *bq = (const float*)d_in[5];
    const float* Wk = (const float*)d_in[6],  *bk = (const float*)d_in[7];
    const float* Wv = (const float*)d_in[8],  *bv = (const float*)d_in[9];
    const float* Wr = (const float*)d_in[10], *br = (const float*)d_in[11];
    const float* Wo = (const float*)d_in[12], *bo = (const float*)d_in[13];
    const float* u  = (const float*)d_in[14];
    const float* v  = (const float*)d_in[15];
    float* out = (float*)d_out;

    const int G_SMEM = 2 * 4 * GTB;   // 81920
    const int S_SMEM = 4 * STB;       // 73728
    const int A_SMEM = 2 * ABUF;      // 73728
    cudaFuncSetAttribute(hm_gemm,   cudaFuncAttributeMaxDynamicSharedMemorySize, G_SMEM);
    cudaFuncSetAttribute(hm_scores, cudaFuncAttributeMaxDynamicSharedMemorySize, S_SMEM);
    cudaFuncSetAttribute(hm_attnv,  cudaFuncAttributeMaxDynamicSharedMemorySize, A_SMEM);

    float *pAC, *pBD;
    cudaGetSymbolAddress((void**)&pAC, g_AC);
    cudaGetSymbolAddress((void**)&pBD, g_BD);

    __nv_bfloat16 *pRELh, *pRELl, *pWh, *pWl;
    __nv_bfloat16 *pKVh, *pKVl, *pQUh, *pQUl, *pQVh, *pQVl;
    __nv_bfloat16 *pKh, *pKl, *pRh, *pRl, *pO1h, *pO1l;
    __half *pVh, *pVl;
    cudaGetSymbolAddress((void**)&pRELh, g_RELh); cudaGetSymbolAddress((void**)&pRELl, g_RELl);
    cudaGetSymbolAddress((void**)&pWh,   g_Wh);   cudaGetSymbolAddress((void**)&pWl,   g_Wl);
    cudaGetSymbolAddress((void**)&pKVh,  g_KVh);  cudaGetSymbolAddress((void**)&pKVl,  g_KVl);
    cudaGetSymbolAddress((void**)&pQUh,  g_QUh);  cudaGetSymbolAddress((void**)&pQUl,  g_QUl);
    cudaGetSymbolAddress((void**)&pQVh,  g_QVh);  cudaGetSymbolAddress((void**)&pQVl,  g_QVl);
    cudaGetSymbolAddress((void**)&pKh,   g_Kh);   cudaGetSymbolAddress((void**)&pKl,   g_Kl);
    cudaGetSymbolAddress((void**)&pRh,   g_Rh);   cudaGetSymbolAddress((void**)&pRl,   g_Rl);
    cudaGetSymbolAddress((void**)&pVh,   g_Vh);   cudaGetSymbolAddress((void**)&pVl,   g_Vl);
    cudaGetSymbolAddress((void**)&pO1h,  g_O1h);  cudaGetSymbolAddress((void**)&pO1l,  g_O1l);

    const size_t WSZ = (size_t)1024 * 1024;

    // 1. input splits (TE split eliminated via remapA; see Q-proj)
    gather_split_kv<<<8192, 256>>>((const float4*)TE, (const float4*)MEMS);
    split_bf16<<<2048, 256>>>((const float4*)REL, (__nv_bfloat162*)pRELh, (__nv_bfloat162*)pRELl, 524288);
    split5_w<<<dim3(1024, 5), 256>>>((const float4*)Wq, (const float4*)Wk, (const float4*)Wv,
                                     (const float4*)Wr, (const float4*)Wo,
                                     (__nv_bfloat162*)pWh, (__nv_bfloat162*)pWl);

    // 2. projections
    hm_gemm<<<dim3(8, 32), 256, G_SMEM>>>(pKVh, pKVl, pWh + 0*WSZ, pWl + 0*WSZ, bq, nullptr,
        pQUh, pQUl, pQVh, pQVl, u, v, 2, 1);                       // Q (remapA)
    hm_gemm<<<dim3(8, 64), 256, G_SMEM>>>(pKVh, pKVl, pWh + 1*WSZ, pWl + 1*WSZ, bk, nullptr,
        pKh, pKl, nullptr, nullptr, nullptr, nullptr, 1, 0);       // K (bf16 split)
    hm_gemm<<<dim3(8, 64), 256, G_SMEM>>>(pKVh, pKVl, pWh + 2*WSZ, pWl + 2*WSZ, bv, nullptr,
        pVh, pVl, nullptr, nullptr, nullptr, nullptr, 3, 0);       // V (fp16 split)
    hm_gemm<<<dim3(8, 16), 256, G_SMEM>>>(pRELh, pRELl, pWh + 3*WSZ, pWl + 3*WSZ, br, nullptr,
        pRh, pRl, nullptr, nullptr, nullptr, nullptr, 1, 0);       // R

    // 3. score GEMMs (AC + BD in one launch)
    hm_scores<<<dim3(16, 8, 128), 256, S_SMEM>>>(pQUh, pQUl, pKh, pKl,
                                                 pQVh, pQVl, pRh, pRl, pAC, pBD);

    // 4. rel-shift + mask + softmax over heads -> ATT (fp16), 4 j/thread
    softmax_heads<<<dim3(4, 1024, 4), 128>>>(AMASK);

    // 5. attn @ V (fp16 2-term) -> O1 hi/lo
    hm_attnv<<<dim3(8, 64), 256, A_SMEM>>>();

    // 6. O projection -> d_out (fp32)
    hm_gemm<<<dim3(8, 32), 256, G_SMEM>>>(pO1h, pO1l, pWh + 4*WSZ, pWl + 4*WSZ, bo, out,
        nullptr, nullptr, nullptr, nullptr, nullptr, nullptr, 0, 0);

    // 7. mems_new
    if (out_size >= 12582912)
        write_mems<<<8192, 256>>>((const float4*)MEMS, (const float4*)out,
                                  (float4*)(out + 4194304));
}

// round 10
// speedup vs baseline: 1.2946x; 1.0524x over previous
#include <cuda_runtime.h>
#include <cuda_bf16.h>
#include <cuda_fp16.h>
#include <stdint.h>
#include <math.h>

// ---------------------------------------------------------------------------
// Problem constants: B=4, S=1024, H=1024, HEADS=16, HEAD_D=64, K=2048
// ---------------------------------------------------------------------------
#define PLANE 2097152ull   // 1024*2048

// ---------------- scratch ----------------
__device__ float         g_AC [(size_t)64 * PLANE];
__device__ float         g_BD [(size_t)64 * PLANE];
__device__ __half        g_ATT[(size_t)64 * PLANE];          // attn, single fp16

__device__ __nv_bfloat16 g_KVh [(size_t)8192*1024], g_KVl [(size_t)8192*1024];
__device__ __nv_bfloat16 g_RELh[(size_t)2048*1024], g_RELl[(size_t)2048*1024];
__device__ __nv_bfloat16 g_Wh  [(size_t)5*1024*1024], g_Wl [(size_t)5*1024*1024];
__device__ __nv_bfloat16 g_QUh [(size_t)4096*1024], g_QUl [(size_t)4096*1024];
__device__ __nv_bfloat16 g_QVh [(size_t)4096*1024], g_QVl [(size_t)4096*1024];
__device__ __nv_bfloat16 g_Kh  [(size_t)8192*1024], g_Kl  [(size_t)8192*1024];
__device__ __nv_bfloat16 g_Rh  [(size_t)2048*1024], g_Rl  [(size_t)2048*1024];
__device__ __half        g_Vh  [(size_t)8192*1024], g_Vl  [(size_t)8192*1024];  // fp16
__device__ __nv_bfloat16 g_O1h [(size_t)4096*1024], g_O1l [(size_t)4096*1024];

// ---------------------------------------------------------------------------
// Low-level helpers (sm_80-compatible: ldmatrix / mma.sync / cp.async)
// ---------------------------------------------------------------------------
__device__ __forceinline__ uint32_t smem_u32(const void* p) {
    uint32_t a;
    asm("{ .reg .u64 t; cvta.to.shared.u64 t, %1; cvt.u32.u64 %0, t; }"
        : "=r"(a) : "l"(p));
    return a;
}
__device__ __forceinline__ void ldsm4(uint32_t* r, uint32_t a) {
    asm volatile("ldmatrix.sync.aligned.m8n8.x4.shared.b16 {%0,%1,%2,%3}, [%4];"
        : "=r"(r[0]), "=r"(r[1]), "=r"(r[2]), "=r"(r[3]) : "r"(a));
}
__device__ __forceinline__ void ldsm4t(uint32_t* r, uint32_t a) {
    asm volatile("ldmatrix.sync.aligned.m8n8.x4.trans.shared.b16 {%0,%1,%2,%3}, [%4];"
        : "=r"(r[0]), "=r"(r[1]), "=r"(r[2]), "=r"(r[3]) : "r"(a));
}
__device__ __forceinline__ void mma16816(float* c, const uint32_t* a, const uint32_t* b) {
    asm volatile(
        "mma.sync.aligned.m16n8k16.row.col.f32.bf16.bf16.f32 "
        "{%0,%1,%2,%3}, {%4,%5,%6,%7}, {%8,%9}, {%0,%1,%2,%3};"
        : "+f"(c[0]), "+f"(c[1]), "+f"(c[2]), "+f"(c[3])
        : "r"(a[0]), "r"(a[1]), "r"(a[2]), "r"(a[3]), "r"(b[0]), "r"(b[1]));
}
__device__ __forceinline__ void mma16816h(float* c, const uint32_t* a, const uint32_t* b) {
    asm volatile(
        "mma.sync.aligned.m16n8k16.row.col.f32.f16.f16.f32 "
        "{%0,%1,%2,%3}, {%4,%5,%6,%7}, {%8,%9}, {%0,%1,%2,%3};"
        : "+f"(c[0]), "+f"(c[1]), "+f"(c[2]), "+f"(c[3])
        : "r"(a[0]), "r"(a[1]), "r"(a[2]), "r"(a[3]), "r"(b[0]), "r"(b[1]));
}
#define CP_ASYNC(dst, src) \
    asm volatile("cp.async.cg.shared.global [%0], [%1], 16;" :: "r"(dst), "l"(src))
#define CP_COMMIT() asm volatile("cp.async.commit_group;" ::: "memory")
#define CP_WAIT1()  asm volatile("cp.async.wait_group 1;" ::: "memory")
#define CP_WAIT0()  asm volatile("cp.async.wait_group 0;" ::: "memory")

__device__ __forceinline__ void split2(float x, float y,
                                       __nv_bfloat162& h, __nv_bfloat162& l) {
    __nv_bfloat16 hx = __float2bfloat16(x), hy = __float2bfloat16(y);
    h = __halves2bfloat162(hx, hy);
    l = __halves2bfloat162(__float2bfloat16(x - __bfloat162float(hx)),
                           __float2bfloat16(y - __bfloat162float(hy)));
}
__device__ __forceinline__ void split2h(float x, float y,
                                        __half2& h, __half2& l) {
    __half hx = __float2half_rn(x), hy = __float2half_rn(y);
    h = __halves2half2(hx, hy);
    l = __halves2half2(__float2half_rn(x - __half2float(hx)),
                       __float2half_rn(y - __half2float(hy)));
}

// ---------------------------------------------------------------------------
// split fp32 -> bf16 hi/lo (generic)
// ---------------------------------------------------------------------------
__global__ void split_bf16(const float4* __restrict__ in,
                           __nv_bfloat162* __restrict__ hi,
                           __nv_bfloat162* __restrict__ lo, int n4)
{
    int i = blockIdx.x * blockDim.x + threadIdx.x;
    if (i >= n4) return;
    float4 x = in[i];
    __nv_bfloat162 h0, l0, h1, l1;
    split2(x.x, x.y, h0, l0);
    split2(x.z, x.w, h1, l1);
    hi[i*2+0] = h0; hi[i*2+1] = h1;
    lo[i*2+0] = l0; lo[i*2+1] = l1;
}

// split 5 weight matrices in one launch
__global__ void split5_w(const float4* w0, const float4* w1, const float4* w2,
                         const float4* w3, const float4* w4,
                         __nv_bfloat162* __restrict__ hi,
                         __nv_bfloat162* __restrict__ lo)
{
    const float4* srcs[5] = {w0, w1, w2, w3, w4};
    int which = blockIdx.y;
    int i = blockIdx.x * blockDim.x + threadIdx.x;      // 0..262143
    float4 x = srcs[which][i];
    size_t d = (size_t)which * 524288 + (size_t)i * 2;
    __nv_bfloat162 h0, l0, h1, l1;
    split2(x.x, x.y, h0, l0);
    split2(x.z, x.w, h1, l1);
    hi[d] = h0; hi[d+1] = h1;
    lo[d] = l0; lo[d+1] = l1;
}

// gather kv_in (natural flat order row = b*2048+j) + split to bf16 hi/lo
__global__ void gather_split_kv(const float4* __restrict__ te,
                                const float4* __restrict__ mems)
{
    int idx = blockIdx.x * blockDim.x + threadIdx.x;    // 8192*256
    int row = idx >> 8, c = idx & 255;
    int b = row >> 11, j = row & 2047;
    float4 x;
    if (j < 1024) x = te  [((size_t)b * 1024 + j) * 256 + c];
    else          x = mems[((size_t)b * 2048 + (j - 1024)) * 256 + c];
    __nv_bfloat162 h0, l0, h1, l1;
    split2(x.x, x.y, h0, l0);
    split2(x.z, x.w, h1, l1);
    ((__nv_bfloat162*)g_KVh)[idx*2]   = h0;
    ((__nv_bfloat162*)g_KVh)[idx*2+1] = h1;
    ((__nv_bfloat162*)g_KVl)[idx*2]   = l0;
    ((__nv_bfloat162*)g_KVl)[idx*2+1] = l1;
}

// ---------------------------------------------------------------------------
// HMMA GEMM core (shared by fused-projection and O-proj kernels).
// 128x128 CTA tile, BK=32, 8 warps (64x32), cp.async double-buffer.
// Epilogue modes: 0 = fp32+bias -> C; 1 = bias+split(bf16) -> o1;
//                 2 = dual split (bias+u -> o1, bias+v -> o2);
//                 3 = bias+split(fp16) -> o1.
// ---------------------------------------------------------------------------
#define GLD 40
#define GTB 10240

__device__ __forceinline__ void gemm_issue(
    uint32_t sb, int buf, int c, int tid,
    const __nv_bfloat16* Ah, const __nv_bfloat16* Al,
    const __nv_bfloat16* Wh, const __nv_bfloat16* Wl, int m0, int n0, int remapA)
{
    const int k0 = c * 32;
    const uint32_t base = sb + buf * 4 * GTB;
#pragma unroll
    for (int p = 0; p < 2; p++) {
        int ch = tid + p * 256;
        int r = ch >> 2, s = ch & 3;
        uint32_t d = base + (uint32_t)(r * GLD + s * 8) * 2;
        int arow = m0 + r;
        if (remapA) arow += (arow >> 10) << 10;
        size_t ga = (size_t)arow * 1024 + k0 + s * 8;
        size_t gw = (size_t)(n0 + r) * 1024 + k0 + s * 8;
        CP_ASYNC(d,         Ah + ga);
        CP_ASYNC(d + GTB,   Al + ga);
        CP_ASYNC(d + 2*GTB, Wh + gw);
        CP_ASYNC(d + 3*GTB, Wl + gw);
    }
}

__device__ __forceinline__ void gemm_body(
    const __nv_bfloat16* Ah, const __nv_bfloat16* Al,
    const __nv_bfloat16* Wh, const __nv_bfloat16* Wl,
    const float* bias, float* C,
    void* o1h, void* o1l, void* o2h, void* o2l,
    const float* addu, const float* addv,
    int mode, int remapA, int m0, int n0, __nv_bfloat16* sm)
{
    const int tid = threadIdx.x, w = tid >> 5, lane = tid & 31;
    const int wm = (w & 1) * 64, wn = (w >> 1) * 32;
    const uint32_t sb = smem_u32(sm);
    const int lr = lane & 7, li = lane >> 3;

    float acc[4][4][4];
#pragma unroll
    for (int a = 0; a < 4; a++)
#pragma unroll
        for (int b = 0; b < 4; b++)
#pragma unroll
            for (int k = 0; k < 4; k++) acc[a][b][k] = 0.f;

    gemm_issue(sb, 0, 0, tid, Ah, Al, Wh, Wl, m0, n0, remapA);
    CP_COMMIT();

    for (int c = 0; c < 32; c++) {
        if (c < 31) {
            gemm_issue(sb, (c + 1) & 1, c + 1, tid, Ah, Al, Wh, Wl, m0, n0, remapA);
            CP_COMMIT();
            CP_WAIT1();
        } else {
            CP_WAIT0();
        }
        __syncthreads();

        const uint32_t bb = sb + (c & 1) * 4 * GTB;
#pragma unroll
        for (int ks = 0; ks < 2; ks++) {
            uint32_t ahf[4][4], alf[4][4];
            const uint32_t acol = (uint32_t)(ks * 16 + (li >> 1) * 8) * 2;
            const uint32_t arow0 = (uint32_t)(wm + (li & 1) * 8 + lr);
#pragma unroll
            for (int mt = 0; mt < 4; mt++) {
                uint32_t ao = bb + (arow0 + mt * 16) * (GLD * 2) + acol;
                ldsm4(ahf[mt], ao);
                ldsm4(alf[mt], ao + GTB);
            }
            uint32_t bhf[2][4], blf[2][4];
            const uint32_t bcol = (uint32_t)(ks * 16 + (li & 1) * 8) * 2;
            const uint32_t brow0 = (uint32_t)(wn + (li >> 1) * 8 + lr);
#pragma unroll
            for (int nb = 0; nb < 2; nb++) {
                uint32_t bo = bb + 2*GTB + (brow0 + nb * 16) * (GLD * 2) + bcol;
                ldsm4(bhf[nb], bo);
                ldsm4(blf[nb], bo + GTB);
            }
#pragma unroll
            for (int mt = 0; mt < 4; mt++)
#pragma unroll
                for (int nt = 0; nt < 4; nt++) {
                    const uint32_t* bh = &bhf[nt >> 1][(nt & 1) * 2];
                    const uint32_t* bl = &blf[nt >> 1][(nt & 1) * 2];
                    mma16816(acc[mt][nt], ahf[mt], bh);
                    mma16816(acc[mt][nt], ahf[mt], bl);
                    mma16816(acc[mt][nt], alf[mt], bh);
                }
        }
        __syncthreads();
    }

#pragma unroll
    for (int mt = 0; mt < 4; mt++) {
        int m = m0 + wm + mt * 16 + (lane >> 2);
#pragma unroll
        for (int half = 0; half < 2; half++) {
            size_t mrow = (size_t)(m + half * 8);
#pragma unroll
            for (int nt = 0; nt < 4; nt++) {
                int col = wn + nt * 8 + (lane & 3) * 2;
                int cg = n0 + col;
                float x = acc[mt][nt][half*2+0] + bias[cg];
                float y = acc[mt][nt][half*2+1] + bias[cg+1];
                size_t d = (mrow * 1024 + cg) >> 1;
                if (mode == 0) {
                    *(float2*)(C + mrow * 1024 + cg) = make_float2(x, y);
                } else if (mode == 1) {
                    __nv_bfloat162 h, l;
                    split2(x, y, h, l);
                    ((__nv_bfloat162*)o1h)[d] = h; ((__nv_bfloat162*)o1l)[d] = l;
                } else if (mode == 2) {
                    __nv_bfloat162 h, l;
                    split2(x + addu[cg], y + addu[cg+1], h, l);
                    ((__nv_bfloat162*)o1h)[d] = h; ((__nv_bfloat162*)o1l)[d] = l;
                    split2(x + addv[cg], y + addv[cg+1], h, l);
                    ((__nv_bfloat162*)o2h)[d] = h; ((__nv_bfloat162*)o2l)[d] = l;
                } else {
                    __half2 h, l;
                    split2h(x, y, h, l);
                    ((__half2*)o1h)[d] = h; ((__half2*)o1l)[d] = l;
                }
            }
        }
    }
}

// Fused Q/K/V/R projection launch: flat blockIdx.x in [0, 1408)
//   [0,512)=K-proj, [512,1024)=V-proj, [1024,1280)=Q-proj, [1280,1408)=R-proj
__global__ void __launch_bounds__(256, 2) hm_proj_fused(
    const float* __restrict__ bq, const float* __restrict__ bk,
    const float* __restrict__ bv, const float* __restrict__ br,
    const float* __restrict__ u,  const float* __restrict__ v)
{
    extern __shared__ __nv_bfloat16 sm[];
    const size_t WSZ = (size_t)1024 * 1024;
    const int bid = blockIdx.x;

    if (bid < 512) {                        // K projection: M=8192
        int l = bid;
        gemm_body(g_KVh, g_KVl, g_Wh + 1*WSZ, g_Wl + 1*WSZ, bk, nullptr,
                  g_Kh, g_Kl, nullptr, nullptr, nullptr, nullptr,
                  1, 0, (l >> 3) * 128, (l & 7) * 128, sm);
    } else if (bid < 1024) {                // V projection: M=8192, fp16 split
        int l = bid - 512;
        gemm_body(g_KVh, g_KVl, g_Wh + 2*WSZ, g_Wl + 2*WSZ, bv, nullptr,
                  g_Vh, g_Vl, nullptr, nullptr, nullptr, nullptr,
                  3, 0, (l >> 3) * 128, (l & 7) * 128, sm);
    } else if (bid < 1280) {                // Q projection: M=4096, dual split, remap
        int l = bid - 1024;
        gemm_body(g_KVh, g_KVl, g_Wh + 0*WSZ, g_Wl + 0*WSZ, bq, nullptr,
                  g_QUh, g_QUl, g_QVh, g_QVl, u, v,
                  2, 1, (l >> 3) * 128, (l & 7) * 128, sm);
    } else {                                // R projection: M=2048
        int l = bid - 1280;
        gemm_body(g_RELh, g_RELl, g_Wh + 3*WSZ, g_Wl + 3*WSZ, br, nullptr,
                  g_Rh, g_Rl, nullptr, nullptr, nullptr, nullptr,
                  1, 0, (l >> 3) * 128, (l & 7) * 128, sm);
    }
}

// O projection (separate: depends on attnv output)
__global__ void __launch_bounds__(256, 2) hm_gemm_o(
    const float* __restrict__ bo, float* __restrict__ C)
{
    extern __shared__ __nv_bfloat16 sm[];
    const size_t WSZ = (size_t)1024 * 1024;
    gemm_body(g_O1h, g_O1l, g_Wh + 4*WSZ, g_Wl + 4*WSZ, bo, C,
              nullptr, nullptr, nullptr, nullptr, nullptr, nullptr,
              0, 0, blockIdx.y * 128, blockIdx.x * 128, sm);
}

// ---------------------------------------------------------------------------
// HMMA batched scores, one launch. blockIdx.z in [0,128): mode = z>=64.
//   mode0 (AC): C[i,j] = (q+u)[i,b,n,:]·k[j,b,n,:]
//   mode1 (BD): C[i,l] = (q+v)[i,b,n,:]·kr[l,n,:]
// K=64 single shot. smem: 4 tiles x 128x72x2 = 73728 B (2 CTA/SM)
// ---------------------------------------------------------------------------
#define SLD 72
#define STB 18432

__global__ void __launch_bounds__(256, 2) hm_scores(
    const __nv_bfloat16* __restrict__ QUh, const __nv_bfloat16* __restrict__ QUl,
    const __nv_bfloat16* __restrict__ Kh,  const __nv_bfloat16* __restrict__ Kl,
    const __nv_bfloat16* __restrict__ QVh, const __nv_bfloat16* __restrict__ QVl,
    const __nv_bfloat16* __restrict__ Rh,  const __nv_bfloat16* __restrict__ Rl,
    float* __restrict__ AC, float* __restrict__ BD)
{
    extern __shared__ __nv_bfloat16 sm[];
    const int tid = threadIdx.x, w = tid >> 5, lane = tid & 31;
    const int zz = blockIdx.z;
    const int mode = zz >= 64;
    const int z = zz & 63, b = z >> 4, n = z & 15;
    const int j0 = blockIdx.x * 128, i0 = blockIdx.y * 128;
    const int wm = (w & 1) * 64, wn = (w >> 1) * 32;
    const uint32_t sb = smem_u32(sm);
    const int lr = lane & 7, li = lane >> 3;

    const __nv_bfloat16* Ah = mode ? QVh : QUh;
    const __nv_bfloat16* Al = mode ? QVl : QUl;
    const __nv_bfloat16* Bh = mode ? Rh  : Kh;
    const __nv_bfloat16* Bl = mode ? Rl  : Kl;
    float* Out = mode ? BD : AC;

#pragma unroll
    for (int p = 0; p < 4; p++) {
        int ch = tid + p * 256;          // 0..1023
        int r = ch >> 3, s = ch & 7;
        uint32_t d = sb + (uint32_t)(r * SLD + s * 8) * 2;
        size_t ga = ((size_t)(i0 + r) * 4 + b) * 1024 + n * 64 + s * 8;
        size_t gb = mode ? ((size_t)(j0 + r) * 1024 + n * 64 + s * 8)
                         : (((size_t)(j0 + r) * 4 + b) * 1024 + n * 64 + s * 8);
        CP_ASYNC(d,           Ah + ga);
        CP_ASYNC(d + STB,     Al + ga);
        CP_ASYNC(d + 2*STB,   Bh + gb);
        CP_ASYNC(d + 3*STB,   Bl + gb);
    }
    CP_COMMIT();
    CP_WAIT0();
    __syncthreads();

    float acc[4][4][4];
#pragma unroll
    for (int a = 0; a < 4; a++)
#pragma unroll
        for (int c = 0; c < 4; c++)
#pragma unroll
            for (int k = 0; k < 4; k++) acc[a][c][k] = 0.f;

#pragma unroll
    for (int ks = 0; ks < 4; ks++) {
        uint32_t ahf[4][4], alf[4][4];
        const uint32_t acol = (uint32_t)(ks * 16 + (li >> 1) * 8) * 2;
        const uint32_t arow0 = (uint32_t)(wm + (li & 1) * 8 + lr);
#pragma unroll
        for (int mt = 0; mt < 4; mt++) {
            uint32_t ao = sb + (arow0 + mt * 16) * (SLD * 2) + acol;
            ldsm4(ahf[mt], ao);
            ldsm4(alf[mt], ao + STB);
        }
        uint32_t bhf[2][4], blf[2][4];
        const uint32_t bcol = (uint32_t)(ks * 16 + (li & 1) * 8) * 2;
        const uint32_t brow0 = (uint32_t)(wn + (li >> 1) * 8 + lr);
#pragma unroll
        for (int nb = 0; nb < 2; nb++) {
            uint32_t bo = sb + 2*STB + (brow0 + nb * 16) * (SLD * 2) + bcol;
            ldsm4(bhf[nb], bo);
            ldsm4(blf[nb], bo + STB);
        }
#pragma unroll
        for (int mt = 0; mt < 4; mt++)
#pragma unroll
            for (int nt = 0; nt < 4; nt++) {
                const uint32_t* bh = &bhf[nt >> 1][(nt & 1) * 2];
                const uint32_t* bl = &blf[nt >> 1][(nt & 1) * 2];
                mma16816(acc[mt][nt], ahf[mt], bh);
                mma16816(acc[mt][nt], ahf[mt], bl);
                mma16816(acc[mt][nt], alf[mt], bh);
            }
    }

    const size_t obase = (size_t)z * PLANE;
#pragma unroll
    for (int mt = 0; mt < 4; mt++) {
        int row = i0 + wm + mt * 16 + (lane >> 2);
        float* r0 = Out + obase + (size_t)row * 2048 + j0 + wn;
        float* r8 = r0 + (size_t)8 * 2048;
#pragma unroll
        for (int nt = 0; nt < 4; nt++) {
            int col = nt * 8 + (lane & 3) * 2;
            *(float2*)(r0 + col) = make_float2(acc[mt][nt][0], acc[mt][nt][1]);
            *(float2*)(r8 + col) = make_float2(acc[mt][nt][2], acc[mt][nt][3]);
        }
    }
}

// ---------------------------------------------------------------------------
// Softmax over the 16-head axis, 4 j per thread (float4):
//   AC + shifted BD + mask -> ATT (single fp16)
// ---------------------------------------------------------------------------
__global__ void softmax_heads(const float* __restrict__ amask)
{
    const int j4 = blockIdx.x * 128 + threadIdx.x;   // 0..511 (float4 col index)
    const int j  = j4 * 4;
    const int i  = blockIdx.y;
    const int b  = blockIdx.z;
    const int ioff = 1023 - i;                        // l = j + ioff
    const int bprime = i >> 8;
    const float* amrow = amask + (size_t)bprime * 1024;

    const size_t base = ((size_t)b * 16 * 1024 + i) * 2048;
    const float4* AC4 = (const float4*)(g_AC + base);

    float s[16][4];
    float mx[4] = {-1e30f, -1e30f, -1e30f, -1e30f};
#pragma unroll
    for (int n = 0; n < 16; n++) {
        float4 ac = AC4[(size_t)n * 524288 + j4];
        float a[4] = {ac.x, ac.y, ac.z, ac.w};
        const float* BDn = g_BD + base + (size_t)n * PLANE;
#pragma unroll
        for (int e = 0; e < 4; e++) {
            int l = j + e + ioff;
            float bd = (l < 2048) ? BDn[l] : 0.f;
            float val = (a[e] + bd) * 0.125f;
            int jp = ((j + e) * 64 + b * 16 + n) & 2047;
            float m = (jp < 1024) ? 1.f : amrow[jp - 1024];
            val -= (1.f - m) * 1e9f;
            s[n][e] = val;
            mx[e] = fmaxf(mx[e], val);
        }
    }
    float sum[4] = {0.f, 0.f, 0.f, 0.f};
#pragma unroll
    for (int n = 0; n < 16; n++)
#pragma unroll
        for (int e = 0; e < 4; e++) {
            s[n][e] = __expf(s[n][e] - mx[e]);
            sum[e] += s[n][e];
        }
    float inv[4] = {1.f/sum[0], 1.f/sum[1], 1.f/sum[2], 1.f/sum[3]};
#pragma unroll
    for (int n = 0; n < 16; n++) {
        __half2 p0 = __halves2half2(__float2half_rn(s[n][0] * inv[0]),
                                    __float2half_rn(s[n][1] * inv[1]));
        __half2 p1 = __halves2half2(__float2half_rn(s[n][2] * inv[2]),
                                    __float2half_rn(s[n][3] * inv[3]));
        size_t el = base + (size_t)n * PLANE + j;
        *(uint2*)(g_ATT + el) = make_uint2(*(const uint32_t*)&p0,
                                           *(const uint32_t*)&p1);
    }
}

// ---------------------------------------------------------------------------
// HMMA attn@V, fp16 2-term: A·Vh + A·Vl. Writes O1 hi/lo bf16 split.
// smem/buf: ATT 18432 + Vh/l 2x9216 = 36864; x2 bufs = 73728 B (2 CTA/SM)
// ---------------------------------------------------------------------------
#define VTB 9216
#define ABUF 36864

__device__ __forceinline__ void attnv_issue(
    uint32_t sb, int buf, int c, int tid, int i0, int b, int n, size_t zbase)
{
    const uint32_t base = sb + buf * ABUF;
#pragma unroll
    for (int p = 0; p < 4; p++) {
        int ch = tid + p * 256;          // 0..1023
        int r = ch >> 3, s = ch & 7;
        uint32_t d = base + (uint32_t)(r * SLD + s * 8) * 2;
        size_t g = zbase + (size_t)(i0 + r) * 2048 + c * 64 + s * 8;
        CP_ASYNC(d, g_ATT + g);
    }
#pragma unroll
    for (int p = 0; p < 2; p++) {
        int ch = tid + p * 256;          // 0..511
        int r = ch >> 3, s = ch & 7;
        uint32_t d = base + STB + (uint32_t)(r * SLD + s * 8) * 2;
        size_t g = ((size_t)(c * 64 + r) * 4 + b) * 1024 + n * 64 + s * 8;
        CP_ASYNC(d,       g_Vh + g);
        CP_ASYNC(d + VTB, g_Vl + g);
    }
}

__global__ void __launch_bounds__(256, 2) hm_attnv()
{
    extern __shared__ __nv_bfloat16 sm[];
    const int tid = threadIdx.x, w = tid >> 5, lane = tid & 31;
    const int z = blockIdx.y, b = z >> 4, n = z & 15;
    const int i0 = blockIdx.x * 128;
    const int wm = (w & 3) * 32, wn = (w >> 2) * 32;
    const size_t zbase = (size_t)z * PLANE;
    const uint32_t sb = smem_u32(sm);
    const int lr = lane & 7, li = lane >> 3;

    float acc[2][4][4];
#pragma unroll
    for (int a = 0; a < 2; a++)
#pragma unroll
        for (int c = 0; c < 4; c++)
#pragma unroll
            for (int k = 0; k < 4; k++) acc[a][c][k] = 0.f;

    attnv_issue(sb, 0, 0, tid, i0, b, n, zbase);
    CP_COMMIT();

    for (int c = 0; c < 32; c++) {
        if (c < 31) {
            attnv_issue(sb, (c + 1) & 1, c + 1, tid, i0, b, n, zbase);
            CP_COMMIT();
            CP_WAIT1();
        } else {
            CP_WAIT0();
        }
        __syncthreads();

        const uint32_t bb = sb + (c & 1) * ABUF;
#pragma unroll
        for (int ks = 0; ks < 4; ks++) {
            uint32_t ahf[2][4];
            const uint32_t acol = (uint32_t)(ks * 16 + (li >> 1) * 8) * 2;
            const uint32_t arow0 = (uint32_t)(wm + (li & 1) * 8 + lr);
#pragma unroll
            for (int mt = 0; mt < 2; mt++) {
                uint32_t ao = bb + (arow0 + mt * 16) * (SLD * 2) + acol;
                ldsm4(ahf[mt], ao);
            }
            uint32_t bhf[2][4], blf[2][4];
            const uint32_t vrow0 = (uint32_t)(ks * 16 + (li & 1) * 8 + lr);
#pragma unroll
            for (int nb = 0; nb < 2; nb++) {
                uint32_t vcol = (uint32_t)(wn + nb * 16 + (li >> 1) * 8) * 2;
                uint32_t bo = bb + STB + vrow0 * (SLD * 2) + vcol;
                ldsm4t(bhf[nb], bo);
                ldsm4t(blf[nb], bo + VTB);
            }
#pragma unroll
            for (int mt = 0; mt < 2; mt++)
#pragma unroll
                for (int nt = 0; nt < 4; nt++) {
                    const uint32_t* bh = &bhf[nt >> 1][(nt & 1) * 2];
                    const uint32_t* bl = &blf[nt >> 1][(nt & 1) * 2];
                    mma16816h(acc[mt][nt], ahf[mt], bh);
                    mma16816h(acc[mt][nt], ahf[mt], bl);
                }
        }
        __syncthreads();
    }

#pragma unroll
    for (int mt = 0; mt < 2; mt++) {
        int i = i0 + wm + mt * 16 + (lane >> 2);
#pragma unroll
        for (int half = 0; half < 2; half++) {
            size_t rbase = ((size_t)(i + half * 8) * 4 + b) * 1024 + n * 64;
#pragma unroll
            for (int nt = 0; nt < 4; nt++) {
                int col = wn + nt * 8 + (lane & 3) * 2;
                __nv_bfloat162 h, l;
                split2(acc[mt][nt][half*2+0], acc[mt][nt][half*2+1], h, l);
                size_t d = (rbase + col) >> 1;
                ((__nv_bfloat162*)g_O1h)[d] = h;
                ((__nv_bfloat162*)g_O1l)[d] = l;
            }
        }
    }
}

// ---------------------------------------------------------------------------
__global__ void write_mems(const float4* __restrict__ mems,
                           const float4* __restrict__ out,
                           float4* __restrict__ dst)
{
    int idx = blockIdx.x * blockDim.x + threadIdx.x;
    int row = idx >> 8, c = idx & 255;
    int b = row >> 11, pos = row & 2047;
    float4 v;
    if (pos < 1024) v = mems[idx];
    else            v = out[(((size_t)b * 1024) + (pos - 1024)) * 256 + c];
    dst[idx] = v;
}

// ---------------------------------------------------------------------------
extern "C" void kernel_launch(void* const* d_in, const int* in_sizes, int n_in,
                              void* d_out, int out_size)
{
    const float* TE    = (const float*)d_in[0];
    const float* REL   = (const float*)d_in[1];
    const float* MEMS  = (const float*)d_in[2];
    const float* AMASK = (const float*)d_in[3];
    const float* Wq = (const float*)d_in[4],  *bq = (const float*)d_in[5];
    const float* Wk = (const float*)d_in[6],  *bk = (const float*)d_in[7];
    const float* Wv = (const float*)d_in[8],  *bv = (const float*)d_in[9];
    const float* Wr = (const float*)d_in[10], *br = (const float*)d_in[11];
    const float* Wo = (const float*)d_in[12], *bo = (const float*)d_in[13];
    const float* u  = (const float*)d_in[14];
    const float* v  = (const float*)d_in[15];
    float* out = (float*)d_out;

    const int G_SMEM = 2 * 4 * GTB;   // 81920
    const int S_SMEM = 4 * STB;       // 73728
    const int A_SMEM = 2 * ABUF;      // 73728
    cudaFuncSetAttribute(hm_proj_fused, cudaFuncAttributeMaxDynamicSharedMemorySize, G_SMEM);
    cudaFuncSetAttribute(hm_gemm_o,     cudaFuncAttributeMaxDynamicSharedMemorySize, G_SMEM);
    cudaFuncSetAttribute(hm_scores,     cudaFuncAttributeMaxDynamicSharedMemorySize, S_SMEM);
    cudaFuncSetAttribute(hm_attnv,      cudaFuncAttributeMaxDynamicSharedMemorySize, A_SMEM);

    float *pAC, *pBD;
    cudaGetSymbolAddress((void**)&pAC, g_AC);
    cudaGetSymbolAddress((void**)&pBD, g_BD);

    __nv_bfloat16 *pRELh, *pRELl, *pWh, *pWl;
    __nv_bfloat16 *pQUh, *pQUl, *pQVh, *pQVl, *pKh, *pKl, *pRh, *pRl;
    cudaGetSymbolAddress((void**)&pRELh, g_RELh); cudaGetSymbolAddress((void**)&pRELl, g_RELl);
    cudaGetSymbolAddress((void**)&pWh,   g_Wh);   cudaGetSymbolAddress((void**)&pWl,   g_Wl);
    cudaGetSymbolAddress((void**)&pQUh,  g_QUh);  cudaGetSymbolAddress((void**)&pQUl,  g_QUl);
    cudaGetSymbolAddress((void**)&pQVh,  g_QVh);  cudaGetSymbolAddress((void**)&pQVl,  g_QVl);
    cudaGetSymbolAddress((void**)&pKh,   g_Kh);   cudaGetSymbolAddress((void**)&pKl,   g_Kl);
    cudaGetSymbolAddress((void**)&pRh,   g_Rh);   cudaGetSymbolAddress((void**)&pRl,   g_Rl);

    // 1. input splits (TE split eliminated via remapA in Q-proj)
    gather_split_kv<<<8192, 256>>>((const float4*)TE, (const float4*)MEMS);
    split_bf16<<<2048, 256>>>((const float4*)REL, (__nv_bfloat162*)pRELh, (__nv_bfloat162*)pRELl, 524288);
    split5_w<<<dim3(1024, 5), 256>>>((const float4*)Wq, (const float4*)Wk, (const float4*)Wv,
                                     (const float4*)Wr, (const float4*)Wo,
                                     (__nv_bfloat162*)pWh, (__nv_bfloat162*)pWl);

    // 2. all four projections in ONE launch (wave-packed)
    hm_proj_fused<<<1408, 256, G_SMEM>>>(bq, bk, bv, br, u, v);

    // 3. score GEMMs (AC + BD in one launch)
    hm_scores<<<dim3(16, 8, 128), 256, S_SMEM>>>(pQUh, pQUl, pKh, pKl,
                                                 pQVh, pQVl, pRh, pRl, pAC, pBD);

    // 4. rel-shift + mask + softmax over heads -> ATT (fp16), 4 j/thread
    softmax_heads<<<dim3(4, 1024, 4), 128>>>(AMASK);

    // 5. attn @ V (fp16 2-term) -> O1 hi/lo
    hm_attnv<<<dim3(8, 64), 256, A_SMEM>>>();

    // 6. O projection -> d_out (fp32)
    hm_gemm_o<<<dim3(8, 32), 256, G_SMEM>>>(bo, out);

    // 7. mems_new
    if (out_size >= 12582912)
        write_mems<<<8192, 256>>>((const float4*)MEMS, (const float4*)out,
                                  (float4*)(out + 4194304));
}

// round 12
// speedup vs baseline: 1.3813x; 1.0669x over previous
#include <cuda_runtime.h>
#include <cuda_bf16.h>
#include <cuda_fp16.h>
#include <stdint.h>
#include <math.h>

// ---------------------------------------------------------------------------
// Problem constants: B=4, S=1024, H=1024, HEADS=16, HEAD_D=64, K=2048
// ---------------------------------------------------------------------------
#define PLANE 2097152ull   // 1024*2048

// ---------------- scratch ----------------
__device__ float         g_AC [(size_t)64 * PLANE];
__device__ float         g_BD [(size_t)64 * PLANE];
__device__ __half        g_ATT[(size_t)64 * PLANE];          // attn, single fp16

__device__ __nv_bfloat16 g_KVh [(size_t)8192*1024], g_KVl [(size_t)8192*1024];
__device__ __nv_bfloat16 g_RELh[(size_t)2048*1024], g_RELl[(size_t)2048*1024];
__device__ __nv_bfloat16 g_Wh  [(size_t)5*1024*1024], g_Wl [(size_t)5*1024*1024];
__device__ __nv_bfloat16 g_QUh [(size_t)4096*1024], g_QUl [(size_t)4096*1024];
__device__ __nv_bfloat16 g_QVh [(size_t)4096*1024], g_QVl [(size_t)4096*1024];
__device__ __nv_bfloat16 g_Kh  [(size_t)8192*1024], g_Kl  [(size_t)8192*1024];
__device__ __nv_bfloat16 g_Rh  [(size_t)2048*1024], g_Rl  [(size_t)2048*1024];
__device__ __half        g_Vh  [(size_t)8192*1024], g_Vl  [(size_t)8192*1024];  // fp16
__device__ __nv_bfloat16 g_O1h [(size_t)4096*1024], g_O1l [(size_t)4096*1024];

// ---------------------------------------------------------------------------
// Low-level helpers (sm_80-compatible: ldmatrix / mma.sync / cp.async)
// ---------------------------------------------------------------------------
__device__ __forceinline__ uint32_t smem_u32(const void* p) {
    uint32_t a;
    asm("{ .reg .u64 t; cvta.to.shared.u64 t, %1; cvt.u32.u64 %0, t; }"
        : "=r"(a) : "l"(p));
    return a;
}
__device__ __forceinline__ void ldsm4(uint32_t* r, uint32_t a) {
    asm volatile("ldmatrix.sync.aligned.m8n8.x4.shared.b16 {%0,%1,%2,%3}, [%4];"
        : "=r"(r[0]), "=r"(r[1]), "=r"(r[2]), "=r"(r[3]) : "r"(a));
}
__device__ __forceinline__ void ldsm4t(uint32_t* r, uint32_t a) {
    asm volatile("ldmatrix.sync.aligned.m8n8.x4.trans.shared.b16 {%0,%1,%2,%3}, [%4];"
        : "=r"(r[0]), "=r"(r[1]), "=r"(r[2]), "=r"(r[3]) : "r"(a));
}
__device__ __forceinline__ void mma16816(float* c, const uint32_t* a, const uint32_t* b) {
    asm volatile(
        "mma.sync.aligned.m16n8k16.row.col.f32.bf16.bf16.f32 "
        "{%0,%1,%2,%3}, {%4,%5,%6,%7}, {%8,%9}, {%0,%1,%2,%3};"
        : "+f"(c[0]), "+f"(c[1]), "+f"(c[2]), "+f"(c[3])
        : "r"(a[0]), "r"(a[1]), "r"(a[2]), "r"(a[3]), "r"(b[0]), "r"(b[1]));
}
__device__ __forceinline__ void mma16816h(float* c, const uint32_t* a, const uint32_t* b) {
    asm volatile(
        "mma.sync.aligned.m16n8k16.row.col.f32.f16.f16.f32 "
        "{%0,%1,%2,%3}, {%4,%5,%6,%7}, {%8,%9}, {%0,%1,%2,%3};"
        : "+f"(c[0]), "+f"(c[1]), "+f"(c[2]), "+f"(c[3])
        : "r"(a[0]), "r"(a[1]), "r"(a[2]), "r"(a[3]), "r"(b[0]), "r"(b[1]));
}
#define CP_ASYNC(dst, src) \
    asm volatile("cp.async.cg.shared.global [%0], [%1], 16;" :: "r"(dst), "l"(src))
#define CP_COMMIT() asm volatile("cp.async.commit_group;" ::: "memory")
#define CP_WAIT2()  asm volatile("cp.async.wait_group 2;" ::: "memory")
#define CP_WAIT1()  asm volatile("cp.async.wait_group 1;" ::: "memory")
#define CP_WAIT0()  asm volatile("cp.async.wait_group 0;" ::: "memory")

// GEMM tile swizzle: 64B rows (4 x 16B chunks), chunk permuted by row.
// For any 8-aligned row base, the 8 ldmatrix lane addresses hit 8 distinct
// 16B bank groups; every address is 16B aligned.
#define GSWZ(r) ((((r) ^ ((r) >> 2))) & 3)

__device__ __forceinline__ void split2(float x, float y,
                                       __nv_bfloat162& h, __nv_bfloat162& l) {
    __nv_bfloat16 hx = __float2bfloat16(x), hy = __float2bfloat16(y);
    h = __halves2bfloat162(hx, hy);
    l = __halves2bfloat162(__float2bfloat16(x - __bfloat162float(hx)),
                           __float2bfloat16(y - __bfloat162float(hy)));
}
__device__ __forceinline__ void split2h(float x, float y,
                                        __half2& h, __half2& l) {
    __half hx = __float2half_rn(x), hy = __float2half_rn(y);
    h = __halves2half2(hx, hy);
    l = __halves2half2(__float2half_rn(x - __half2float(hx)),
                       __float2half_rn(y - __half2float(hy)));
}

// ---------------------------------------------------------------------------
// split fp32 -> bf16 hi/lo (generic)
// ---------------------------------------------------------------------------
__global__ void split_bf16(const float4* __restrict__ in,
                           __nv_bfloat162* __restrict__ hi,
                           __nv_bfloat162* __restrict__ lo, int n4)
{
    int i = blockIdx.x * blockDim.x + threadIdx.x;
    if (i >= n4) return;
    float4 x = in[i];
    __nv_bfloat162 h0, l0, h1, l1;
    split2(x.x, x.y, h0, l0);
    split2(x.z, x.w, h1, l1);
    hi[i*2+0] = h0; hi[i*2+1] = h1;
    lo[i*2+0] = l0; lo[i*2+1] = l1;
}

// split 5 weight matrices in one launch
__global__ void split5_w(const float4* w0, const float4* w1, const float4* w2,
                         const float4* w3, const float4* w4,
                         __nv_bfloat162* __restrict__ hi,
                         __nv_bfloat162* __restrict__ lo)
{
    const float4* srcs[5] = {w0, w1, w2, w3, w4};
    int which = blockIdx.y;
    int i = blockIdx.x * blockDim.x + threadIdx.x;      // 0..262143
    float4 x = srcs[which][i];
    size_t d = (size_t)which * 524288 + (size_t)i * 2;
    __nv_bfloat162 h0, l0, h1, l1;
    split2(x.x, x.y, h0, l0);
    split2(x.z, x.w, h1, l1);
    hi[d] = h0; hi[d+1] = h1;
    lo[d] = l0; lo[d+1] = l1;
}

// gather kv_in (natural flat order row = b*2048+j) + split to bf16 hi/lo
__global__ void gather_split_kv(const float4* __restrict__ te,
                                const float4* __restrict__ mems)
{
    int idx = blockIdx.x * blockDim.x + threadIdx.x;    // 8192*256
    int row = idx >> 8, c = idx & 255;
    int b = row >> 11, j = row & 2047;
    float4 x;
    if (j < 1024) x = te  [((size_t)b * 1024 + j) * 256 + c];
    else          x = mems[((size_t)b * 2048 + (j - 1024)) * 256 + c];
    __nv_bfloat162 h0, l0, h1, l1;
    split2(x.x, x.y, h0, l0);
    split2(x.z, x.w, h1, l1);
    ((__nv_bfloat162*)g_KVh)[idx*2]   = h0;
    ((__nv_bfloat162*)g_KVh)[idx*2+1] = h1;
    ((__nv_bfloat162*)g_KVl)[idx*2]   = l0;
    ((__nv_bfloat162*)g_KVl)[idx*2+1] = l1;
}

// ---------------------------------------------------------------------------
// HMMA GEMM core, 3-stage cp.async pipeline, swizzled zero-pad tiles.
// 128x128 CTA tile, BK=32, 8 warps (64x32).
// Tile: 128 rows x 64B (no pad, XOR chunk swizzle). GTB=8192; buf 4 tiles =
// 32768 B; 3 bufs = 98304 B -> 2 CTA/SM (196608 <= 228KB).
// Epilogue modes: 0 = fp32+bias -> C; 1 = bias+split(bf16) -> o1;
//                 2 = dual split (bias+u -> o1, bias+v -> o2);
//                 3 = bias+split(fp16) -> o1.
// ---------------------------------------------------------------------------
#define GTB 8192
#define GBUF 32768

__device__ __forceinline__ void gemm_issue(
    uint32_t sb, int buf, int c, int tid,
    const __nv_bfloat16* Ah, const __nv_bfloat16* Al,
    const __nv_bfloat16* Wh, const __nv_bfloat16* Wl, int m0, int n0, int remapA)
{
    const int k0 = c * 32;
    const uint32_t base = sb + buf * GBUF;
#pragma unroll
    for (int p = 0; p < 2; p++) {
        int ch = tid + p * 256;
        int r = ch >> 2, s = ch & 3;
        uint32_t d = base + (uint32_t)(r * 64 + ((s ^ GSWZ(r)) << 4));
        int arow = m0 + r;
        if (remapA) arow += (arow >> 10) << 10;
        size_t ga = (size_t)arow * 1024 + k0 + s * 8;
        size_t gw = (size_t)(n0 + r) * 1024 + k0 + s * 8;
        CP_ASYNC(d,         Ah + ga);
        CP_ASYNC(d + GTB,   Al + ga);
        CP_ASYNC(d + 2*GTB, Wh + gw);
        CP_ASYNC(d + 3*GTB, Wl + gw);
    }
}

__device__ __forceinline__ void gemm_body(
    const __nv_bfloat16* Ah, const __nv_bfloat16* Al,
    const __nv_bfloat16* Wh, const __nv_bfloat16* Wl,
    const float* bias, float* C,
    void* o1h, void* o1l, void* o2h, void* o2l,
    const float* addu, const float* addv,
    int mode, int remapA, int m0, int n0, __nv_bfloat16* sm)
{
    const int tid = threadIdx.x, w = tid >> 5, lane = tid & 31;
    const int wm = (w & 1) * 64, wn = (w >> 1) * 32;
    const uint32_t sb = smem_u32(sm);
    const int lr = lane & 7, li = lane >> 3;

    float acc[4][4][4];
#pragma unroll
    for (int a = 0; a < 4; a++)
#pragma unroll
        for (int b = 0; b < 4; b++)
#pragma unroll
            for (int k = 0; k < 4; k++) acc[a][b][k] = 0.f;

    gemm_issue(sb, 0, 0, tid, Ah, Al, Wh, Wl, m0, n0, remapA);
    CP_COMMIT();
    gemm_issue(sb, 1, 1, tid, Ah, Al, Wh, Wl, m0, n0, remapA);
    CP_COMMIT();

    int bnext = 2;   // (c+2) % 3
    int bcur  = 0;   // c % 3
    for (int c = 0; c < 32; c++) {
        __syncthreads();          // all warps done reading buf bnext (= (c-1)%3)
        if (c + 2 < 32) {
            gemm_issue(sb, bnext, c + 2, tid, Ah, Al, Wh, Wl, m0, n0, remapA);
            CP_COMMIT();
            CP_WAIT2();
        } else if (c + 1 < 32) {
            CP_WAIT1();
        } else {
            CP_WAIT0();
        }
        __syncthreads();

        const uint32_t bb = sb + bcur * GBUF;
#pragma unroll
        for (int ks = 0; ks < 2; ks++) {
            const int sA = ks * 2 + (li >> 1);      // chunk for A frags
            const int sB = ks * 2 + (li & 1);       // chunk for B frags
            uint32_t ahf[4][4], alf[4][4];
            const int arow0 = wm + (li & 1) * 8 + lr;
#pragma unroll
            for (int mt = 0; mt < 4; mt++) {
                int rowA = arow0 + mt * 16;
                uint32_t ao = bb + (uint32_t)(rowA * 64 + ((sA ^ GSWZ(rowA)) << 4));
                ldsm4(ahf[mt], ao);
                ldsm4(alf[mt], ao + GTB);
            }
            uint32_t bhf[2][4], blf[2][4];
            const int brow0 = wn + (li >> 1) * 8 + lr;
#pragma unroll
            for (int nb = 0; nb < 2; nb++) {
                int rowB = brow0 + nb * 16;
                uint32_t bo = bb + 2*GTB + (uint32_t)(rowB * 64 + ((sB ^ GSWZ(rowB)) << 4));
                ldsm4(bhf[nb], bo);
                ldsm4(blf[nb], bo + GTB);
            }
#pragma unroll
            for (int mt = 0; mt < 4; mt++)
#pragma unroll
                for (int nt = 0; nt < 4; nt++) {
                    const uint32_t* bh = &bhf[nt >> 1][(nt & 1) * 2];
                    const uint32_t* bl = &blf[nt >> 1][(nt & 1) * 2];
                    mma16816(acc[mt][nt], ahf[mt], bh);
                    mma16816(acc[mt][nt], ahf[mt], bl);
                    mma16816(acc[mt][nt], alf[mt], bh);
                }
        }
        bcur = (bcur == 2) ? 0 : bcur + 1;
        bnext = (bnext == 2) ? 0 : bnext + 1;
    }

#pragma unroll
    for (int mt = 0; mt < 4; mt++) {
        int m = m0 + wm + mt * 16 + (lane >> 2);
#pragma unroll
        for (int half = 0; half < 2; half++) {
            size_t mrow = (size_t)(m + half * 8);
#pragma unroll
            for (int nt = 0; nt < 4; nt++) {
                int col = wn + nt * 8 + (lane & 3) * 2;
                int cg = n0 + col;
                float x = acc[mt][nt][half*2+0] + bias[cg];
                float y = acc[mt][nt][half*2+1] + bias[cg+1];
                size_t d = (mrow * 1024 + cg) >> 1;
                if (mode == 0) {
                    *(float2*)(C + mrow * 1024 + cg) = make_float2(x, y);
                } else if (mode == 1) {
                    __nv_bfloat162 h, l;
                    split2(x, y, h, l);
                    ((__nv_bfloat162*)o1h)[d] = h; ((__nv_bfloat162*)o1l)[d] = l;
                } else if (mode == 2) {
                    __nv_bfloat162 h, l;
                    split2(x + addu[cg], y + addu[cg+1], h, l);
                    ((__nv_bfloat162*)o1h)[d] = h; ((__nv_bfloat162*)o1l)[d] = l;
                    split2(x + addv[cg], y + addv[cg+1], h, l);
                    ((__nv_bfloat162*)o2h)[d] = h; ((__nv_bfloat162*)o2l)[d] = l;
                } else {
                    __half2 h, l;
                    split2h(x, y, h, l);
                    ((__half2*)o1h)[d] = h; ((__half2*)o1l)[d] = l;
                }
            }
        }
    }
}

// Fused Q/K/V/R projection launch: flat blockIdx.x in [0, 1408)
//   [0,512)=K-proj, [512,1024)=V-proj, [1024,1280)=Q-proj, [1280,1408)=R-proj
__global__ void __launch_bounds__(256, 2) hm_proj_fused(
    const float* __restrict__ bq, const float* __restrict__ bk,
    const float* __restrict__ bv, const float* __restrict__ br,
    const float* __restrict__ u,  const float* __restrict__ v)
{
    extern __shared__ __nv_bfloat16 sm[];
    const size_t WSZ = (size_t)1024 * 1024;
    const int bid = blockIdx.x;

    if (bid < 512) {                        // K projection: M=8192
        int l = bid;
        gemm_body(g_KVh, g_KVl, g_Wh + 1*WSZ, g_Wl + 1*WSZ, bk, nullptr,
                  g_Kh, g_Kl, nullptr, nullptr, nullptr, nullptr,
                  1, 0, (l >> 3) * 128, (l & 7) * 128, sm);
    } else if (bid < 1024) {                // V projection: M=8192, fp16 split
        int l = bid - 512;
        gemm_body(g_KVh, g_KVl, g_Wh + 2*WSZ, g_Wl + 2*WSZ, bv, nullptr,
                  g_Vh, g_Vl, nullptr, nullptr, nullptr, nullptr,
                  3, 0, (l >> 3) * 128, (l & 7) * 128, sm);
    } else if (bid < 1280) {                // Q projection: M=4096, dual split, remap
        int l = bid - 1024;
        gemm_body(g_KVh, g_KVl, g_Wh + 0*WSZ, g_Wl + 0*WSZ, bq, nullptr,
                  g_QUh, g_QUl, g_QVh, g_QVl, u, v,
                  2, 1, (l >> 3) * 128, (l & 7) * 128, sm);
    } else {                                // R projection: M=2048
        int l = bid - 1280;
        gemm_body(g_RELh, g_RELl, g_Wh + 3*WSZ, g_Wl + 3*WSZ, br, nullptr,
                  g_Rh, g_Rl, nullptr, nullptr, nullptr, nullptr,
                  1, 0, (l >> 3) * 128, (l & 7) * 128, sm);
    }
}

// O projection (separate: depends on attnv output)
__global__ void __launch_bounds__(256, 2) hm_gemm_o(
    const float* __restrict__ bo, float* __restrict__ C)
{
    extern __shared__ __nv_bfloat16 sm[];
    const size_t WSZ = (size_t)1024 * 1024;
    gemm_body(g_O1h, g_O1l, g_Wh + 4*WSZ, g_Wl + 4*WSZ, bo, C,
              nullptr, nullptr, nullptr, nullptr, nullptr, nullptr,
              0, 0, blockIdx.y * 128, blockIdx.x * 128, sm);
}

// ---------------------------------------------------------------------------
// HMMA batched scores, one launch. blockIdx.z in [0,128): mode = z>=64.
//   mode0 (AC): C[i,j] = (q+u)[i,b,n,:]·k[j,b,n,:]
//   mode1 (BD): C[i,l] = (q+v)[i,b,n,:]·kr[l,n,:]
// K=64 single shot. smem: 4 tiles x 128 rows x 144B (SLD=72 elem) = 73728 B
// (144 = 9*16: 16B aligned, conflict-free.)
// ---------------------------------------------------------------------------
#define SLD 72
#define STB 18432

__global__ void __launch_bounds__(256, 2) hm_scores(
    const __nv_bfloat16* __restrict__ QUh, const __nv_bfloat16* __restrict__ QUl,
    const __nv_bfloat16* __restrict__ Kh,  const __nv_bfloat16* __restrict__ Kl,
    const __nv_bfloat16* __restrict__ QVh, const __nv_bfloat16* __restrict__ QVl,
    const __nv_bfloat16* __restrict__ Rh,  const __nv_bfloat16* __restrict__ Rl,
    float* __restrict__ AC, float* __restrict__ BD)
{
    extern __shared__ __nv_bfloat16 sm[];
    const int tid = threadIdx.x, w = tid >> 5, lane = tid & 31;
    const int zz = blockIdx.z;
    const int mode = zz >= 64;
    const int z = zz & 63, b = z >> 4, n = z & 15;
    const int j0 = blockIdx.x * 128, i0 = blockIdx.y * 128;
    const int wm = (w & 1) * 64, wn = (w >> 1) * 32;
    const uint32_t sb = smem_u32(sm);
    const int lr = lane & 7, li = lane >> 3;

    const __nv_bfloat16* Ah = mode ? QVh : QUh;
    const __nv_bfloat16* Al = mode ? QVl : QUl;
    const __nv_bfloat16* Bh = mode ? Rh  : Kh;
    const __nv_bfloat16* Bl = mode ? Rl  : Kl;
    float* Out = mode ? BD : AC;

#pragma unroll
    for (int p = 0; p < 4; p++) {
        int ch = tid + p * 256;          // 0..1023
        int r = ch >> 3, s = ch & 7;
        uint32_t d = sb + (uint32_t)(r * SLD + s * 8) * 2;
        size_t ga = ((size_t)(i0 + r) * 4 + b) * 1024 + n * 64 + s * 8;
        size_t gb = mode ? ((size_t)(j0 + r) * 1024 + n * 64 + s * 8)
                         : (((size_t)(j0 + r) * 4 + b) * 1024 + n * 64 + s * 8);
        CP_ASYNC(d,           Ah + ga);
        CP_ASYNC(d + STB,     Al + ga);
        CP_ASYNC(d + 2*STB,   Bh + gb);
        CP_ASYNC(d + 3*STB,   Bl + gb);
    }
    CP_COMMIT();
    CP_WAIT0();
    __syncthreads();

    float acc[4][4][4];
#pragma unroll
    for (int a = 0; a < 4; a++)
#pragma unroll
        for (int c = 0; c < 4; c++)
#pragma unroll
            for (int k = 0; k < 4; k++) acc[a][c][k] = 0.f;

#pragma unroll
    for (int ks = 0; ks < 4; ks++) {
        uint32_t ahf[4][4], alf[4][4];
        const uint32_t acol = (uint32_t)(ks * 16 + (li >> 1) * 8) * 2;
        const uint32_t arow0 = (uint32_t)(wm + (li & 1) * 8 + lr);
#pragma unroll
        for (int mt = 0; mt < 4; mt++) {
            uint32_t ao = sb + (arow0 + mt * 16) * (SLD * 2) + acol;
            ldsm4(ahf[mt], ao);
            ldsm4(alf[mt], ao + STB);
        }
        uint32_t bhf[2][4], blf[2][4];
        const uint32_t bcol = (uint32_t)(ks * 16 + (li & 1) * 8) * 2;
        const uint32_t brow0 = (uint32_t)(wn + (li >> 1) * 8 + lr);
#pragma unroll
        for (int nb = 0; nb < 2; nb++) {
            uint32_t bo = sb + 2*STB + (brow0 + nb * 16) * (SLD * 2) + bcol;
            ldsm4(bhf[nb], bo);
            ldsm4(blf[nb], bo + STB);
        }
#pragma unroll
        for (int mt = 0; mt < 4; mt++)
#pragma unroll
            for (int nt = 0; nt < 4; nt++) {
                const uint32_t* bh = &bhf[nt >> 1][(nt & 1) * 2];
                const uint32_t* bl = &blf[nt >> 1][(nt & 1) * 2];
                mma16816(acc[mt][nt], ahf[mt], bh);
                mma16816(acc[mt][nt], ahf[mt], bl);
                mma16816(acc[mt][nt], alf[mt], bh);
            }
    }

    const size_t obase = (size_t)z * PLANE;
#pragma unroll
    for (int mt = 0; mt < 4; mt++) {
        int row = i0 + wm + mt * 16 + (lane >> 2);
        float* r0 = Out + obase + (size_t)row * 2048 + j0 + wn;
        float* r8 = r0 + (size_t)8 * 2048;
#pragma unroll
        for (int nt = 0; nt < 4; nt++) {
            int col = nt * 8 + (lane & 3) * 2;
            *(float2*)(r0 + col) = make_float2(acc[mt][nt][0], acc[mt][nt][1]);
            *(float2*)(r8 + col) = make_float2(acc[mt][nt][2], acc[mt][nt][3]);
        }
    }
}

// ---------------------------------------------------------------------------
// Softmax over the 16-head axis, 4 j per thread (float4):
//   AC + shifted BD + mask -> ATT (single fp16)
// ---------------------------------------------------------------------------
__global__ void softmax_heads(const float* __restrict__ amask)
{
    const int j4 = blockIdx.x * 128 + threadIdx.x;   // 0..511 (float4 col index)
    const int j  = j4 * 4;
    const int i  = blockIdx.y;
    const int b  = blockIdx.z;
    const int ioff = 1023 - i;                        // l = j + ioff
    const int bprime = i >> 8;
    const float* amrow = amask + (size_t)bprime * 1024;

    const size_t base = ((size_t)b * 16 * 1024 + i) * 2048;
    const float4* AC4 = (const float4*)(g_AC + base);

    float s[16][4];
    float mx[4] = {-1e30f, -1e30f, -1e30f, -1e30f};
#pragma unroll
    for (int n = 0; n < 16; n++) {
        float4 ac = AC4[(size_t)n * 524288 + j4];
        float a[4] = {ac.x, ac.y, ac.z, ac.w};
        const float* BDn = g_BD + base + (size_t)n * PLANE;
#pragma unroll
        for (int e = 0; e < 4; e++) {
            int l = j + e + ioff;
            float bd = (l < 2048) ? BDn[l] : 0.f;
            float val = (a[e] + bd) * 0.125f;
            int jp = ((j + e) * 64 + b * 16 + n) & 2047;
            float m = (jp < 1024) ? 1.f : amrow[jp - 1024];
            val -= (1.f - m) * 1e9f;
            s[n][e] = val;
            mx[e] = fmaxf(mx[e], val);
        }
    }
    float sum[4] = {0.f, 0.f, 0.f, 0.f};
#pragma unroll
    for (int n = 0; n < 16; n++)
#pragma unroll
        for (int e = 0; e < 4; e++) {
            s[n][e] = __expf(s[n][e] - mx[e]);
            sum[e] += s[n][e];
        }
    float inv[4] = {1.f/sum[0], 1.f/sum[1], 1.f/sum[2], 1.f/sum[3]};
#pragma unroll
    for (int n = 0; n < 16; n++) {
        __half2 p0 = __halves2half2(__float2half_rn(s[n][0] * inv[0]),
                                    __float2half_rn(s[n][1] * inv[1]));
        __half2 p1 = __halves2half2(__float2half_rn(s[n][2] * inv[2]),
                                    __float2half_rn(s[n][3] * inv[3]));
        size_t el = base + (size_t)n * PLANE + j;
        *(uint2*)(g_ATT + el) = make_uint2(*(const uint32_t*)&p0,
                                           *(const uint32_t*)&p1);
    }
}

// ---------------------------------------------------------------------------
// HMMA attn@V, fp16 2-term: A·Vh + A·Vl. Writes O1 hi/lo bf16 split.
// 3-stage pipeline. buf: ATT 18432 + Vh/l 2x9216 = 36864; x3 = 110592 B
// (SLD=72 elem -> 144B stride, 16B aligned, conflict-free.)
// ---------------------------------------------------------------------------
#define VTB 9216
#define ABUF 36864

__device__ __forceinline__ void attnv_issue(
    uint32_t sb, int buf, int c, int tid, int i0, int b, int n, size_t zbase)
{
    const uint32_t base = sb + buf * ABUF;
#pragma unroll
    for (int p = 0; p < 4; p++) {
        int ch = tid + p * 256;          // 0..1023
        int r = ch >> 3, s = ch & 7;
        uint32_t d = base + (uint32_t)(r * SLD + s * 8) * 2;
        size_t g = zbase + (size_t)(i0 + r) * 2048 + c * 64 + s * 8;
        CP_ASYNC(d, g_ATT + g);
    }
#pragma unroll
    for (int p = 0; p < 2; p++) {
        int ch = tid + p * 256;          // 0..511
        int r = ch >> 3, s = ch & 7;
        uint32_t d = base + STB + (uint32_t)(r * SLD + s * 8) * 2;
        size_t g = ((size_t)(c * 64 + r) * 4 + b) * 1024 + n * 64 + s * 8;
        CP_ASYNC(d,       g_Vh + g);
        CP_ASYNC(d + VTB, g_Vl + g);
    }
}

__global__ void __launch_bounds__(256, 2) hm_attnv()
{
    extern __shared__ __nv_bfloat16 sm[];
    const int tid = threadIdx.x, w = tid >> 5, lane = tid & 31;
    const int z = blockIdx.y, b = z >> 4, n = z & 15;
    const int i0 = blockIdx.x * 128;
    const int wm = (w & 3) * 32, wn = (w >> 2) * 32;
    const size_t zbase = (size_t)z * PLANE;
    const uint32_t sb = smem_u32(sm);
    const int lr = lane & 7, li = lane >> 3;

    float acc[2][4][4];
#pragma unroll
    for (int a = 0; a < 2; a++)
#pragma unroll
        for (int c = 0; c < 4; c++)
#pragma unroll
            for (int k = 0; k < 4; k++) acc[a][c][k] = 0.f;

    attnv_issue(sb, 0, 0, tid, i0, b, n, zbase);
    CP_COMMIT();
    attnv_issue(sb, 1, 1, tid, i0, b, n, zbase);
    CP_COMMIT();

    int bcur = 0, bnext = 2;
    for (int c = 0; c < 32; c++) {
        __syncthreads();
        if (c + 2 < 32) {
            attnv_issue(sb, bnext, c + 2, tid, i0, b, n, zbase);
            CP_COMMIT();
            CP_WAIT2();
        } else if (c + 1 < 32) {
            CP_WAIT1();
        } else {
            CP_WAIT0();
        }
        __syncthreads();

        const uint32_t bb = sb + bcur * ABUF;
#pragma unroll
        for (int ks = 0; ks < 4; ks++) {
            uint32_t ahf[2][4];
            const uint32_t acol = (uint32_t)(ks * 16 + (li >> 1) * 8) * 2;
            const uint32_t arow0 = (uint32_t)(wm + (li & 1) * 8 + lr);
#pragma unroll
            for (int mt = 0; mt < 2; mt++) {
                uint32_t ao = bb + (arow0 + mt * 16) * (SLD * 2) + acol;
                ldsm4(ahf[mt], ao);
            }
            uint32_t bhf[2][4], blf[2][4];
            const uint32_t vrow0 = (uint32_t)(ks * 16 + (li & 1) * 8 + lr);
#pragma unroll
            for (int nb = 0; nb < 2; nb++) {
                uint32_t vcol = (uint32_t)(wn + nb * 16 + (li >> 1) * 8) * 2;
                uint32_t bo = bb + STB + vrow0 * (SLD * 2) + vcol;
                ldsm4t(bhf[nb], bo);
                ldsm4t(blf[nb], bo + VTB);
            }
#pragma unroll
            for (int mt = 0; mt < 2; mt++)
#pragma unroll
                for (int nt = 0; nt < 4; nt++) {
                    const uint32_t* bh = &bhf[nt >> 1][(nt & 1) * 2];
                    const uint32_t* bl = &blf[nt >> 1][(nt & 1) * 2];
                    mma16816h(acc[mt][nt], ahf[mt], bh);
                    mma16816h(acc[mt][nt], ahf[mt], bl);
                }
        }
        bcur = (bcur == 2) ? 0 : bcur + 1;
        bnext = (bnext == 2) ? 0 : bnext + 1;
    }

#pragma unroll
    for (int mt = 0; mt < 2; mt++) {
        int i = i0 + wm + mt * 16 + (lane >> 2);
#pragma unroll
        for (int half = 0; half < 2; half++) {
            size_t rbase = ((size_t)(i + half * 8) * 4 + b) * 1024 + n * 64;
#pragma unroll
            for (int nt = 0; nt < 4; nt++) {
                int col = wn + nt * 8 + (lane & 3) * 2;
                __nv_bfloat162 h, l;
                split2(acc[mt][nt][half*2+0], acc[mt][nt][half*2+1], h, l);
                size_t d = (rbase + col) >> 1;
                ((__nv_bfloat162*)g_O1h)[d] = h;
                ((__nv_bfloat162*)g_O1l)[d] = l;
            }
        }
    }
}

// ---------------------------------------------------------------------------
__global__ void write_mems(const float4* __restrict__ mems,
                           const float4* __restrict__ out,
                           float4* __restrict__ dst)
{
    int idx = blockIdx.x * blockDim.x + threadIdx.x;
    int row = idx >> 8, c = idx & 255;
    int b = row >> 11, pos = row & 2047;
    float4 v;
    if (pos < 1024) v = mems[idx];
    else            v = out[(((size_t)b * 1024) + (pos - 1024)) * 256 + c];
    dst[idx] = v;
}

// ---------------------------------------------------------------------------
extern "C" void kernel_launch(void* const* d_in, const int* in_sizes, int n_in,
                              void* d_out, int out_size)
{
    const float* TE    = (const float*)d_in[0];
    const float* REL   = (const float*)d_in[1];
    const float* MEMS  = (const float*)d_in[2];
    const float* AMASK = (const float*)d_in[3];
    const float* Wq = (const float*)d_in[4],  *bq = (const float*)d_in[5];
    const float* Wk = (const float*)d_in[6],  *bk = (const float*)d_in[7];
    const float* Wv = (const float*)d_in[8],  *bv = (const float*)d_in[9];
    const float* Wr = (const float*)d_in[10], *br = (const float*)d_in[11];
    const float* Wo = (const float*)d_in[12], *bo = (const float*)d_in[13];
    const float* u  = (const float*)d_in[14];
    const float* v  = (const float*)d_in[15];
    float* out = (float*)d_out;

    const int G_SMEM = 3 * GBUF;      // 98304
    const int S_SMEM = 4 * STB;       // 73728
    const int A_SMEM = 3 * ABUF;      // 110592
    cudaFuncSetAttribute(hm_proj_fused, cudaFuncAttributeMaxDynamicSharedMemorySize, G_SMEM);
    cudaFuncSetAttribute(hm_gemm_o,     cudaFuncAttributeMaxDynamicSharedMemorySize, G_SMEM);
    cudaFuncSetAttribute(hm_scores,     cudaFuncAttributeMaxDynamicSharedMemorySize, S_SMEM);
    cudaFuncSetAttribute(hm_attnv,      cudaFuncAttributeMaxDynamicSharedMemorySize, A_SMEM);

    float *pAC, *pBD;
    cudaGetSymbolAddress((void**)&pAC, g_AC);
    cudaGetSymbolAddress((void**)&pBD, g_BD);

    __nv_bfloat16 *pRELh, *pRELl, *pWh, *pWl;
    __nv_bfloat16 *pQUh, *pQUl, *pQVh, *pQVl, *pKh, *pKl, *pRh, *pRl;
    cudaGetSymbolAddress((void**)&pRELh, g_RELh); cudaGetSymbolAddress((void**)&pRELl, g_RELl);
    cudaGetSymbolAddress((void**)&pWh,   g_Wh);   cudaGetSymbolAddress((void**)&pWl,   g_Wl);
    cudaGetSymbolAddress((void**)&pQUh,  g_QUh);  cudaGetSymbolAddress((void**)&pQUl,  g_QUl);
    cudaGetSymbolAddress((void**)&pQVh,  g_QVh);  cudaGetSymbolAddress((void**)&pQVl,  g_QVl);
    cudaGetSymbolAddress((void**)&pKh,   g_Kh);   cudaGetSymbolAddress((void**)&pKl,   g_Kl);
    cudaGetSymbolAddress((void**)&pRh,   g_Rh);   cudaGetSymbolAddress((void**)&pRl,   g_Rl);

    // 1. input splits (TE split eliminated via remapA in Q-proj)
    gather_split_kv<<<8192, 256>>>((const float4*)TE, (const float4*)MEMS);
    split_bf16<<<2048, 256>>>((const float4*)REL, (__nv_bfloat162*)pRELh, (__nv_bfloat162*)pRELl, 524288);
    split5_w<<<dim3(1024, 5), 256>>>((const float4*)Wq, (const float4*)Wk, (const float4*)Wv,
                                     (const float4*)Wr, (const float4*)Wo,
                                     (__nv_bfloat162*)pWh, (__nv_bfloat162*)pWl);

    // 2. all four projections in ONE launch (wave-packed, 3-stage pipeline)
    hm_proj_fused<<<1408, 256, G_SMEM>>>(bq, bk, bv, br, u, v);

    // 3. score GEMMs (AC + BD in one launch)
    hm_scores<<<dim3(16, 8, 128), 256, S_SMEM>>>(pQUh, pQUl, pKh, pKl,
                                                 pQVh, pQVl, pRh, pRl, pAC, pBD);

    // 4. rel-shift + mask + softmax over heads -> ATT (fp16), 4 j/thread
    softmax_heads<<<dim3(4, 1024, 4), 128>>>(AMASK);

    // 5. attn @ V (fp16 2-term, 3-stage pipeline) -> O1 hi/lo
    hm_attnv<<<dim3(8, 64), 256, A_SMEM>>>();

    // 6. O projection -> d_out (fp32)
    hm_gemm_o<<<dim3(8, 32), 256, G_SMEM>>>(bo, out);

    // 7. mems_new
    if (out_size >= 12582912)
        write_mems<<<8192, 256>>>((const float4*)MEMS, (const float4*)out,
                                  (float4*)(out + 4194304));
}

// round 13
// speedup vs baseline: 1.6814x; 1.2173x over previous
#include <cuda_runtime.h>
#include <cuda_fp16.h>
#include <stdint.h>
#include <math.h>

// ---------------------------------------------------------------------------
// Problem constants: B=4, S=1024, H=1024, HEADS=16, HEAD_D=64, K=2048
// ---------------------------------------------------------------------------
#define PLANE 2097152ull   // 1024*2048

// ---------------- scratch ----------------
__device__ float  g_AC [(size_t)64 * PLANE];
__device__ float  g_BD [(size_t)64 * PLANE];
__device__ __half g_ATT[(size_t)64 * PLANE];                 // attn, single fp16

__device__ __half g_KV [(size_t)8192*1024];                  // single fp16 (A-side)
__device__ __half g_REL[(size_t)2048*1024];                  // single fp16
__device__ __half g_Wh [(size_t)5*1024*1024], g_Wl [(size_t)5*1024*1024];
__device__ __half g_QU [(size_t)4096*1024];                  // single fp16
__device__ __half g_QV [(size_t)4096*1024];                  // single fp16
__device__ __half g_Kh [(size_t)8192*1024], g_Kl [(size_t)8192*1024];
__device__ __half g_Rh [(size_t)2048*1024], g_Rl [(size_t)2048*1024];
__device__ __half g_Vh [(size_t)8192*1024], g_Vl [(size_t)8192*1024];
__device__ __half g_O1 [(size_t)4096*1024];                  // single fp16

// ---------------------------------------------------------------------------
// Low-level helpers (sm_80-compatible: ldmatrix / mma.sync / cp.async)
// ---------------------------------------------------------------------------
__device__ __forceinline__ uint32_t smem_u32(const void* p) {
    uint32_t a;
    asm("{ .reg .u64 t; cvta.to.shared.u64 t, %1; cvt.u32.u64 %0, t; }"
        : "=r"(a) : "l"(p));
    return a;
}
__device__ __forceinline__ void ldsm4(uint32_t* r, uint32_t a) {
    asm volatile("ldmatrix.sync.aligned.m8n8.x4.shared.b16 {%0,%1,%2,%3}, [%4];"
        : "=r"(r[0]), "=r"(r[1]), "=r"(r[2]), "=r"(r[3]) : "r"(a));
}
__device__ __forceinline__ void ldsm4t(uint32_t* r, uint32_t a) {
    asm volatile("ldmatrix.sync.aligned.m8n8.x4.trans.shared.b16 {%0,%1,%2,%3}, [%4];"
        : "=r"(r[0]), "=r"(r[1]), "=r"(r[2]), "=r"(r[3]) : "r"(a));
}
__device__ __forceinline__ void mma16816h(float* c, const uint32_t* a, const uint32_t* b) {
    asm volatile(
        "mma.sync.aligned.m16n8k16.row.col.f32.f16.f16.f32 "
        "{%0,%1,%2,%3}, {%4,%5,%6,%7}, {%8,%9}, {%0,%1,%2,%3};"
        : "+f"(c[0]), "+f"(c[1]), "+f"(c[2]), "+f"(c[3])
        : "r"(a[0]), "r"(a[1]), "r"(a[2]), "r"(a[3]), "r"(b[0]), "r"(b[1]));
}
#define CP_ASYNC(dst, src) \
    asm volatile("cp.async.cg.shared.global [%0], [%1], 16;" :: "r"(dst), "l"(src))
#define CP_COMMIT() asm volatile("cp.async.commit_group;" ::: "memory")
#define CP_WAIT2()  asm volatile("cp.async.wait_group 2;" ::: "memory")
#define CP_WAIT1()  asm volatile("cp.async.wait_group 1;" ::: "memory")
#define CP_WAIT0()  asm volatile("cp.async.wait_group 0;" ::: "memory")

// GEMM tile swizzle: 64B rows (4 x 16B chunks), chunk permuted by row.
#define GSWZ(r) ((((r) ^ ((r) >> 2))) & 3)

__device__ __forceinline__ void split2h(float x, float y,
                                        __half2& h, __half2& l) {
    __half hx = __float2half_rn(x), hy = __float2half_rn(y);
    h = __halves2half2(hx, hy);
    l = __halves2half2(__float2half_rn(x - __half2float(hx)),
                       __float2half_rn(y - __half2float(hy)));
}

// ---------------------------------------------------------------------------
// fp32 -> single fp16 (generic)
// ---------------------------------------------------------------------------
__global__ void tohalf(const float4* __restrict__ in,
                       __half2* __restrict__ out, int n4)
{
    int i = blockIdx.x * blockDim.x + threadIdx.x;
    if (i >= n4) return;
    float4 x = in[i];
    out[i*2+0] = __halves2half2(__float2half_rn(x.x), __float2half_rn(x.y));
    out[i*2+1] = __halves2half2(__float2half_rn(x.z), __float2half_rn(x.w));
}

// split 5 weight matrices to fp16 hi/lo in one launch
__global__ void split5_w(const float4* w0, const float4* w1, const float4* w2,
                         const float4* w3, const float4* w4,
                         __half2* __restrict__ hi, __half2* __restrict__ lo)
{
    const float4* srcs[5] = {w0, w1, w2, w3, w4};
    int which = blockIdx.y;
    int i = blockIdx.x * blockDim.x + threadIdx.x;      // 0..262143
    float4 x = srcs[which][i];
    size_t d = (size_t)which * 524288 + (size_t)i * 2;
    __half2 h0, l0, h1, l1;
    split2h(x.x, x.y, h0, l0);
    split2h(x.z, x.w, h1, l1);
    hi[d] = h0; hi[d+1] = h1;
    lo[d] = l0; lo[d+1] = l1;
}

// gather kv_in (natural flat order row = b*2048+j) -> single fp16
__global__ void gather_kv_h(const float4* __restrict__ te,
                            const float4* __restrict__ mems)
{
    int idx = blockIdx.x * blockDim.x + threadIdx.x;    // 8192*256
    int row = idx >> 8, c = idx & 255;
    int b = row >> 11, j = row & 2047;
    float4 x;
    if (j < 1024) x = te  [((size_t)b * 1024 + j) * 256 + c];
    else          x = mems[((size_t)b * 2048 + (j - 1024)) * 256 + c];
    ((__half2*)g_KV)[idx*2+0] = __halves2half2(__float2half_rn(x.x), __float2half_rn(x.y));
    ((__half2*)g_KV)[idx*2+1] = __halves2half2(__float2half_rn(x.z), __float2half_rn(x.w));
}

// ---------------------------------------------------------------------------
// fp16 2-term HMMA GEMM core, 3-stage cp.async pipeline, swizzled tiles.
// C = A @ (Wh+Wl)^T + bias; A single fp16, W fp16 hi/lo; 2 MMAs per k-step.
// 128x128 CTA tile, BK=32, 8 warps (64x32).
// Tile 8192 B; buf 3 tiles = 24576 B; 3 bufs = 73728 B -> 2 CTA/SM.
// Epilogue modes: 0 = fp32+bias -> C; 1 = bias, fp16 hi/lo -> (o1h,o1l);
//                 2 = bias+u -> o1h (fp16), bias+v -> o2h (fp16).
// ---------------------------------------------------------------------------
#define GTB 8192
#define GBUF 24576

__device__ __forceinline__ void gemm_issue(
    uint32_t sb, int buf, int c, int tid,
    const __half* A, const __half* Wh, const __half* Wl,
    int m0, int n0, int remapA)
{
    const int k0 = c * 32;
    const uint32_t base = sb + buf * GBUF;
#pragma unroll
    for (int p = 0; p < 2; p++) {
        int ch = tid + p * 256;
        int r = ch >> 2, s = ch & 3;
        uint32_t d = base + (uint32_t)(r * 64 + ((s ^ GSWZ(r)) << 4));
        int arow = m0 + r;
        if (remapA) arow += (arow >> 10) << 10;
        size_t ga = (size_t)arow * 1024 + k0 + s * 8;
        size_t gw = (size_t)(n0 + r) * 1024 + k0 + s * 8;
        CP_ASYNC(d,         A  + ga);
        CP_ASYNC(d + GTB,   Wh + gw);
        CP_ASYNC(d + 2*GTB, Wl + gw);
    }
}

__device__ __forceinline__ void gemm_body(
    const __half* A, const __half* Wh, const __half* Wl,
    const float* bias, float* C,
    void* o1h, void* o1l, void* o2h,
    const float* addu, const float* addv,
    int mode, int remapA, int m0, int n0, __half* sm)
{
    const int tid = threadIdx.x, w = tid >> 5, lane = tid & 31;
    const int wm = (w & 1) * 64, wn = (w >> 1) * 32;
    const uint32_t sb = smem_u32(sm);
    const int lr = lane & 7, li = lane >> 3;

    float acc[4][4][4];
#pragma unroll
    for (int a = 0; a < 4; a++)
#pragma unroll
        for (int b = 0; b < 4; b++)
#pragma unroll
            for (int k = 0; k < 4; k++) acc[a][b][k] = 0.f;

    gemm_issue(sb, 0, 0, tid, A, Wh, Wl, m0, n0, remapA);
    CP_COMMIT();
    gemm_issue(sb, 1, 1, tid, A, Wh, Wl, m0, n0, remapA);
    CP_COMMIT();

    int bnext = 2, bcur = 0;
    for (int c = 0; c < 32; c++) {
        __syncthreads();
        if (c + 2 < 32) {
            gemm_issue(sb, bnext, c + 2, tid, A, Wh, Wl, m0, n0, remapA);
            CP_COMMIT();
            CP_WAIT2();
        } else if (c + 1 < 32) {
            CP_WAIT1();
        } else {
            CP_WAIT0();
        }
        __syncthreads();

        const uint32_t bb = sb + bcur * GBUF;
#pragma unroll
        for (int ks = 0; ks < 2; ks++) {
            const int sA = ks * 2 + (li >> 1);
            const int sB = ks * 2 + (li & 1);
            uint32_t ahf[4][4];
            const int arow0 = wm + (li & 1) * 8 + lr;
#pragma unroll
            for (int mt = 0; mt < 4; mt++) {
                int rowA = arow0 + mt * 16;
                uint32_t ao = bb + (uint32_t)(rowA * 64 + ((sA ^ GSWZ(rowA)) << 4));
                ldsm4(ahf[mt], ao);
            }
            uint32_t whf[2][4], wlf[2][4];
            const int brow0 = wn + (li >> 1) * 8 + lr;
#pragma unroll
            for (int nb = 0; nb < 2; nb++) {
                int rowB = brow0 + nb * 16;
                uint32_t bo = bb + GTB + (uint32_t)(rowB * 64 + ((sB ^ GSWZ(rowB)) << 4));
                ldsm4(whf[nb], bo);
                ldsm4(wlf[nb], bo + GTB);
            }
#pragma unroll
            for (int mt = 0; mt < 4; mt++)
#pragma unroll
                for (int nt = 0; nt < 4; nt++) {
                    const uint32_t* wh = &whf[nt >> 1][(nt & 1) * 2];
                    const uint32_t* wl = &wlf[nt >> 1][(nt & 1) * 2];
                    mma16816h(acc[mt][nt], ahf[mt], wh);
                    mma16816h(acc[mt][nt], ahf[mt], wl);
                }
        }
        bcur = (bcur == 2) ? 0 : bcur + 1;
        bnext = (bnext == 2) ? 0 : bnext + 1;
    }

#pragma unroll
    for (int mt = 0; mt < 4; mt++) {
        int m = m0 + wm + mt * 16 + (lane >> 2);
#pragma unroll
        for (int half = 0; half < 2; half++) {
            size_t mrow = (size_t)(m + half * 8);
#pragma unroll
            for (int nt = 0; nt < 4; nt++) {
                int col = wn + nt * 8 + (lane & 3) * 2;
                int cg = n0 + col;
                float x = acc[mt][nt][half*2+0] + bias[cg];
                float y = acc[mt][nt][half*2+1] + bias[cg+1];
                size_t d = (mrow * 1024 + cg) >> 1;
                if (mode == 0) {
                    *(float2*)(C + mrow * 1024 + cg) = make_float2(x, y);
                } else if (mode == 1) {
                    __half2 h, l;
                    split2h(x, y, h, l);
                    ((__half2*)o1h)[d] = h; ((__half2*)o1l)[d] = l;
                } else {
                    ((__half2*)o1h)[d] = __halves2half2(
                        __float2half_rn(x + addu[cg]), __float2half_rn(y + addu[cg+1]));
                    ((__half2*)o2h)[d] = __halves2half2(
                        __float2half_rn(x + addv[cg]), __float2half_rn(y + addv[cg+1]));
                }
            }
        }
    }
}

// Fused Q/K/V/R projection launch: flat blockIdx.x in [0, 1408)
__global__ void __launch_bounds__(256, 2) hm_proj_fused(
    const float* __restrict__ bq, const float* __restrict__ bk,
    const float* __restrict__ bv, const float* __restrict__ br,
    const float* __restrict__ u,  const float* __restrict__ v)
{
    extern __shared__ __half sm[];
    const size_t WSZ = (size_t)1024 * 1024;
    const int bid = blockIdx.x;

    if (bid < 512) {                        // K projection: M=8192
        int l = bid;
        gemm_body(g_KV, g_Wh + 1*WSZ, g_Wl + 1*WSZ, bk, nullptr,
                  g_Kh, g_Kl, nullptr, nullptr, nullptr,
                  1, 0, (l >> 3) * 128, (l & 7) * 128, sm);
    } else if (bid < 1024) {                // V projection: M=8192
        int l = bid - 512;
        gemm_body(g_KV, g_Wh + 2*WSZ, g_Wl + 2*WSZ, bv, nullptr,
                  g_Vh, g_Vl, nullptr, nullptr, nullptr,
                  1, 0, (l >> 3) * 128, (l & 7) * 128, sm);
    } else if (bid < 1280) {                // Q projection: M=4096, dual, remap
        int l = bid - 1024;
        gemm_body(g_KV, g_Wh + 0*WSZ, g_Wl + 0*WSZ, bq, nullptr,
                  g_QU, nullptr, g_QV, u, v,
                  2, 1, (l >> 3) * 128, (l & 7) * 128, sm);
    } else {                                // R projection: M=2048
        int l = bid - 1280;
        gemm_body(g_REL, g_Wh + 3*WSZ, g_Wl + 3*WSZ, br, nullptr,
                  g_Rh, g_Rl, nullptr, nullptr, nullptr,
                  1, 0, (l >> 3) * 128, (l & 7) * 128, sm);
    }
}

// O projection (depends on attnv output)
__global__ void __launch_bounds__(256, 2) hm_gemm_o(
    const float* __restrict__ bo, float* __restrict__ C)
{
    extern __shared__ __half sm[];
    const size_t WSZ = (size_t)1024 * 1024;
    gemm_body(g_O1, g_Wh + 4*WSZ, g_Wl + 4*WSZ, bo, C,
              nullptr, nullptr, nullptr, nullptr, nullptr,
              0, 0, blockIdx.y * 128, blockIdx.x * 128, sm);
}

// ---------------------------------------------------------------------------
// fp16 2-term batched scores, one launch. blockIdx.z in [0,128): mode = z>=64.
//   mode0 (AC): C[i,j] = (q+u)[i,b,n,:]·k[j,b,n,:]
//   mode1 (BD): C[i,l] = (q+v)[i,b,n,:]·kr[l,n,:]
// K=64 single shot. smem: 3 tiles x 128 rows x 144B = 55296 B
// ---------------------------------------------------------------------------
#define SLD 72
#define STB 18432

__global__ void __launch_bounds__(256, 2) hm_scores(
    float* __restrict__ AC, float* __restrict__ BD)
{
    extern __shared__ __half sm[];
    const int tid = threadIdx.x, w = tid >> 5, lane = tid & 31;
    const int zz = blockIdx.z;
    const int mode = zz >= 64;
    const int z = zz & 63, b = z >> 4, n = z & 15;
    const int j0 = blockIdx.x * 128, i0 = blockIdx.y * 128;
    const int wm = (w & 1) * 64, wn = (w >> 1) * 32;
    const uint32_t sb = smem_u32(sm);
    const int lr = lane & 7, li = lane >> 3;

    const __half* A  = mode ? g_QV : g_QU;
    const __half* Bh = mode ? g_Rh : g_Kh;
    const __half* Bl = mode ? g_Rl : g_Kl;
    float* Out = mode ? BD : AC;

#pragma unroll
    for (int p = 0; p < 4; p++) {
        int ch = tid + p * 256;          // 0..1023
        int r = ch >> 3, s = ch & 7;
        uint32_t d = sb + (uint32_t)(r * SLD + s * 8) * 2;
        size_t ga = ((size_t)(i0 + r) * 4 + b) * 1024 + n * 64 + s * 8;
        size_t gb = mode ? ((size_t)(j0 + r) * 1024 + n * 64 + s * 8)
                         : (((size_t)(j0 + r) * 4 + b) * 1024 + n * 64 + s * 8);
        CP_ASYNC(d,           A  + ga);
        CP_ASYNC(d + STB,     Bh + gb);
        CP_ASYNC(d + 2*STB,   Bl + gb);
    }
    CP_COMMIT();
    CP_WAIT0();
    __syncthreads();

    float acc[4][4][4];
#pragma unroll
    for (int a = 0; a < 4; a++)
#pragma unroll
        for (int c = 0; c < 4; c++)
#pragma unroll
            for (int k = 0; k < 4; k++) acc[a][c][k] = 0.f;

#pragma unroll
    for (int ks = 0; ks < 4; ks++) {
        uint32_t ahf[4][4];
        const uint32_t acol = (uint32_t)(ks * 16 + (li >> 1) * 8) * 2;
        const uint32_t arow0 = (uint32_t)(wm + (li & 1) * 8 + lr);
#pragma unroll
        for (int mt = 0; mt < 4; mt++) {
            uint32_t ao = sb + (arow0 + mt * 16) * (SLD * 2) + acol;
            ldsm4(ahf[mt], ao);
        }
        uint32_t bhf[2][4], blf[2][4];
        const uint32_t bcol = (uint32_t)(ks * 16 + (li & 1) * 8) * 2;
        const uint32_t brow0 = (uint32_t)(wn + (li >> 1) * 8 + lr);
#pragma unroll
        for (int nb = 0; nb < 2; nb++) {
            uint32_t bo = sb + STB + (brow0 + nb * 16) * (SLD * 2) + bcol;
            ldsm4(bhf[nb], bo);
            ldsm4(blf[nb], bo + STB);
        }
#pragma unroll
        for (int mt = 0; mt < 4; mt++)
#pragma unroll
            for (int nt = 0; nt < 4; nt++) {
                const uint32_t* bh = &bhf[nt >> 1][(nt & 1) * 2];
                const uint32_t* bl = &blf[nt >> 1][(nt & 1) * 2];
                mma16816h(acc[mt][nt], ahf[mt], bh);
                mma16816h(acc[mt][nt], ahf[mt], bl);
            }
    }

    const size_t obase = (size_t)z * PLANE;
#pragma unroll
    for (int mt = 0; mt < 4; mt++) {
        int row = i0 + wm + mt * 16 + (lane >> 2);
        float* r0 = Out + obase + (size_t)row * 2048 + j0 + wn;
        float* r8 = r0 + (size_t)8 * 2048;
#pragma unroll
        for (int nt = 0; nt < 4; nt++) {
            int col = nt * 8 + (lane & 3) * 2;
            *(float2*)(r0 + col) = make_float2(acc[mt][nt][0], acc[mt][nt][1]);
            *(float2*)(r8 + col) = make_float2(acc[mt][nt][2], acc[mt][nt][3]);
        }
    }
}

// ---------------------------------------------------------------------------
// Softmax over the 16-head axis, 4 j per thread (float4):
//   AC + shifted BD + mask -> ATT (single fp16)
// ---------------------------------------------------------------------------
__global__ void softmax_heads(const float* __restrict__ amask)
{
    const int j4 = blockIdx.x * 128 + threadIdx.x;   // 0..511
    const int j  = j4 * 4;
    const int i  = blockIdx.y;
    const int b  = blockIdx.z;
    const int ioff = 1023 - i;
    const int bprime = i >> 8;
    const float* amrow = amask + (size_t)bprime * 1024;

    const size_t base = ((size_t)b * 16 * 1024 + i) * 2048;
    const float4* AC4 = (const float4*)(g_AC + base);

    float s[16][4];
    float mx[4] = {-1e30f, -1e30f, -1e30f, -1e30f};
#pragma unroll
    for (int n = 0; n < 16; n++) {
        float4 ac = AC4[(size_t)n * 524288 + j4];
        float a[4] = {ac.x, ac.y, ac.z, ac.w};
        const float* BDn = g_BD + base + (size_t)n * PLANE;
#pragma unroll
        for (int e = 0; e < 4; e++) {
            int l = j + e + ioff;
            float bd = (l < 2048) ? BDn[l] : 0.f;
            float val = (a[e] + bd) * 0.125f;
            int jp = ((j + e) * 64 + b * 16 + n) & 2047;
            float m = (jp < 1024) ? 1.f : amrow[jp - 1024];
            val -= (1.f - m) * 1e9f;
            s[n][e] = val;
            mx[e] = fmaxf(mx[e], val);
        }
    }
    float sum[4] = {0.f, 0.f, 0.f, 0.f};
#pragma unroll
    for (int n = 0; n < 16; n++)
#pragma unroll
        for (int e = 0; e < 4; e++) {
            s[n][e] = __expf(s[n][e] - mx[e]);
            sum[e] += s[n][e];
        }
    float inv[4] = {1.f/sum[0], 1.f/sum[1], 1.f/sum[2], 1.f/sum[3]};
#pragma unroll
    for (int n = 0; n < 16; n++) {
        __half2 p0 = __halves2half2(__float2half_rn(s[n][0] * inv[0]),
                                    __float2half_rn(s[n][1] * inv[1]));
        __half2 p1 = __halves2half2(__float2half_rn(s[n][2] * inv[2]),
                                    __float2half_rn(s[n][3] * inv[3]));
        size_t el = base + (size_t)n * PLANE + j;
        *(uint2*)(g_ATT + el) = make_uint2(*(const uint32_t*)&p0,
                                           *(const uint32_t*)&p1);
    }
}

// ---------------------------------------------------------------------------
// HMMA attn@V, fp16 2-term: A·Vh + A·Vl. Writes O1 single fp16.
// 3-stage pipeline. buf: ATT 18432 + Vh/l 2x9216 = 36864; x3 = 110592 B
// ---------------------------------------------------------------------------
#define VTB 9216
#define ABUF 36864

__device__ __forceinline__ void attnv_issue(
    uint32_t sb, int buf, int c, int tid, int i0, int b, int n, size_t zbase)
{
    const uint32_t base = sb + buf * ABUF;
#pragma unroll
    for (int p = 0; p < 4; p++) {
        int ch = tid + p * 256;          // 0..1023
        int r = ch >> 3, s = ch & 7;
        uint32_t d = base + (uint32_t)(r * SLD + s * 8) * 2;
        size_t g = zbase + (size_t)(i0 + r) * 2048 + c * 64 + s * 8;
        CP_ASYNC(d, g_ATT + g);
    }
#pragma unroll
    for (int p = 0; p < 2; p++) {
        int ch = tid + p * 256;          // 0..511
        int r = ch >> 3, s = ch & 7;
        uint32_t d = base + STB + (uint32_t)(r * SLD + s * 8) * 2;
        size_t g = ((size_t)(c * 64 + r) * 4 + b) * 1024 + n * 64 + s * 8;
        CP_ASYNC(d,       g_Vh + g);
        CP_ASYNC(d + VTB, g_Vl + g);
    }
}

__global__ void __launch_bounds__(256, 2) hm_attnv()
{
    extern __shared__ __half sm[];
    const int tid = threadIdx.x, w = tid >> 5, lane = tid & 31;
    const int z = blockIdx.y, b = z >> 4, n = z & 15;
    const int i0 = blockIdx.x * 128;
    const int wm = (w & 3) * 32, wn = (w >> 2) * 32;
    const size_t zbase = (size_t)z * PLANE;
    const uint32_t sb = smem_u32(sm);
    const int lr = lane & 7, li = lane >> 3;

    float acc[2][4][4];
#pragma unroll
    for (int a = 0; a < 2; a++)
#pragma unroll
        for (int c = 0; c < 4; c++)
#pragma unroll
            for (int k = 0; k < 4; k++) acc[a][c][k] = 0.f;

    attnv_issue(sb, 0, 0, tid, i0, b, n, zbase);
    CP_COMMIT();
    attnv_issue(sb, 1, 1, tid, i0, b, n, zbase);
    CP_COMMIT();

    int bcur = 0, bnext = 2;
    for (int c = 0; c < 32; c++) {
        __syncthreads();
        if (c + 2 < 32) {
            attnv_issue(sb, bnext, c + 2, tid, i0, b, n, zbase);
            CP_COMMIT();
            CP_WAIT2();
        } else if (c + 1 < 32) {
            CP_WAIT1();
        } else {
            CP_WAIT0();
        }
        __syncthreads();

        const uint32_t bb = sb + bcur * ABUF;
#pragma unroll
        for (int ks = 0; ks < 4; ks++) {
            uint32_t ahf[2][4];
            const uint32_t acol = (uint32_t)(ks * 16 + (li >> 1) * 8) * 2;
            const uint32_t arow0 = (uint32_t)(wm + (li & 1) * 8 + lr);
#pragma unroll
            for (int mt = 0; mt < 2; mt++) {
                uint32_t ao = bb + (arow0 + mt * 16) * (SLD * 2) + acol;
                ldsm4(ahf[mt], ao);
            }
            uint32_t bhf[2][4], blf[2][4];
            const uint32_t vrow0 = (uint32_t)(ks * 16 + (li & 1) * 8 + lr);
#pragma unroll
            for (int nb = 0; nb < 2; nb++) {
                uint32_t vcol = (uint32_t)(wn + nb * 16 + (li >> 1) * 8) * 2;
                uint32_t bo = bb + STB + vrow0 * (SLD * 2) + vcol;
                ldsm4t(bhf[nb], bo);
                ldsm4t(blf[nb], bo + VTB);
            }
#pragma unroll
            for (int mt = 0; mt < 2; mt++)
#pragma unroll
                for (int nt = 0; nt < 4; nt++) {
                    const uint32_t* bh = &bhf[nt >> 1][(nt & 1) * 2];
                    const uint32_t* bl = &blf[nt >> 1][(nt & 1) * 2];
                    mma16816h(acc[mt][nt], ahf[mt], bh);
                    mma16816h(acc[mt][nt], ahf[mt], bl);
                }
        }
        bcur = (bcur == 2) ? 0 : bcur + 1;
        bnext = (bnext == 2) ? 0 : bnext + 1;
    }

#pragma unroll
    for (int mt = 0; mt < 2; mt++) {
        int i = i0 + wm + mt * 16 + (lane >> 2);
#pragma unroll
        for (int half = 0; half < 2; half++) {
            size_t rbase = ((size_t)(i + half * 8) * 4 + b) * 1024 + n * 64;
#pragma unroll
            for (int nt = 0; nt < 4; nt++) {
                int col = wn + nt * 8 + (lane & 3) * 2;
                size_t d = (rbase + col) >> 1;
                ((__half2*)g_O1)[d] = __halves2half2(
                    __float2half_rn(acc[mt][nt][half*2+0]),
                    __float2half_rn(acc[mt][nt][half*2+1]));
            }
        }
    }
}

// ---------------------------------------------------------------------------
__global__ void write_mems(const float4* __restrict__ mems,
                           const float4* __restrict__ out,
                           float4* __restrict__ dst)
{
    int idx = blockIdx.x * blockDim.x + threadIdx.x;
    int row = idx >> 8, c = idx & 255;
    int b = row >> 11, pos = row & 2047;
    float4 v;
    if (pos < 1024) v = mems[idx];
    else            v = out[(((size_t)b * 1024) + (pos - 1024)) * 256 + c];
    dst[idx] = v;
}

// ---------------------------------------------------------------------------
extern "C" void kernel_launch(void* const* d_in, const int* in_sizes, int n_in,
                              void* d_out, int out_size)
{
    const float* TE    = (const float*)d_in[0];
    const float* REL   = (const float*)d_in[1];
    const float* MEMS  = (const float*)d_in[2];
    const float* AMASK = (const float*)d_in[3];
    const float* Wq = (const float*)d_in[4],  *bq = (const float*)d_in[5];
    const float* Wk = (const float*)d_in[6],  *bk = (const float*)d_in[7];
    const float* Wv = (const float*)d_in[8],  *bv = (const float*)d_in[9];
    const float* Wr = (const float*)d_in[10], *br = (const float*)d_in[11];
    const float* Wo = (const float*)d_in[12], *bo = (const float*)d_in[13];
    const float* u  = (const float*)d_in[14];
    const float* v  = (const float*)d_in[15];
    float* out = (float*)d_out;

    const int G_SMEM = 3 * GBUF;      // 73728
    const int S_SMEM = 3 * STB;       // 55296
    const int A_SMEM = 3 * ABUF;      // 110592
    cudaFuncSetAttribute(hm_proj_fused, cudaFuncAttributeMaxDynamicSharedMemorySize, G_SMEM);
    cudaFuncSetAttribute(hm_gemm_o,     cudaFuncAttributeMaxDynamicSharedMemorySize, G_SMEM);
    cudaFuncSetAttribute(hm_scores,     cudaFuncAttributeMaxDynamicSharedMemorySize, S_SMEM);
    cudaFuncSetAttribute(hm_attnv,      cudaFuncAttributeMaxDynamicSharedMemorySize, A_SMEM);

    float *pAC, *pBD;
    cudaGetSymbolAddress((void**)&pAC, g_AC);
    cudaGetSymbolAddress((void**)&pBD, g_BD);
    __half *pREL, *pWh, *pWl;
    cudaGetSymbolAddress((void**)&pREL, g_REL);
    cudaGetSymbolAddress((void**)&pWh,  g_Wh);
    cudaGetSymbolAddress((void**)&pWl,  g_Wl);

    // 1. input conversions (fp16): KV gather, REL, weights hi/lo
    gather_kv_h<<<8192, 256>>>((const float4*)TE, (const float4*)MEMS);
    tohalf<<<2048, 256>>>((const float4*)REL, (__half2*)pREL, 524288);
    split5_w<<<dim3(1024, 5), 256>>>((const float4*)Wq, (const float4*)Wk, (const float4*)Wv,
                                     (const float4*)Wr, (const float4*)Wo,
                                     (__half2*)pWh, (__half2*)pWl);

    // 2. all four projections in ONE launch (wave-packed, 3-stage, fp16 2-term)
    hm_proj_fused<<<1408, 256, G_SMEM>>>(bq, bk, bv, br, u, v);

    // 3. score GEMMs (AC + BD in one launch)
    hm_scores<<<dim3(16, 8, 128), 256, S_SMEM>>>(pAC, pBD);

    // 4. rel-shift + mask + softmax over heads -> ATT (fp16)
    softmax_heads<<<dim3(4, 1024, 4), 128>>>(AMASK);

    // 5. attn @ V (fp16 2-term, 3-stage) -> O1 single fp16
    hm_attnv<<<dim3(8, 64), 256, A_SMEM>>>();

    // 6. O projection -> d_out (fp32)
    hm_gemm_o<<<dim3(8, 32), 256, G_SMEM>>>(bo, out);

    // 7. mems_new
    if (out_size >= 12582912)
        write_mems<<<8192, 256>>>((const float4*)MEMS, (const float4*)out,
                                  (float4*)(out + 4194304));
}

// round 14
// speedup vs baseline: 1.6824x; 1.0006x over previous
#include <cuda_runtime.h>
#include <cuda_fp16.h>
#include <stdint.h>
#include <math.h>

// ---------------------------------------------------------------------------
// Problem constants: B=4, S=1024, H=1024, HEADS=16, HEAD_D=64, K=2048
// ---------------------------------------------------------------------------
#define PLANE 2097152ull   // 1024*2048

// ---------------- scratch ----------------
__device__ __half g_AC [(size_t)64 * PLANE];                 // fp16 score planes
__device__ __half g_BD [(size_t)64 * PLANE];
__device__ __half g_ATT[(size_t)64 * PLANE];                 // attn, single fp16

__device__ __half g_KV [(size_t)8192*1024];                  // single fp16 (A-side)
__device__ __half g_REL[(size_t)2048*1024];                  // single fp16
__device__ __half g_Wh [(size_t)5*1024*1024], g_Wl [(size_t)5*1024*1024];
__device__ __half g_QU [(size_t)4096*1024];                  // single fp16
__device__ __half g_QV [(size_t)4096*1024];                  // single fp16
__device__ __half g_Kh [(size_t)8192*1024], g_Kl [(size_t)8192*1024];
__device__ __half g_Rh [(size_t)2048*1024], g_Rl [(size_t)2048*1024];
__device__ __half g_Vh [(size_t)8192*1024], g_Vl [(size_t)8192*1024];
__device__ __half g_O1 [(size_t)4096*1024];                  // single fp16

// ---------------------------------------------------------------------------
// Low-level helpers (sm_80-compatible: ldmatrix / mma.sync / cp.async)
// ---------------------------------------------------------------------------
__device__ __forceinline__ uint32_t smem_u32(const void* p) {
    uint32_t a;
    asm("{ .reg .u64 t; cvta.to.shared.u64 t, %1; cvt.u32.u64 %0, t; }"
        : "=r"(a) : "l"(p));
    return a;
}
__device__ __forceinline__ void ldsm4(uint32_t* r, uint32_t a) {
    asm volatile("ldmatrix.sync.aligned.m8n8.x4.shared.b16 {%0,%1,%2,%3}, [%4];"
        : "=r"(r[0]), "=r"(r[1]), "=r"(r[2]), "=r"(r[3]) : "r"(a));
}
__device__ __forceinline__ void ldsm4t(uint32_t* r, uint32_t a) {
    asm volatile("ldmatrix.sync.aligned.m8n8.x4.trans.shared.b16 {%0,%1,%2,%3}, [%4];"
        : "=r"(r[0]), "=r"(r[1]), "=r"(r[2]), "=r"(r[3]) : "r"(a));
}
__device__ __forceinline__ void mma16816h(float* c, const uint32_t* a, const uint32_t* b) {
    asm volatile(
        "mma.sync.aligned.m16n8k16.row.col.f32.f16.f16.f32 "
        "{%0,%1,%2,%3}, {%4,%5,%6,%7}, {%8,%9}, {%0,%1,%2,%3};"
        : "+f"(c[0]), "+f"(c[1]), "+f"(c[2]), "+f"(c[3])
        : "r"(a[0]), "r"(a[1]), "r"(a[2]), "r"(a[3]), "r"(b[0]), "r"(b[1]));
}
#define CP_ASYNC(dst, src) \
    asm volatile("cp.async.cg.shared.global [%0], [%1], 16;" :: "r"(dst), "l"(src))
#define CP_COMMIT() asm volatile("cp.async.commit_group;" ::: "memory")
#define CP_WAIT2()  asm volatile("cp.async.wait_group 2;" ::: "memory")
#define CP_WAIT1()  asm volatile("cp.async.wait_group 1;" ::: "memory")
#define CP_WAIT0()  asm volatile("cp.async.wait_group 0;" ::: "memory")

// GEMM tile swizzle: 64B rows (4 x 16B chunks), chunk permuted by row.
#define GSWZ(r) ((((r) ^ ((r) >> 2))) & 3)

__device__ __forceinline__ void split2h(float x, float y,
                                        __half2& h, __half2& l) {
    __half hx = __float2half_rn(x), hy = __float2half_rn(y);
    h = __halves2half2(hx, hy);
    l = __halves2half2(__float2half_rn(x - __half2float(hx)),
                       __float2half_rn(y - __half2float(hy)));
}

// ---------------------------------------------------------------------------
// fp32 -> single fp16 (generic)
// ---------------------------------------------------------------------------
__global__ void tohalf(const float4* __restrict__ in,
                       __half2* __restrict__ out, int n4)
{
    int i = blockIdx.x * blockDim.x + threadIdx.x;
    if (i >= n4) return;
    float4 x = in[i];
    out[i*2+0] = __halves2half2(__float2half_rn(x.x), __float2half_rn(x.y));
    out[i*2+1] = __halves2half2(__float2half_rn(x.z), __float2half_rn(x.w));
}

// split 5 weight matrices to fp16 hi/lo in one launch
__global__ void split5_w(const float4* w0, const float4* w1, const float4* w2,
                         const float4* w3, const float4* w4,
                         __half2* __restrict__ hi, __half2* __restrict__ lo)
{
    const float4* srcs[5] = {w0, w1, w2, w3, w4};
    int which = blockIdx.y;
    int i = blockIdx.x * blockDim.x + threadIdx.x;      // 0..262143
    float4 x = srcs[which][i];
    size_t d = (size_t)which * 524288 + (size_t)i * 2;
    __half2 h0, l0, h1, l1;
    split2h(x.x, x.y, h0, l0);
    split2h(x.z, x.w, h1, l1);
    hi[d] = h0; hi[d+1] = h1;
    lo[d] = l0; lo[d+1] = l1;
}

// gather kv_in (natural flat order row = b*2048+j) -> single fp16
__global__ void gather_kv_h(const float4* __restrict__ te,
                            const float4* __restrict__ mems)
{
    int idx = blockIdx.x * blockDim.x + threadIdx.x;    // 8192*256
    int row = idx >> 8, c = idx & 255;
    int b = row >> 11, j = row & 2047;
    float4 x;
    if (j < 1024) x = te  [((size_t)b * 1024 + j) * 256 + c];
    else          x = mems[((size_t)b * 2048 + (j - 1024)) * 256 + c];
    ((__half2*)g_KV)[idx*2+0] = __halves2half2(__float2half_rn(x.x), __float2half_rn(x.y));
    ((__half2*)g_KV)[idx*2+1] = __halves2half2(__float2half_rn(x.z), __float2half_rn(x.w));
}

// ---------------------------------------------------------------------------
// fp16 2-term HMMA GEMM core, 3-stage cp.async pipeline, swizzled tiles.
// C = A @ (Wh+Wl)^T + bias; A single fp16, W fp16 hi/lo; 2 MMAs per k-step.
// 128x128 CTA tile, BK=32, 8 warps (64x32).
// Tile 8192 B; buf 3 tiles = 24576 B; 3 bufs = 73728 B -> 2 CTA/SM.
// Epilogue modes: 0 = fp32+bias -> C; 1 = bias, fp16 hi/lo -> (o1h,o1l);
//                 2 = bias+u -> o1h (fp16), bias+v -> o2h (fp16).
// ---------------------------------------------------------------------------
#define GTB 8192
#define GBUF 24576

__device__ __forceinline__ void gemm_issue(
    uint32_t sb, int buf, int c, int tid,
    const __half* A, const __half* Wh, const __half* Wl,
    int m0, int n0, int remapA)
{
    const int k0 = c * 32;
    const uint32_t base = sb + buf * GBUF;
#pragma unroll
    for (int p = 0; p < 2; p++) {
        int ch = tid + p * 256;
        int r = ch >> 2, s = ch & 3;
        uint32_t d = base + (uint32_t)(r * 64 + ((s ^ GSWZ(r)) << 4));
        int arow = m0 + r;
        if (remapA) arow += (arow >> 10) << 10;
        size_t ga = (size_t)arow * 1024 + k0 + s * 8;
        size_t gw = (size_t)(n0 + r) * 1024 + k0 + s * 8;
        CP_ASYNC(d,         A  + ga);
        CP_ASYNC(d + GTB,   Wh + gw);
        CP_ASYNC(d + 2*GTB, Wl + gw);
    }
}

__device__ __forceinline__ void gemm_body(
    const __half* A, const __half* Wh, const __half* Wl,
    const float* bias, float* C,
    void* o1h, void* o1l, void* o2h,
    const float* addu, const float* addv,
    int mode, int remapA, int m0, int n0, __half* sm)
{
    const int tid = threadIdx.x, w = tid >> 5, lane = tid & 31;
    const int wm = (w & 1) * 64, wn = (w >> 1) * 32;
    const uint32_t sb = smem_u32(sm);
    const int lr = lane & 7, li = lane >> 3;

    float acc[4][4][4];
#pragma unroll
    for (int a = 0; a < 4; a++)
#pragma unroll
        for (int b = 0; b < 4; b++)
#pragma unroll
            for (int k = 0; k < 4; k++) acc[a][b][k] = 0.f;

    gemm_issue(sb, 0, 0, tid, A, Wh, Wl, m0, n0, remapA);
    CP_COMMIT();
    gemm_issue(sb, 1, 1, tid, A, Wh, Wl, m0, n0, remapA);
    CP_COMMIT();

    int bnext = 2, bcur = 0;
    for (int c = 0; c < 32; c++) {
        __syncthreads();
        if (c + 2 < 32) {
            gemm_issue(sb, bnext, c + 2, tid, A, Wh, Wl, m0, n0, remapA);
            CP_COMMIT();
            CP_WAIT2();
        } else if (c + 1 < 32) {
            CP_WAIT1();
        } else {
            CP_WAIT0();
        }
        __syncthreads();

        const uint32_t bb = sb + bcur * GBUF;
#pragma unroll
        for (int ks = 0; ks < 2; ks++) {
            const int sA = ks * 2 + (li >> 1);
            const int sB = ks * 2 + (li & 1);
            uint32_t ahf[4][4];
            const int arow0 = wm + (li & 1) * 8 + lr;
#pragma unroll
            for (int mt = 0; mt < 4; mt++) {
                int rowA = arow0 + mt * 16;
                uint32_t ao = bb + (uint32_t)(rowA * 64 + ((sA ^ GSWZ(rowA)) << 4));
                ldsm4(ahf[mt], ao);
            }
            uint32_t whf[2][4], wlf[2][4];
            const int brow0 = wn + (li >> 1) * 8 + lr;
#pragma unroll
            for (int nb = 0; nb < 2; nb++) {
                int rowB = brow0 + nb * 16;
                uint32_t bo = bb + GTB + (uint32_t)(rowB * 64 + ((sB ^ GSWZ(rowB)) << 4));
                ldsm4(whf[nb], bo);
                ldsm4(wlf[nb], bo + GTB);
            }
#pragma unroll
            for (int mt = 0; mt < 4; mt++)
#pragma unroll
                for (int nt = 0; nt < 4; nt++) {
                    const uint32_t* wh = &whf[nt >> 1][(nt & 1) * 2];
                    const uint32_t* wl = &wlf[nt >> 1][(nt & 1) * 2];
                    mma16816h(acc[mt][nt], ahf[mt], wh);
                    mma16816h(acc[mt][nt], ahf[mt], wl);
                }
        }
        bcur = (bcur == 2) ? 0 : bcur + 1;
        bnext = (bnext == 2) ? 0 : bnext + 1;
    }

#pragma unroll
    for (int mt = 0; mt < 4; mt++) {
        int m = m0 + wm + mt * 16 + (lane >> 2);
#pragma unroll
        for (int half = 0; half < 2; half++) {
            size_t mrow = (size_t)(m + half * 8);
#pragma unroll
            for (int nt = 0; nt < 4; nt++) {
                int col = wn + nt * 8 + (lane & 3) * 2;
                int cg = n0 + col;
                float x = acc[mt][nt][half*2+0] + bias[cg];
                float y = acc[mt][nt][half*2+1] + bias[cg+1];
                size_t d = (mrow * 1024 + cg) >> 1;
                if (mode == 0) {
                    *(float2*)(C + mrow * 1024 + cg) = make_float2(x, y);
                } else if (mode == 1) {
                    __half2 h, l;
                    split2h(x, y, h, l);
                    ((__half2*)o1h)[d] = h; ((__half2*)o1l)[d] = l;
                } else {
                    ((__half2*)o1h)[d] = __halves2half2(
                        __float2half_rn(x + addu[cg]), __float2half_rn(y + addu[cg+1]));
                    ((__half2*)o2h)[d] = __halves2half2(
                        __float2half_rn(x + addv[cg]), __float2half_rn(y + addv[cg+1]));
                }
            }
        }
    }
}

// Fused Q/K/V/R projection launch: flat blockIdx.x in [0, 1408)
__global__ void __launch_bounds__(256, 2) hm_proj_fused(
    const float* __restrict__ bq, const float* __restrict__ bk,
    const float* __restrict__ bv, const float* __restrict__ br,
    const float* __restrict__ u,  const float* __restrict__ v)
{
    extern __shared__ __half sm[];
    const size_t WSZ = (size_t)1024 * 1024;
    const int bid = blockIdx.x;

    if (bid < 512) {                        // K projection: M=8192
        int l = bid;
        gemm_body(g_KV, g_Wh + 1*WSZ, g_Wl + 1*WSZ, bk, nullptr,
                  g_Kh, g_Kl, nullptr, nullptr, nullptr,
                  1, 0, (l >> 3) * 128, (l & 7) * 128, sm);
    } else if (bid < 1024) {                // V projection: M=8192
        int l = bid - 512;
        gemm_body(g_KV, g_Wh + 2*WSZ, g_Wl + 2*WSZ, bv, nullptr,
                  g_Vh, g_Vl, nullptr, nullptr, nullptr,
                  1, 0, (l >> 3) * 128, (l & 7) * 128, sm);
    } else if (bid < 1280) {                // Q projection: M=4096, dual, remap
        int l = bid - 1024;
        gemm_body(g_KV, g_Wh + 0*WSZ, g_Wl + 0*WSZ, bq, nullptr,
                  g_QU, nullptr, g_QV, u, v,
                  2, 1, (l >> 3) * 128, (l & 7) * 128, sm);
    } else {                                // R projection: M=2048
        int l = bid - 1280;
        gemm_body(g_REL, g_Wh + 3*WSZ, g_Wl + 3*WSZ, br, nullptr,
                  g_Rh, g_Rl, nullptr, nullptr, nullptr,
                  1, 0, (l >> 3) * 128, (l & 7) * 128, sm);
    }
}

// O projection (depends on attnv output)
__global__ void __launch_bounds__(256, 2) hm_gemm_o(
    const float* __restrict__ bo, float* __restrict__ C)
{
    extern __shared__ __half sm[];
    const size_t WSZ = (size_t)1024 * 1024;
    gemm_body(g_O1, g_Wh + 4*WSZ, g_Wl + 4*WSZ, bo, C,
              nullptr, nullptr, nullptr, nullptr, nullptr,
              0, 0, blockIdx.y * 128, blockIdx.x * 128, sm);
}

// ---------------------------------------------------------------------------
// fp16 2-term batched scores -> fp16 planes. blockIdx.z in [0,128): mode=z>=64.
//   mode0 (AC): C[i,j] = (q+u)[i,b,n,:]·k[j,b,n,:]
//   mode1 (BD): C[i,l] = (q+v)[i,b,n,:]·kr[l,n,:]
// K=64 single shot. smem: 3 tiles x 128 rows x 144B = 55296 B
// ---------------------------------------------------------------------------
#define SLD 72
#define STB 18432

__global__ void __launch_bounds__(256, 2) hm_scores()
{
    extern __shared__ __half sm[];
    const int tid = threadIdx.x, w = tid >> 5, lane = tid & 31;
    const int zz = blockIdx.z;
    const int mode = zz >= 64;
    const int z = zz & 63, b = z >> 4, n = z & 15;
    const int j0 = blockIdx.x * 128, i0 = blockIdx.y * 128;
    const int wm = (w & 1) * 64, wn = (w >> 1) * 32;
    const uint32_t sb = smem_u32(sm);
    const int lr = lane & 7, li = lane >> 3;

    const __half* A  = mode ? g_QV : g_QU;
    const __half* Bh = mode ? g_Rh : g_Kh;
    const __half* Bl = mode ? g_Rl : g_Kl;
    __half* Out = mode ? g_BD : g_AC;

#pragma unroll
    for (int p = 0; p < 4; p++) {
        int ch = tid + p * 256;          // 0..1023
        int r = ch >> 3, s = ch & 7;
        uint32_t d = sb + (uint32_t)(r * SLD + s * 8) * 2;
        size_t ga = ((size_t)(i0 + r) * 4 + b) * 1024 + n * 64 + s * 8;
        size_t gb = mode ? ((size_t)(j0 + r) * 1024 + n * 64 + s * 8)
                         : (((size_t)(j0 + r) * 4 + b) * 1024 + n * 64 + s * 8);
        CP_ASYNC(d,           A  + ga);
        CP_ASYNC(d + STB,     Bh + gb);
        CP_ASYNC(d + 2*STB,   Bl + gb);
    }
    CP_COMMIT();
    CP_WAIT0();
    __syncthreads();

    float acc[4][4][4];
#pragma unroll
    for (int a = 0; a < 4; a++)
#pragma unroll
        for (int c = 0; c < 4; c++)
#pragma unroll
            for (int k = 0; k < 4; k++) acc[a][c][k] = 0.f;

#pragma unroll
    for (int ks = 0; ks < 4; ks++) {
        uint32_t ahf[4][4];
        const uint32_t acol = (uint32_t)(ks * 16 + (li >> 1) * 8) * 2;
        const uint32_t arow0 = (uint32_t)(wm + (li & 1) * 8 + lr);
#pragma unroll
        for (int mt = 0; mt < 4; mt++) {
            uint32_t ao = sb + (arow0 + mt * 16) * (SLD * 2) + acol;
            ldsm4(ahf[mt], ao);
        }
        uint32_t bhf[2][4], blf[2][4];
        const uint32_t bcol = (uint32_t)(ks * 16 + (li & 1) * 8) * 2;
        const uint32_t brow0 = (uint32_t)(wn + (li >> 1) * 8 + lr);
#pragma unroll
        for (int nb = 0; nb < 2; nb++) {
            uint32_t bo = sb + STB + (brow0 + nb * 16) * (SLD * 2) + bcol;
            ldsm4(bhf[nb], bo);
            ldsm4(blf[nb], bo + STB);
        }
#pragma unroll
        for (int mt = 0; mt < 4; mt++)
#pragma unroll
            for (int nt = 0; nt < 4; nt++) {
                const uint32_t* bh = &bhf[nt >> 1][(nt & 1) * 2];
                const uint32_t* bl = &blf[nt >> 1][(nt & 1) * 2];
                mma16816h(acc[mt][nt], ahf[mt], bh);
                mma16816h(acc[mt][nt], ahf[mt], bl);
            }
    }

    const size_t obase = (size_t)z * PLANE;
#pragma unroll
    for (int mt = 0; mt < 4; mt++) {
        int row = i0 + wm + mt * 16 + (lane >> 2);
        __half* r0 = Out + obase + (size_t)row * 2048 + j0 + wn;
        __half* r8 = r0 + (size_t)8 * 2048;
#pragma unroll
        for (int nt = 0; nt < 4; nt++) {
            int col = nt * 8 + (lane & 3) * 2;
            *(__half2*)(r0 + col) = __halves2half2(
                __float2half_rn(acc[mt][nt][0]), __float2half_rn(acc[mt][nt][1]));
            *(__half2*)(r8 + col) = __halves2half2(
                __float2half_rn(acc[mt][nt][2]), __float2half_rn(acc[mt][nt][3]));
        }
    }
}

// ---------------------------------------------------------------------------
// Softmax over the 16-head axis, 4 j per thread:
//   AC(fp16) + shifted BD(fp16) + mask -> ATT (single fp16)
// ---------------------------------------------------------------------------
__global__ void softmax_heads(const float* __restrict__ amask)
{
    const int j4 = blockIdx.x * 128 + threadIdx.x;   // 0..511
    const int j  = j4 * 4;
    const int i  = blockIdx.y;
    const int b  = blockIdx.z;
    const int ioff = 1023 - i;
    const int bprime = i >> 8;
    const float* amrow = amask + (size_t)bprime * 1024;

    const size_t base = ((size_t)b * 16 * 1024 + i) * 2048;

    float s[16][4];
    float mx[4] = {-1e30f, -1e30f, -1e30f, -1e30f};
#pragma unroll
    for (int n = 0; n < 16; n++) {
        const __half* ACn = g_AC + base + (size_t)n * PLANE;
        uint2 raw = *(const uint2*)(ACn + j);             // 4 halves
        __half2 a01 = *(__half2*)&raw.x;
        __half2 a23 = *(__half2*)&raw.y;
        float a[4] = { __low2float(a01), __high2float(a01),
                       __low2float(a23), __high2float(a23) };
        const __half* BDn = g_BD + base + (size_t)n * PLANE;
#pragma unroll
        for (int e = 0; e < 4; e++) {
            int l = j + e + ioff;
            float bd = (l < 2048) ? __half2float(BDn[l]) : 0.f;
            float val = (a[e] + bd) * 0.125f;
            int jp = ((j + e) * 64 + b * 16 + n) & 2047;
            float m = (jp < 1024) ? 1.f : amrow[jp - 1024];
            val -= (1.f - m) * 1e9f;
            s[n][e] = val;
            mx[e] = fmaxf(mx[e], val);
        }
    }
    float sum[4] = {0.f, 0.f, 0.f, 0.f};
#pragma unroll
    for (int n = 0; n < 16; n++)
#pragma unroll
        for (int e = 0; e < 4; e++) {
            s[n][e] = __expf(s[n][e] - mx[e]);
            sum[e] += s[n][e];
        }
    float inv[4] = {1.f/sum[0], 1.f/sum[1], 1.f/sum[2], 1.f/sum[3]};
#pragma unroll
    for (int n = 0; n < 16; n++) {
        __half2 p0 = __halves2half2(__float2half_rn(s[n][0] * inv[0]),
                                    __float2half_rn(s[n][1] * inv[1]));
        __half2 p1 = __halves2half2(__float2half_rn(s[n][2] * inv[2]),
                                    __float2half_rn(s[n][3] * inv[3]));
        size_t el = base + (size_t)n * PLANE + j;
        *(uint2*)(g_ATT + el) = make_uint2(*(const uint32_t*)&p0,
                                           *(const uint32_t*)&p1);
    }
}

// ---------------------------------------------------------------------------
// HMMA attn@V, fp16 2-term: A·Vh + A·Vl. Writes O1 single fp16.
// 3-stage pipeline. buf: ATT 18432 + Vh/l 2x9216 = 36864; x3 = 110592 B
// ---------------------------------------------------------------------------
#define VTB 9216
#define ABUF 36864

__device__ __forceinline__ void attnv_issue(
    uint32_t sb, int buf, int c, int tid, int i0, int b, int n, size_t zbase)
{
    const uint32_t base = sb + buf * ABUF;
#pragma unroll
    for (int p = 0; p < 4; p++) {
        int ch = tid + p * 256;          // 0..1023
        int r = ch >> 3, s = ch & 7;
        uint32_t d = base + (uint32_t)(r * SLD + s * 8) * 2;
        size_t g = zbase + (size_t)(i0 + r) * 2048 + c * 64 + s * 8;
        CP_ASYNC(d, g_ATT + g);
    }
#pragma unroll
    for (int p = 0; p < 2; p++) {
        int ch = tid + p * 256;          // 0..511
        int r = ch >> 3, s = ch & 7;
        uint32_t d = base + STB + (uint32_t)(r * SLD + s * 8) * 2;
        size_t g = ((size_t)(c * 64 + r) * 4 + b) * 1024 + n * 64 + s * 8;
        CP_ASYNC(d,       g_Vh + g);
        CP_ASYNC(d + VTB, g_Vl + g);
    }
}

__global__ void __launch_bounds__(256, 2) hm_attnv()
{
    extern __shared__ __half sm[];
    const int tid = threadIdx.x, w = tid >> 5, lane = tid & 31;
    const int z = blockIdx.y, b = z >> 4, n = z & 15;
    const int i0 = blockIdx.x * 128;
    const int wm = (w & 3) * 32, wn = (w >> 2) * 32;
    const size_t zbase = (size_t)z * PLANE;
    const uint32_t sb = smem_u32(sm);
    const int lr = lane & 7, li = lane >> 3;

    float acc[2][4][4];
#pragma unroll
    for (int a = 0; a < 2; a++)
#pragma unroll
        for (int c = 0; c < 4; c++)
#pragma unroll
            for (int k = 0; k < 4; k++) acc[a][c][k] = 0.f;

    attnv_issue(sb, 0, 0, tid, i0, b, n, zbase);
    CP_COMMIT();
    attnv_issue(sb, 1, 1, tid, i0, b, n, zbase);
    CP_COMMIT();

    int bcur = 0, bnext = 2;
    for (int c = 0; c < 32; c++) {
        __syncthreads();
        if (c + 2 < 32) {
            attnv_issue(sb, bnext, c + 2, tid, i0, b, n, zbase);
            CP_COMMIT();
            CP_WAIT2();
        } else if (c + 1 < 32) {
            CP_WAIT1();
        } else {
            CP_WAIT0();
        }
        __syncthreads();

        const uint32_t bb = sb + bcur * ABUF;
#pragma unroll
        for (int ks = 0; ks < 4; ks++) {
            uint32_t ahf[2][4];
            const uint32_t acol = (uint32_t)(ks * 16 + (li >> 1) * 8) * 2;
            const uint32_t arow0 = (uint32_t)(wm + (li & 1) * 8 + lr);
#pragma unroll
            for (int mt = 0; mt < 2; mt++) {
                uint32_t ao = bb + (arow0 + mt * 16) * (SLD * 2) + acol;
                ldsm4(ahf[mt], ao);
            }
            uint32_t bhf[2][4], blf[2][4];
            const uint32_t vrow0 = (uint32_t)(ks * 16 + (li & 1) * 8 + lr);
#pragma unroll
            for (int nb = 0; nb < 2; nb++) {
                uint32_t vcol = (uint32_t)(wn + nb * 16 + (li >> 1) * 8) * 2;
                uint32_t bo = bb + STB + vrow0 * (SLD * 2) + vcol;
                ldsm4t(bhf[nb], bo);
                ldsm4t(blf[nb], bo + VTB);
            }
#pragma unroll
            for (int mt = 0; mt < 2; mt++)
#pragma unroll
                for (int nt = 0; nt < 4; nt++) {
                    const uint32_t* bh = &bhf[nt >> 1][(nt & 1) * 2];
                    const uint32_t* bl = &blf[nt >> 1][(nt & 1) * 2];
                    mma16816h(acc[mt][nt], ahf[mt], bh);
                    mma16816h(acc[mt][nt], ahf[mt], bl);
                }
        }
        bcur = (bcur == 2) ? 0 : bcur + 1;
        bnext = (bnext == 2) ? 0 : bnext + 1;
    }

#pragma unroll
    for (int mt = 0; mt < 2; mt++) {
        int i = i0 + wm + mt * 16 + (lane >> 2);
#pragma unroll
        for (int half = 0; half < 2; half++) {
            size_t rbase = ((size_t)(i + half * 8) * 4 + b) * 1024 + n * 64;
#pragma unroll
            for (int nt = 0; nt < 4; nt++) {
                int col = wn + nt * 8 + (lane & 3) * 2;
                size_t d = (rbase + col) >> 1;
                ((__half2*)g_O1)[d] = __halves2half2(
                    __float2half_rn(acc[mt][nt][half*2+0]),
                    __float2half_rn(acc[mt][nt][half*2+1]));
            }
        }
    }
}

// ---------------------------------------------------------------------------
__global__ void write_mems(const float4* __restrict__ mems,
                           const float4* __restrict__ out,
                           float4* __restrict__ dst)
{
    int idx = blockIdx.x * blockDim.x + threadIdx.x;
    int row = idx >> 8, c = idx & 255;
    int b = row >> 11, pos = row & 2047;
    float4 v;
    if (pos < 1024) v = mems[idx];
    else            v = out[(((size_t)b * 1024) + (pos - 1024)) * 256 + c];
    dst[idx] = v;
}

// ---------------------------------------------------------------------------
extern "C" void kernel_launch(void* const* d_in, const int* in_sizes, int n_in,
                              void* d_out, int out_size)
{
    const float* TE    = (const float*)d_in[0];
    const float* REL   = (const float*)d_in[1];
    const float* MEMS  = (const float*)d_in[2];
    const float* AMASK = (const float*)d_in[3];
    const float* Wq = (const float*)d_in[4],  *bq = (const float*)d_in[5];
    const float* Wk = (const float*)d_in[6],  *bk = (const float*)d_in[7];
    const float* Wv = (const float*)d_in[8],  *bv = (const float*)d_in[9];
    const float* Wr = (const float*)d_in[10], *br = (const float*)d_in[11];
    const float* Wo = (const float*)d_in[12], *bo = (const float*)d_in[13];
    const float* u  = (const float*)d_in[14];
    const float* v  = (const float*)d_in[15];
    float* out = (float*)d_out;

    const int G_SMEM = 3 * GBUF;      // 73728
    const int S_SMEM = 3 * STB;       // 55296
    const int A_SMEM = 3 * ABUF;      // 110592
    cudaFuncSetAttribute(hm_proj_fused, cudaFuncAttributeMaxDynamicSharedMemorySize, G_SMEM);
    cudaFuncSetAttribute(hm_gemm_o,     cudaFuncAttributeMaxDynamicSharedMemorySize, G_SMEM);
    cudaFuncSetAttribute(hm_scores,     cudaFuncAttributeMaxDynamicSharedMemorySize, S_SMEM);
    cudaFuncSetAttribute(hm_attnv,      cudaFuncAttributeMaxDynamicSharedMemorySize, A_SMEM);

    __half *pREL, *pWh, *pWl;
    cudaGetSymbolAddress((void**)&pREL, g_REL);
    cudaGetSymbolAddress((void**)&pWh,  g_Wh);
    cudaGetSymbolAddress((void**)&pWl,  g_Wl);

    // 1. input conversions (fp16): KV gather, REL, weights hi/lo
    gather_kv_h<<<8192, 256>>>((const float4*)TE, (const float4*)MEMS);
    tohalf<<<2048, 256>>>((const float4*)REL, (__half2*)pREL, 524288);
    split5_w<<<dim3(1024, 5), 256>>>((const float4*)Wq, (const float4*)Wk, (const float4*)Wv,
                                     (const float4*)Wr, (const float4*)Wo,
                                     (__half2*)pWh, (__half2*)pWl);

    // 2. all four projections in ONE launch (wave-packed, 3-stage, fp16 2-term)
    hm_proj_fused<<<1408, 256, G_SMEM>>>(bq, bk, bv, br, u, v);

    // 3. score GEMMs (AC + BD in one launch, fp16 planes)
    hm_scores<<<dim3(16, 8, 128), 256, S_SMEM>>>();

    // 4. rel-shift + mask + softmax over heads -> ATT (fp16)
    softmax_heads<<<dim3(4, 1024, 4), 128>>>(AMASK);

    // 5. attn @ V (fp16 2-term, 3-stage) -> O1 single fp16
    hm_attnv<<<dim3(8, 64), 256, A_SMEM>>>();

    // 6. O projection -> d_out (fp32)
    hm_gemm_o<<<dim3(8, 32), 256, G_SMEM>>>(bo, out);

    // 7. mems_new
    if (out_size >= 12582912)
        write_mems<<<8192, 256>>>((const float4*)MEMS, (const float4*)out,
                                  (float4*)(out + 4194304));
}

// round 15
// speedup vs baseline: 1.7152x; 1.0195x over previous
#include <cuda_runtime.h>
#include <cuda_fp16.h>
#include <stdint.h>
#include <math.h>

// ---------------------------------------------------------------------------
// Problem constants: B=4, S=1024, H=1024, HEADS=16, HEAD_D=64, K=2048
// ---------------------------------------------------------------------------
#define PLANE 2097152ull   // 1024*2048

// ---------------- scratch ----------------
__device__ __half g_AC [(size_t)64 * PLANE];                 // fp16 score planes
__device__ __half g_BD [(size_t)64 * PLANE];
__device__ __half g_ATT[(size_t)64 * PLANE];                 // attn, single fp16

__device__ __half g_KV [(size_t)8192*1024];                  // single fp16 (A-side)
__device__ __half g_REL[(size_t)2048*1024];                  // single fp16
__device__ __half g_Wh [(size_t)5*1024*1024], g_Wl [(size_t)5*1024*1024];
__device__ __half g_QU [(size_t)4096*1024];                  // single fp16
__device__ __half g_QV [(size_t)4096*1024];                  // single fp16
__device__ __half g_Kh [(size_t)8192*1024], g_Kl [(size_t)8192*1024];
__device__ __half g_Rh [(size_t)2048*1024], g_Rl [(size_t)2048*1024];
__device__ __half g_Vh [(size_t)8192*1024], g_Vl [(size_t)8192*1024];
__device__ __half g_O1 [(size_t)4096*1024];                  // single fp16

// ---------------------------------------------------------------------------
// Low-level helpers (sm_80-compatible: ldmatrix / mma.sync / cp.async)
// ---------------------------------------------------------------------------
__device__ __forceinline__ uint32_t smem_u32(const void* p) {
    uint32_t a;
    asm("{ .reg .u64 t; cvta.to.shared.u64 t, %1; cvt.u32.u64 %0, t; }"
        : "=r"(a) : "l"(p));
    return a;
}
__device__ __forceinline__ void ldsm4(uint32_t* r, uint32_t a) {
    asm volatile("ldmatrix.sync.aligned.m8n8.x4.shared.b16 {%0,%1,%2,%3}, [%4];"
        : "=r"(r[0]), "=r"(r[1]), "=r"(r[2]), "=r"(r[3]) : "r"(a));
}
__device__ __forceinline__ void ldsm4t(uint32_t* r, uint32_t a) {
    asm volatile("ldmatrix.sync.aligned.m8n8.x4.trans.shared.b16 {%0,%1,%2,%3}, [%4];"
        : "=r"(r[0]), "=r"(r[1]), "=r"(r[2]), "=r"(r[3]) : "r"(a));
}
__device__ __forceinline__ void mma16816h(float* c, const uint32_t* a, const uint32_t* b) {
    asm volatile(
        "mma.sync.aligned.m16n8k16.row.col.f32.f16.f16.f32 "
        "{%0,%1,%2,%3}, {%4,%5,%6,%7}, {%8,%9}, {%0,%1,%2,%3};"
        : "+f"(c[0]), "+f"(c[1]), "+f"(c[2]), "+f"(c[3])
        : "r"(a[0]), "r"(a[1]), "r"(a[2]), "r"(a[3]), "r"(b[0]), "r"(b[1]));
}
#define CP_ASYNC(dst, src) \
    asm volatile("cp.async.cg.shared.global [%0], [%1], 16;" :: "r"(dst), "l"(src))
#define CP_COMMIT() asm volatile("cp.async.commit_group;" ::: "memory")
#define CP_WAIT2()  asm volatile("cp.async.wait_group 2;" ::: "memory")
#define CP_WAIT1()  asm volatile("cp.async.wait_group 1;" ::: "memory")
#define CP_WAIT0()  asm volatile("cp.async.wait_group 0;" ::: "memory")

// GEMM tile swizzle: 64B rows (4 x 16B chunks), chunk permuted by row.
#define GSWZ(r) ((((r) ^ ((r) >> 2))) & 3)

__device__ __forceinline__ void split2h(float x, float y,
                                        __half2& h, __half2& l) {
    __half hx = __float2half_rn(x), hy = __float2half_rn(y);
    h = __halves2half2(hx, hy);
    l = __halves2half2(__float2half_rn(x - __half2float(hx)),
                       __float2half_rn(y - __half2float(hy)));
}

// ---------------------------------------------------------------------------
// fp32 -> single fp16 (generic)
// ---------------------------------------------------------------------------
__global__ void tohalf(const float4* __restrict__ in,
                       __half2* __restrict__ out, int n4)
{
    int i = blockIdx.x * blockDim.x + threadIdx.x;
    if (i >= n4) return;
    float4 x = in[i];
    out[i*2+0] = __halves2half2(__float2half_rn(x.x), __float2half_rn(x.y));
    out[i*2+1] = __halves2half2(__float2half_rn(x.z), __float2half_rn(x.w));
}

// split 5 weight matrices to fp16 hi/lo in one launch
__global__ void split5_w(const float4* w0, const float4* w1, const float4* w2,
                         const float4* w3, const float4* w4,
                         __half2* __restrict__ hi, __half2* __restrict__ lo)
{
    const float4* srcs[5] = {w0, w1, w2, w3, w4};
    int which = blockIdx.y;
    int i = blockIdx.x * blockDim.x + threadIdx.x;      // 0..262143
    float4 x = srcs[which][i];
    size_t d = (size_t)which * 524288 + (size_t)i * 2;
    __half2 h0, l0, h1, l1;
    split2h(x.x, x.y, h0, l0);
    split2h(x.z, x.w, h1, l1);
    hi[d] = h0; hi[d+1] = h1;
    lo[d] = l0; lo[d+1] = l1;
}

// gather kv_in (natural flat order row = b*2048+j) -> single fp16
__global__ void gather_kv_h(const float4* __restrict__ te,
                            const float4* __restrict__ mems)
{
    int idx = blockIdx.x * blockDim.x + threadIdx.x;    // 8192*256
    int row = idx >> 8, c = idx & 255;
    int b = row >> 11, j = row & 2047;
    float4 x;
    if (j < 1024) x = te  [((size_t)b * 1024 + j) * 256 + c];
    else          x = mems[((size_t)b * 2048 + (j - 1024)) * 256 + c];
    ((__half2*)g_KV)[idx*2+0] = __halves2half2(__float2half_rn(x.x), __float2half_rn(x.y));
    ((__half2*)g_KV)[idx*2+1] = __halves2half2(__float2half_rn(x.z), __float2half_rn(x.w));
}

// ---------------------------------------------------------------------------
// fp16 2-term HMMA GEMM core, 3-stage cp.async pipeline, swizzled tiles.
// C = A @ (Wh+Wl)^T + bias; A single fp16, W fp16 hi/lo; 2 MMAs per k-step.
// 128x128 CTA tile, BK=32, 8 warps (64x32).
// Tile 8192 B; buf 3 tiles = 24576 B; 3 bufs = 73728 B -> 2 CTA/SM.
// Epilogue modes: 0 = fp32+bias -> C; 1 = bias, fp16 hi/lo -> (o1h,o1l);
//                 2 = bias+u -> o1h (fp16), bias+v -> o2h (fp16).
// ---------------------------------------------------------------------------
#define GTB 8192
#define GBUF 24576

__device__ __forceinline__ void gemm_issue(
    uint32_t sb, int buf, int c, int tid,
    const __half* A, const __half* Wh, const __half* Wl,
    int m0, int n0, int remapA)
{
    const int k0 = c * 32;
    const uint32_t base = sb + buf * GBUF;
#pragma unroll
    for (int p = 0; p < 2; p++) {
        int ch = tid + p * 256;
        int r = ch >> 2, s = ch & 3;
        uint32_t d = base + (uint32_t)(r * 64 + ((s ^ GSWZ(r)) << 4));
        int arow = m0 + r;
        if (remapA) arow += (arow >> 10) << 10;
        size_t ga = (size_t)arow * 1024 + k0 + s * 8;
        size_t gw = (size_t)(n0 + r) * 1024 + k0 + s * 8;
        CP_ASYNC(d,         A  + ga);
        CP_ASYNC(d + GTB,   Wh + gw);
        CP_ASYNC(d + 2*GTB, Wl + gw);
    }
}

__device__ __forceinline__ void gemm_body(
    const __half* A, const __half* Wh, const __half* Wl,
    const float* bias, float* C,
    void* o1h, void* o1l, void* o2h,
    const float* addu, const float* addv,
    int mode, int remapA, int m0, int n0, __half* sm)
{
    const int tid = threadIdx.x, w = tid >> 5, lane = tid & 31;
    const int wm = (w & 1) * 64, wn = (w >> 1) * 32;
    const uint32_t sb = smem_u32(sm);
    const int lr = lane & 7, li = lane >> 3;

    float acc[4][4][4];
#pragma unroll
    for (int a = 0; a < 4; a++)
#pragma unroll
        for (int b = 0; b < 4; b++)
#pragma unroll
            for (int k = 0; k < 4; k++) acc[a][b][k] = 0.f;

    gemm_issue(sb, 0, 0, tid, A, Wh, Wl, m0, n0, remapA);
    CP_COMMIT();
    gemm_issue(sb, 1, 1, tid, A, Wh, Wl, m0, n0, remapA);
    CP_COMMIT();

    int bnext = 2, bcur = 0;
    for (int c = 0; c < 32; c++) {
        __syncthreads();
        if (c + 2 < 32) {
            gemm_issue(sb, bnext, c + 2, tid, A, Wh, Wl, m0, n0, remapA);
            CP_COMMIT();
            CP_WAIT2();
        } else if (c + 1 < 32) {
            CP_WAIT1();
        } else {
            CP_WAIT0();
        }
        __syncthreads();

        const uint32_t bb = sb + bcur * GBUF;
#pragma unroll
        for (int ks = 0; ks < 2; ks++) {
            const int sA = ks * 2 + (li >> 1);
            const int sB = ks * 2 + (li & 1);
            uint32_t ahf[4][4];
            const int arow0 = wm + (li & 1) * 8 + lr;
#pragma unroll
            for (int mt = 0; mt < 4; mt++) {
                int rowA = arow0 + mt * 16;
                uint32_t ao = bb + (uint32_t)(rowA * 64 + ((sA ^ GSWZ(rowA)) << 4));
                ldsm4(ahf[mt], ao);
            }
            uint32_t whf[2][4], wlf[2][4];
            const int brow0 = wn + (li >> 1) * 8 + lr;
#pragma unroll
            for (int nb = 0; nb < 2; nb++) {
                int rowB = brow0 + nb * 16;
                uint32_t bo = bb + GTB + (uint32_t)(rowB * 64 + ((sB ^ GSWZ(rowB)) << 4));
                ldsm4(whf[nb], bo);
                ldsm4(wlf[nb], bo + GTB);
            }
#pragma unroll
            for (int mt = 0; mt < 4; mt++)
#pragma unroll
                for (int nt = 0; nt < 4; nt++) {
                    const uint32_t* wh = &whf[nt >> 1][(nt & 1) * 2];
                    const uint32_t* wl = &wlf[nt >> 1][(nt & 1) * 2];
                    mma16816h(acc[mt][nt], ahf[mt], wh);
                    mma16816h(acc[mt][nt], ahf[mt], wl);
                }
        }
        bcur = (bcur == 2) ? 0 : bcur + 1;
        bnext = (bnext == 2) ? 0 : bnext + 1;
    }

#pragma unroll
    for (int mt = 0; mt < 4; mt++) {
        int m = m0 + wm + mt * 16 + (lane >> 2);
#pragma unroll
        for (int half = 0; half < 2; half++) {
            size_t mrow = (size_t)(m + half * 8);
#pragma unroll
            for (int nt = 0; nt < 4; nt++) {
                int col = wn + nt * 8 + (lane & 3) * 2;
                int cg = n0 + col;
                float x = acc[mt][nt][half*2+0] + bias[cg];
                float y = acc[mt][nt][half*2+1] + bias[cg+1];
                size_t d = (mrow * 1024 + cg) >> 1;
                if (mode == 0) {
                    *(float2*)(C + mrow * 1024 + cg) = make_float2(x, y);
                } else if (mode == 1) {
                    __half2 h, l;
                    split2h(x, y, h, l);
                    ((__half2*)o1h)[d] = h; ((__half2*)o1l)[d] = l;
                } else {
                    ((__half2*)o1h)[d] = __halves2half2(
                        __float2half_rn(x + addu[cg]), __float2half_rn(y + addu[cg+1]));
                    ((__half2*)o2h)[d] = __halves2half2(
                        __float2half_rn(x + addv[cg]), __float2half_rn(y + addv[cg+1]));
                }
            }
        }
    }
}

// Fused Q/K/V/R projection launch: flat blockIdx.x in [0, 1408)
__global__ void __launch_bounds__(256, 2) hm_proj_fused(
    const float* __restrict__ bq, const float* __restrict__ bk,
    const float* __restrict__ bv, const float* __restrict__ br,
    const float* __restrict__ u,  const float* __restrict__ v)
{
    extern __shared__ __half sm[];
    const size_t WSZ = (size_t)1024 * 1024;
    const int bid = blockIdx.x;

    if (bid < 512) {                        // K projection: M=8192
        int l = bid;
        gemm_body(g_KV, g_Wh + 1*WSZ, g_Wl + 1*WSZ, bk, nullptr,
                  g_Kh, g_Kl, nullptr, nullptr, nullptr,
                  1, 0, (l >> 3) * 128, (l & 7) * 128, sm);
    } else if (bid < 1024) {                // V projection: M=8192
        int l = bid - 512;
        gemm_body(g_KV, g_Wh + 2*WSZ, g_Wl + 2*WSZ, bv, nullptr,
                  g_Vh, g_Vl, nullptr, nullptr, nullptr,
                  1, 0, (l >> 3) * 128, (l & 7) * 128, sm);
    } else if (bid < 1280) {                // Q projection: M=4096, dual, remap
        int l = bid - 1024;
        gemm_body(g_KV, g_Wh + 0*WSZ, g_Wl + 0*WSZ, bq, nullptr,
                  g_QU, nullptr, g_QV, u, v,
                  2, 1, (l >> 3) * 128, (l & 7) * 128, sm);
    } else {                                // R projection: M=2048
        int l = bid - 1280;
        gemm_body(g_REL, g_Wh + 3*WSZ, g_Wl + 3*WSZ, br, nullptr,
                  g_Rh, g_Rl, nullptr, nullptr, nullptr,
                  1, 0, (l >> 3) * 128, (l & 7) * 128, sm);
    }
}

// O projection (depends on attnv output)
__global__ void __launch_bounds__(256, 2) hm_gemm_o(
    const float* __restrict__ bo, float* __restrict__ C)
{
    extern __shared__ __half sm[];
    const size_t WSZ = (size_t)1024 * 1024;
    gemm_body(g_O1, g_Wh + 4*WSZ, g_Wl + 4*WSZ, bo, C,
              nullptr, nullptr, nullptr, nullptr, nullptr,
              0, 0, blockIdx.y * 128, blockIdx.x * 128, sm);
}

// ---------------------------------------------------------------------------
// fp16 2-term batched scores -> fp16 planes. blockIdx.z in [0,128): mode=z>=64.
//   mode0 (AC): C[i,j] = (q+u)[i,b,n,:]·k[j,b,n,:]
//   mode1 (BD): C[i,l] = (q+v)[i,b,n,:]·kr[l,n,:]
// K=64 single shot. smem: 3 tiles x 128 rows x 144B = 55296 B
// ---------------------------------------------------------------------------
#define SLD 72
#define STB 18432

__global__ void __launch_bounds__(256, 2) hm_scores()
{
    extern __shared__ __half sm[];
    const int tid = threadIdx.x, w = tid >> 5, lane = tid & 31;
    const int zz = blockIdx.z;
    const int mode = zz >= 64;
    const int z = zz & 63, b = z >> 4, n = z & 15;
    const int j0 = blockIdx.x * 128, i0 = blockIdx.y * 128;
    const int wm = (w & 1) * 64, wn = (w >> 1) * 32;
    const uint32_t sb = smem_u32(sm);
    const int lr = lane & 7, li = lane >> 3;

    const __half* A  = mode ? g_QV : g_QU;
    const __half* Bh = mode ? g_Rh : g_Kh;
    const __half* Bl = mode ? g_Rl : g_Kl;
    __half* Out = mode ? g_BD : g_AC;

#pragma unroll
    for (int p = 0; p < 4; p++) {
        int ch = tid + p * 256;          // 0..1023
        int r = ch >> 3, s = ch & 7;
        uint32_t d = sb + (uint32_t)(r * SLD + s * 8) * 2;
        size_t ga = ((size_t)(i0 + r) * 4 + b) * 1024 + n * 64 + s * 8;
        size_t gb = mode ? ((size_t)(j0 + r) * 1024 + n * 64 + s * 8)
                         : (((size_t)(j0 + r) * 4 + b) * 1024 + n * 64 + s * 8);
        CP_ASYNC(d,           A  + ga);
        CP_ASYNC(d + STB,     Bh + gb);
        CP_ASYNC(d + 2*STB,   Bl + gb);
    }
    CP_COMMIT();
    CP_WAIT0();
    __syncthreads();

    float acc[4][4][4];
#pragma unroll
    for (int a = 0; a < 4; a++)
#pragma unroll
        for (int c = 0; c < 4; c++)
#pragma unroll
            for (int k = 0; k < 4; k++) acc[a][c][k] = 0.f;

#pragma unroll
    for (int ks = 0; ks < 4; ks++) {
        uint32_t ahf[4][4];
        const uint32_t acol = (uint32_t)(ks * 16 + (li >> 1) * 8) * 2;
        const uint32_t arow0 = (uint32_t)(wm + (li & 1) * 8 + lr);
#pragma unroll
        for (int mt = 0; mt < 4; mt++) {
            uint32_t ao = sb + (arow0 + mt * 16) * (SLD * 2) + acol;
            ldsm4(ahf[mt], ao);
        }
        uint32_t bhf[2][4], blf[2][4];
        const uint32_t bcol = (uint32_t)(ks * 16 + (li & 1) * 8) * 2;
        const uint32_t brow0 = (uint32_t)(wn + (li >> 1) * 8 + lr);
#pragma unroll
        for (int nb = 0; nb < 2; nb++) {
            uint32_t bo = sb + STB + (brow0 + nb * 16) * (SLD * 2) + bcol;
            ldsm4(bhf[nb], bo);
            ldsm4(blf[nb], bo + STB);
        }
#pragma unroll
        for (int mt = 0; mt < 4; mt++)
#pragma unroll
            for (int nt = 0; nt < 4; nt++) {
                const uint32_t* bh = &bhf[nt >> 1][(nt & 1) * 2];
                const uint32_t* bl = &blf[nt >> 1][(nt & 1) * 2];
                mma16816h(acc[mt][nt], ahf[mt], bh);
                mma16816h(acc[mt][nt], ahf[mt], bl);
            }
    }

    const size_t obase = (size_t)z * PLANE;
#pragma unroll
    for (int mt = 0; mt < 4; mt++) {
        int row = i0 + wm + mt * 16 + (lane >> 2);
        __half* r0 = Out + obase + (size_t)row * 2048 + j0 + wn;
        __half* r8 = r0 + (size_t)8 * 2048;
#pragma unroll
        for (int nt = 0; nt < 4; nt++) {
            int col = nt * 8 + (lane & 3) * 2;
            *(__half2*)(r0 + col) = __halves2half2(
                __float2half_rn(acc[mt][nt][0]), __float2half_rn(acc[mt][nt][1]));
            *(__half2*)(r8 + col) = __halves2half2(
                __float2half_rn(acc[mt][nt][2]), __float2half_rn(acc[mt][nt][3]));
        }
    }
}

// ---------------------------------------------------------------------------
// Softmax over the 16-head axis, parallelized: 4 lanes x 4 heads each,
// butterfly shfl reductions. Each thread: 4 j (one uint2) x 4 n.
// grid (8, 1024, 4) x 256 threads. Lane layout: j4 = lane>>2, nq = lane&3.
// ---------------------------------------------------------------------------
__global__ void softmax_heads(const float* __restrict__ amask)
{
    const int tid = threadIdx.x;
    const int w = tid >> 5, lane = tid & 31;
    const int j4 = blockIdx.x * 64 + w * 8 + (lane >> 2);   // 0..511
    const int j  = j4 * 4;
    const int nq = lane & 3;                                // heads nq*4..nq*4+3
    const int i  = blockIdx.y;
    const int b  = blockIdx.z;
    const int ioff = 1023 - i;
    const float* amrow = amask + (size_t)(i >> 8) * 1024;
    const size_t base = ((size_t)b * 16 * 1024 + i) * 2048;

    float s[4][4];
    float mx[4] = {-1e30f, -1e30f, -1e30f, -1e30f};
#pragma unroll
    for (int nn = 0; nn < 4; nn++) {
        const int n = nq * 4 + nn;
        const __half* ACn = g_AC + base + (size_t)n * PLANE;
        uint2 raw = *(const uint2*)(ACn + j);
        __half2 a01 = *(__half2*)&raw.x;
        __half2 a23 = *(__half2*)&raw.y;
        float a[4] = { __low2float(a01), __high2float(a01),
                       __low2float(a23), __high2float(a23) };
        const __half* BDn = g_BD + base + (size_t)n * PLANE;
#pragma unroll
        for (int e = 0; e < 4; e++) {
            int l = j + e + ioff;
            float bd = (l < 2048) ? __half2float(BDn[l]) : 0.f;
            float val = (a[e] + bd) * 0.125f;
            int jp = ((j + e) * 64 + b * 16 + n) & 2047;
            float m = (jp < 1024) ? 1.f : amrow[jp - 1024];
            val -= (1.f - m) * 1e9f;
            s[nn][e] = val;
            mx[e] = fmaxf(mx[e], val);
        }
    }
    // reduce max over the 4-lane head group (lanes sharing j4)
#pragma unroll
    for (int e = 0; e < 4; e++) {
        mx[e] = fmaxf(mx[e], __shfl_xor_sync(0xFFFFFFFFu, mx[e], 1));
        mx[e] = fmaxf(mx[e], __shfl_xor_sync(0xFFFFFFFFu, mx[e], 2));
    }
    float sum[4] = {0.f, 0.f, 0.f, 0.f};
#pragma unroll
    for (int nn = 0; nn < 4; nn++)
#pragma unroll
        for (int e = 0; e < 4; e++) {
            s[nn][e] = __expf(s[nn][e] - mx[e]);
            sum[e] += s[nn][e];
        }
#pragma unroll
    for (int e = 0; e < 4; e++) {
        sum[e] += __shfl_xor_sync(0xFFFFFFFFu, sum[e], 1);
        sum[e] += __shfl_xor_sync(0xFFFFFFFFu, sum[e], 2);
    }
    float inv[4] = {1.f/sum[0], 1.f/sum[1], 1.f/sum[2], 1.f/sum[3]};
#pragma unroll
    for (int nn = 0; nn < 4; nn++) {
        const int n = nq * 4 + nn;
        __half2 p0 = __halves2half2(__float2half_rn(s[nn][0] * inv[0]),
                                    __float2half_rn(s[nn][1] * inv[1]));
        __half2 p1 = __halves2half2(__float2half_rn(s[nn][2] * inv[2]),
                                    __float2half_rn(s[nn][3] * inv[3]));
        size_t el = base + (size_t)n * PLANE + j;
        *(uint2*)(g_ATT + el) = make_uint2(*(const uint32_t*)&p0,
                                           *(const uint32_t*)&p1);
    }
}

// ---------------------------------------------------------------------------
// HMMA attn@V, fp16 2-term: A·Vh + A·Vl. Writes O1 single fp16.
// 3-stage pipeline. buf: ATT 18432 + Vh/l 2x9216 = 36864; x3 = 110592 B
// ---------------------------------------------------------------------------
#define VTB 9216
#define ABUF 36864

__device__ __forceinline__ void attnv_issue(
    uint32_t sb, int buf, int c, int tid, int i0, int b, int n, size_t zbase)
{
    const uint32_t base = sb + buf * ABUF;
#pragma unroll
    for (int p = 0; p < 4; p++) {
        int ch = tid + p * 256;          // 0..1023
        int r = ch >> 3, s = ch & 7;
        uint32_t d = base + (uint32_t)(r * SLD + s * 8) * 2;
        size_t g = zbase + (size_t)(i0 + r) * 2048 + c * 64 + s * 8;
        CP_ASYNC(d, g_ATT + g);
    }
#pragma unroll
    for (int p = 0; p < 2; p++) {
        int ch = tid + p * 256;          // 0..511
        int r = ch >> 3, s = ch & 7;
        uint32_t d = base + STB + (uint32_t)(r * SLD + s * 8) * 2;
        size_t g = ((size_t)(c * 64 + r) * 4 + b) * 1024 + n * 64 + s * 8;
        CP_ASYNC(d,       g_Vh + g);
        CP_ASYNC(d + VTB, g_Vl + g);
    }
}

__global__ void __launch_bounds__(256, 2) hm_attnv()
{
    extern __shared__ __half sm[];
    const int tid = threadIdx.x, w = tid >> 5, lane = tid & 31;
    const int z = blockIdx.y, b = z >> 4, n = z & 15;
    const int i0 = blockIdx.x * 128;
    const int wm = (w & 3) * 32, wn = (w >> 2) * 32;
    const size_t zbase = (size_t)z * PLANE;
    const uint32_t sb = smem_u32(sm);
    const int lr = lane & 7, li = lane >> 3;

    float acc[2][4][4];
#pragma unroll
    for (int a = 0; a < 2; a++)
#pragma unroll
        for (int c = 0; c < 4; c++)
#pragma unroll
            for (int k = 0; k < 4; k++) acc[a][c][k] = 0.f;

    attnv_issue(sb, 0, 0, tid, i0, b, n, zbase);
    CP_COMMIT();
    attnv_issue(sb, 1, 1, tid, i0, b, n, zbase);
    CP_COMMIT();

    int bcur = 0, bnext = 2;
    for (int c = 0; c < 32; c++) {
        __syncthreads();
        if (c + 2 < 32) {
            attnv_issue(sb, bnext, c + 2, tid, i0, b, n, zbase);
            CP_COMMIT();
            CP_WAIT2();
        } else if (c + 1 < 32) {
            CP_WAIT1();
        } else {
            CP_WAIT0();
        }
        __syncthreads();

        const uint32_t bb = sb + bcur * ABUF;
#pragma unroll
        for (int ks = 0; ks < 4; ks++) {
            uint32_t ahf[2][4];
            const uint32_t acol = (uint32_t)(ks * 16 + (li >> 1) * 8) * 2;
            const uint32_t arow0 = (uint32_t)(wm + (li & 1) * 8 + lr);
#pragma unroll
            for (int mt = 0; mt < 2; mt++) {
                uint32_t ao = bb + (arow0 + mt * 16) * (SLD * 2) + acol;
                ldsm4(ahf[mt], ao);
            }
            uint32_t bhf[2][4], blf[2][4];
            const uint32_t vrow0 = (uint32_t)(ks * 16 + (li & 1) * 8 + lr);
#pragma unroll
            for (int nb = 0; nb < 2; nb++) {
                uint32_t vcol = (uint32_t)(wn + nb * 16 + (li >> 1) * 8) * 2;
                uint32_t bo = bb + STB + vrow0 * (SLD * 2) + vcol;
                ldsm4t(bhf[nb], bo);
                ldsm4t(blf[nb], bo + VTB);
            }
#pragma unroll
            for (int mt = 0; mt < 2; mt++)
#pragma unroll
                for (int nt = 0; nt < 4; nt++) {
                    const uint32_t* bh = &bhf[nt >> 1][(nt & 1) * 2];
                    const uint32_t* bl = &blf[nt >> 1][(nt & 1) * 2];
                    mma16816h(acc[mt][nt], ahf[mt], bh);
                    mma16816h(acc[mt][nt], ahf[mt], bl);
                }
        }
        bcur = (bcur == 2) ? 0 : bcur + 1;
        bnext = (bnext == 2) ? 0 : bnext + 1;
    }

#pragma unroll
    for (int mt = 0; mt < 2; mt++) {
        int i = i0 + wm + mt * 16 + (lane >> 2);
#pragma unroll
        for (int half = 0; half < 2; half++) {
            size_t rbase = ((size_t)(i + half * 8) * 4 + b) * 1024 + n * 64;
#pragma unroll
            for (int nt = 0; nt < 4; nt++) {
                int col = wn + nt * 8 + (lane & 3) * 2;
                size_t d = (rbase + col) >> 1;
                ((__half2*)g_O1)[d] = __halves2half2(
                    __float2half_rn(acc[mt][nt][half*2+0]),
                    __float2half_rn(acc[mt][nt][half*2+1]));
            }
        }
    }
}

// ---------------------------------------------------------------------------
__global__ void write_mems(const float4* __restrict__ mems,
                           const float4* __restrict__ out,
                           float4* __restrict__ dst)
{
    int idx = blockIdx.x * blockDim.x + threadIdx.x;
    int row = idx >> 8, c = idx & 255;
    int b = row >> 11, pos = row & 2047;
    float4 v;
    if (pos < 1024) v = mems[idx];
    else            v = out[(((size_t)b * 1024) + (pos - 1024)) * 256 + c];
    dst[idx] = v;
}

// ---------------------------------------------------------------------------
extern "C" void kernel_launch(void* const* d_in, const int* in_sizes, int n_in,
                              void* d_out, int out_size)
{
    const float* TE    = (const float*)d_in[0];
    const float* REL   = (const float*)d_in[1];
    const float* MEMS  = (const float*)d_in[2];
    const float* AMASK = (const float*)d_in[3];
    const float* Wq = (const float*)d_in[4],  *bq = (const float*)d_in[5];
    const float* Wk = (const float*)d_in[6],  *bk = (const float*)d_in[7];
    const float* Wv = (const float*)d_in[8],  *bv = (const float*)d_in[9];
    const float* Wr = (const float*)d_in[10], *br = (const float*)d_in[11];
    const float* Wo = (const float*)d_in[12], *bo = (const float*)d_in[13];
    const float* u  = (const float*)d_in[14];
    const float* v  = (const float*)d_in[15];
    float* out = (float*)d_out;

    const int G_SMEM = 3 * GBUF;      // 73728
    const int S_SMEM = 3 * STB;       // 55296
    const int A_SMEM = 3 * ABUF;      // 110592
    cudaFuncSetAttribute(hm_proj_fused, cudaFuncAttributeMaxDynamicSharedMemorySize, G_SMEM);
    cudaFuncSetAttribute(hm_gemm_o,     cudaFuncAttributeMaxDynamicSharedMemorySize, G_SMEM);
    cudaFuncSetAttribute(hm_scores,     cudaFuncAttributeMaxDynamicSharedMemorySize, S_SMEM);
    cudaFuncSetAttribute(hm_attnv,      cudaFuncAttributeMaxDynamicSharedMemorySize, A_SMEM);

    __half *pREL, *pWh, *pWl;
    cudaGetSymbolAddress((void**)&pREL, g_REL);
    cudaGetSymbolAddress((void**)&pWh,  g_Wh);
    cudaGetSymbolAddress((void**)&pWl,  g_Wl);

    // 1. input conversions (fp16): KV gather, REL, weights hi/lo
    gather_kv_h<<<8192, 256>>>((const float4*)TE, (const float4*)MEMS);
    tohalf<<<2048, 256>>>((const float4*)REL, (__half2*)pREL, 524288);
    split5_w<<<dim3(1024, 5), 256>>>((const float4*)Wq, (const float4*)Wk, (const float4*)Wv,
                                     (const float4*)Wr, (const float4*)Wo,
                                     (__half2*)pWh, (__half2*)pWl);

    // 2. all four projections in ONE launch (wave-packed, 3-stage, fp16 2-term)
    hm_proj_fused<<<1408, 256, G_SMEM>>>(bq, bk, bv, br, u, v);

    // 3. score GEMMs (AC + BD in one launch, fp16 planes)
    hm_scores<<<dim3(16, 8, 128), 256, S_SMEM>>>();

    // 4. rel-shift + mask + softmax over heads -> ATT (fp16), head-parallel
    softmax_heads<<<dim3(8, 1024, 4), 256>>>(AMASK);

    // 5. attn @ V (fp16 2-term, 3-stage) -> O1 single fp16
    hm_attnv<<<dim3(8, 64), 256, A_SMEM>>>();

    // 6. O projection -> d_out (fp32)
    hm_gemm_o<<<dim3(8, 32), 256, G_SMEM>>>(bo, out);

    // 7. mems_new
    if (out_size >= 12582912)
        write_mems<<<8192, 256>>>((const float4*)MEMS, (const float4*)out,
                                  (float4*)(out + 4194304));
}

// round 16
// speedup vs baseline: 1.7908x; 1.0441x over previous
#include <cuda_runtime.h>
#include <cuda_fp16.h>
#include <stdint.h>
#include <math.h>

// ---------------------------------------------------------------------------
// Problem constants: B=4, S=1024, H=1024, HEADS=16, HEAD_D=64, K=2048
// ---------------------------------------------------------------------------
#define PLANE 2097152ull   // 1024*2048

// ---------------- scratch ----------------
__device__ __half g_AC [(size_t)64 * PLANE];                 // fp16 score planes
__device__ __half g_BD [(size_t)64 * PLANE];
__device__ __half g_ATT[(size_t)64 * PLANE];                 // attn, single fp16

__device__ __half g_KV [(size_t)8192*1024];                  // single fp16 (A-side)
__device__ __half g_REL[(size_t)2048*1024];                  // single fp16
__device__ __half g_Wh [(size_t)5*1024*1024], g_Wl [(size_t)5*1024*1024];
__device__ __half g_QU [(size_t)4096*1024];                  // single fp16
__device__ __half g_QV [(size_t)4096*1024];                  // single fp16
__device__ __half g_Kh [(size_t)8192*1024], g_Kl [(size_t)8192*1024];
__device__ __half g_Rh [(size_t)2048*1024], g_Rl [(size_t)2048*1024];
__device__ __half g_Vh [(size_t)8192*1024], g_Vl [(size_t)8192*1024];
__device__ __half g_O1 [(size_t)4096*1024];                  // single fp16

// ---------------------------------------------------------------------------
// Low-level helpers (sm_80-compatible: ldmatrix / mma.sync / cp.async)
// ---------------------------------------------------------------------------
__device__ __forceinline__ uint32_t smem_u32(const void* p) {
    uint32_t a;
    asm("{ .reg .u64 t; cvta.to.shared.u64 t, %1; cvt.u32.u64 %0, t; }"
        : "=r"(a) : "l"(p));
    return a;
}
__device__ __forceinline__ void ldsm4(uint32_t* r, uint32_t a) {
    asm volatile("ldmatrix.sync.aligned.m8n8.x4.shared.b16 {%0,%1,%2,%3}, [%4];"
        : "=r"(r[0]), "=r"(r[1]), "=r"(r[2]), "=r"(r[3]) : "r"(a));
}
__device__ __forceinline__ void ldsm4t(uint32_t* r, uint32_t a) {
    asm volatile("ldmatrix.sync.aligned.m8n8.x4.trans.shared.b16 {%0,%1,%2,%3}, [%4];"
        : "=r"(r[0]), "=r"(r[1]), "=r"(r[2]), "=r"(r[3]) : "r"(a));
}
__device__ __forceinline__ void mma16816h(float* c, const uint32_t* a, const uint32_t* b) {
    asm volatile(
        "mma.sync.aligned.m16n8k16.row.col.f32.f16.f16.f32 "
        "{%0,%1,%2,%3}, {%4,%5,%6,%7}, {%8,%9}, {%0,%1,%2,%3};"
        : "+f"(c[0]), "+f"(c[1]), "+f"(c[2]), "+f"(c[3])
        : "r"(a[0]), "r"(a[1]), "r"(a[2]), "r"(a[3]), "r"(b[0]), "r"(b[1]));
}
#define CP_ASYNC(dst, src) \
    asm volatile("cp.async.cg.shared.global [%0], [%1], 16;" :: "r"(dst), "l"(src))
#define CP_COMMIT() asm volatile("cp.async.commit_group;" ::: "memory")
#define CP_WAIT2()  asm volatile("cp.async.wait_group 2;" ::: "memory")
#define CP_WAIT1()  asm volatile("cp.async.wait_group 1;" ::: "memory")
#define CP_WAIT0()  asm volatile("cp.async.wait_group 0;" ::: "memory")

// GEMM tile swizzle: 64B rows (4 x 16B chunks), chunk permuted by row.
#define GSWZ(r) ((((r) ^ ((r) >> 2))) & 3)

__device__ __forceinline__ void split2h(float x, float y,
                                        __half2& h, __half2& l) {
    __half hx = __float2half_rn(x), hy = __float2half_rn(y);
    h = __halves2half2(hx, hy);
    l = __halves2half2(__float2half_rn(x - __half2float(hx)),
                       __float2half_rn(y - __half2float(hy)));
}

// ---------------------------------------------------------------------------
// fp32 -> single fp16 (generic)
// ---------------------------------------------------------------------------
__global__ void tohalf(const float4* __restrict__ in,
                       __half2* __restrict__ out, int n4)
{
    int i = blockIdx.x * blockDim.x + threadIdx.x;
    if (i >= n4) return;
    float4 x = in[i];
    out[i*2+0] = __halves2half2(__float2half_rn(x.x), __float2half_rn(x.y));
    out[i*2+1] = __halves2half2(__float2half_rn(x.z), __float2half_rn(x.w));
}

// split 5 weight matrices to fp16 hi/lo in one launch
__global__ void split5_w(const float4* w0, const float4* w1, const float4* w2,
                         const float4* w3, const float4* w4,
                         __half2* __restrict__ hi, __half2* __restrict__ lo)
{
    const float4* srcs[5] = {w0, w1, w2, w3, w4};
    int which = blockIdx.y;
    int i = blockIdx.x * blockDim.x + threadIdx.x;      // 0..262143
    float4 x = srcs[which][i];
    size_t d = (size_t)which * 524288 + (size_t)i * 2;
    __half2 h0, l0, h1, l1;
    split2h(x.x, x.y, h0, l0);
    split2h(x.z, x.w, h1, l1);
    hi[d] = h0; hi[d+1] = h1;
    lo[d] = l0; lo[d+1] = l1;
}

// gather kv_in (natural flat order row = b*2048+j) -> single fp16
__global__ void gather_kv_h(const float4* __restrict__ te,
                            const float4* __restrict__ mems)
{
    int idx = blockIdx.x * blockDim.x + threadIdx.x;    // 8192*256
    int row = idx >> 8, c = idx & 255;
    int b = row >> 11, j = row & 2047;
    float4 x;
    if (j < 1024) x = te  [((size_t)b * 1024 + j) * 256 + c];
    else          x = mems[((size_t)b * 2048 + (j - 1024)) * 256 + c];
    ((__half2*)g_KV)[idx*2+0] = __halves2half2(__float2half_rn(x.x), __float2half_rn(x.y));
    ((__half2*)g_KV)[idx*2+1] = __halves2half2(__float2half_rn(x.z), __float2half_rn(x.w));
}

// ---------------------------------------------------------------------------
// fp16 2-term HMMA GEMM core, 3-stage cp.async pipeline, swizzled tiles.
// C = A @ (Wh+Wl)^T + bias; A single fp16, W fp16 hi/lo; 2 MMAs per k-step.
// 128x128 CTA tile, BK=32, 8 warps (64x32).
// Tile 8192 B; buf 3 tiles = 24576 B; 3 bufs = 73728 B -> 2 CTA/SM.
// Epilogue modes: 0 = fp32+bias -> C; 1 = bias, fp16 hi/lo -> (o1h,o1l);
//                 2 = bias+u -> o1h (fp16), bias+v -> o2h (fp16).
// ---------------------------------------------------------------------------
#define GTB 8192
#define GBUF 24576

__device__ __forceinline__ void gemm_issue(
    uint32_t sb, int buf, int c, int tid,
    const __half* A, const __half* Wh, const __half* Wl,
    int m0, int n0, int remapA)
{
    const int k0 = c * 32;
    const uint32_t base = sb + buf * GBUF;
#pragma unroll
    for (int p = 0; p < 2; p++) {
        int ch = tid + p * 256;
        int r = ch >> 2, s = ch & 3;
        uint32_t d = base + (uint32_t)(r * 64 + ((s ^ GSWZ(r)) << 4));
        int arow = m0 + r;
        if (remapA) arow += (arow >> 10) << 10;
        size_t ga = (size_t)arow * 1024 + k0 + s * 8;
        size_t gw = (size_t)(n0 + r) * 1024 + k0 + s * 8;
        CP_ASYNC(d,         A  + ga);
        CP_ASYNC(d + GTB,   Wh + gw);
        CP_ASYNC(d + 2*GTB, Wl + gw);
    }
}

__device__ __forceinline__ void gemm_body(
    const __half* A, const __half* Wh, const __half* Wl,
    const float* bias, float* C,
    void* o1h, void* o1l, void* o2h,
    const float* addu, const float* addv,
    int mode, int remapA, int m0, int n0, __half* sm)
{
    const int tid = threadIdx.x, w = tid >> 5, lane = tid & 31;
    const int wm = (w & 1) * 64, wn = (w >> 1) * 32;
    const uint32_t sb = smem_u32(sm);
    const int lr = lane & 7, li = lane >> 3;

    float acc[4][4][4];
#pragma unroll
    for (int a = 0; a < 4; a++)
#pragma unroll
        for (int b = 0; b < 4; b++)
#pragma unroll
            for (int k = 0; k < 4; k++) acc[a][b][k] = 0.f;

    gemm_issue(sb, 0, 0, tid, A, Wh, Wl, m0, n0, remapA);
    CP_COMMIT();
    gemm_issue(sb, 1, 1, tid, A, Wh, Wl, m0, n0, remapA);
    CP_COMMIT();

    int bnext = 2, bcur = 0;
    for (int c = 0; c < 32; c++) {
        __syncthreads();
        if (c + 2 < 32) {
            gemm_issue(sb, bnext, c + 2, tid, A, Wh, Wl, m0, n0, remapA);
            CP_COMMIT();
            CP_WAIT2();
        } else if (c + 1 < 32) {
            CP_WAIT1();
        } else {
            CP_WAIT0();
        }
        __syncthreads();

        const uint32_t bb = sb + bcur * GBUF;
#pragma unroll
        for (int ks = 0; ks < 2; ks++) {
            const int sA = ks * 2 + (li >> 1);
            const int sB = ks * 2 + (li & 1);
            uint32_t ahf[4][4];
            const int arow0 = wm + (li & 1) * 8 + lr;
#pragma unroll
            for (int mt = 0; mt < 4; mt++) {
                int rowA = arow0 + mt * 16;
                uint32_t ao = bb + (uint32_t)(rowA * 64 + ((sA ^ GSWZ(rowA)) << 4));
                ldsm4(ahf[mt], ao);
            }
            uint32_t whf[2][4], wlf[2][4];
            const int brow0 = wn + (li >> 1) * 8 + lr;
#pragma unroll
            for (int nb = 0; nb < 2; nb++) {
                int rowB = brow0 + nb * 16;
                uint32_t bo = bb + GTB + (uint32_t)(rowB * 64 + ((sB ^ GSWZ(rowB)) << 4));
                ldsm4(whf[nb], bo);
                ldsm4(wlf[nb], bo + GTB);
            }
#pragma unroll
            for (int mt = 0; mt < 4; mt++)
#pragma unroll
                for (int nt = 0; nt < 4; nt++) {
                    const uint32_t* wh = &whf[nt >> 1][(nt & 1) * 2];
                    const uint32_t* wl = &wlf[nt >> 1][(nt & 1) * 2];
                    mma16816h(acc[mt][nt], ahf[mt], wh);
                    mma16816h(acc[mt][nt], ahf[mt], wl);
                }
        }
        bcur = (bcur == 2) ? 0 : bcur + 1;
        bnext = (bnext == 2) ? 0 : bnext + 1;
    }

#pragma unroll
    for (int mt = 0; mt < 4; mt++) {
        int m = m0 + wm + mt * 16 + (lane >> 2);
#pragma unroll
        for (int half = 0; half < 2; half++) {
            size_t mrow = (size_t)(m + half * 8);
#pragma unroll
            for (int nt = 0; nt < 4; nt++) {
                int col = wn + nt * 8 + (lane & 3) * 2;
                int cg = n0 + col;
                float x = acc[mt][nt][half*2+0] + bias[cg];
                float y = acc[mt][nt][half*2+1] + bias[cg+1];
                size_t d = (mrow * 1024 + cg) >> 1;
                if (mode == 0) {
                    *(float2*)(C + mrow * 1024 + cg) = make_float2(x, y);
                } else if (mode == 1) {
                    __half2 h, l;
                    split2h(x, y, h, l);
                    ((__half2*)o1h)[d] = h; ((__half2*)o1l)[d] = l;
                } else {
                    ((__half2*)o1h)[d] = __halves2half2(
                        __float2half_rn(x + addu[cg]), __float2half_rn(y + addu[cg+1]));
                    ((__half2*)o2h)[d] = __halves2half2(
                        __float2half_rn(x + addv[cg]), __float2half_rn(y + addv[cg+1]));
                }
            }
        }
    }
}

// Fused Q/K/V/R projection launch: flat blockIdx.x in [0, 1408)
__global__ void __launch_bounds__(256, 2) hm_proj_fused(
    const float* __restrict__ bq, const float* __restrict__ bk,
    const float* __restrict__ bv, const float* __restrict__ br,
    const float* __restrict__ u,  const float* __restrict__ v)
{
    extern __shared__ __half sm[];
    const size_t WSZ = (size_t)1024 * 1024;
    const int bid = blockIdx.x;

    if (bid < 512) {                        // K projection: M=8192
        int l = bid;
        gemm_body(g_KV, g_Wh + 1*WSZ, g_Wl + 1*WSZ, bk, nullptr,
                  g_Kh, g_Kl, nullptr, nullptr, nullptr,
                  1, 0, (l >> 3) * 128, (l & 7) * 128, sm);
    } else if (bid < 1024) {                // V projection: M=8192
        int l = bid - 512;
        gemm_body(g_KV, g_Wh + 2*WSZ, g_Wl + 2*WSZ, bv, nullptr,
                  g_Vh, g_Vl, nullptr, nullptr, nullptr,
                  1, 0, (l >> 3) * 128, (l & 7) * 128, sm);
    } else if (bid < 1280) {                // Q projection: M=4096, dual, remap
        int l = bid - 1024;
        gemm_body(g_KV, g_Wh + 0*WSZ, g_Wl + 0*WSZ, bq, nullptr,
                  g_QU, nullptr, g_QV, u, v,
                  2, 1, (l >> 3) * 128, (l & 7) * 128, sm);
    } else {                                // R projection: M=2048
        int l = bid - 1280;
        gemm_body(g_REL, g_Wh + 3*WSZ, g_Wl + 3*WSZ, br, nullptr,
                  g_Rh, g_Rl, nullptr, nullptr, nullptr,
                  1, 0, (l >> 3) * 128, (l & 7) * 128, sm);
    }
}

// O projection (depends on attnv output)
__global__ void __launch_bounds__(256, 2) hm_gemm_o(
    const float* __restrict__ bo, float* __restrict__ C)
{
    extern __shared__ __half sm[];
    const size_t WSZ = (size_t)1024 * 1024;
    gemm_body(g_O1, g_Wh + 4*WSZ, g_Wl + 4*WSZ, bo, C,
              nullptr, nullptr, nullptr, nullptr, nullptr,
              0, 0, blockIdx.y * 128, blockIdx.x * 128, sm);
}

// ---------------------------------------------------------------------------
// j-sweep scores kernel: one CTA = (zz, i-tile), sweeps 16 j-tiles with a
// 2-deep B pipeline; A tile resident. zz in [0,128): mode = zz>=64.
//   mode0 (AC): C[i,j] = (q+u)[i,b,n,:]·k[j,b,n,:]
//   mode1 (BD): C[i,l] = (q+v)[i,b,n,:]·kr[l,n,:]; tiles with
//               i0/128 + jc < 7 are never read by the rel-shift -> skipped.
// smem: A 18432 + 2 bufs x (Bh+Bl 36864) = 92160 B -> 2 CTA/SM.
// ---------------------------------------------------------------------------
#define SLD 72
#define STB 18432

__device__ __forceinline__ void sc_issue_B(
    uint32_t sb, int buf, int jc, int tid,
    const __half* Bh, const __half* Bl, int mode, int b, int n)
{
    const int j0 = jc * 128;
    const uint32_t base = sb + STB + buf * 2 * STB;
#pragma unroll
    for (int p = 0; p < 4; p++) {
        int ch = tid + p * 256;          // 0..1023
        int r = ch >> 3, s = ch & 7;
        uint32_t d = base + (uint32_t)(r * SLD + s * 8) * 2;
        size_t gb = mode ? ((size_t)(j0 + r) * 1024 + n * 64 + s * 8)
                         : (((size_t)(j0 + r) * 4 + b) * 1024 + n * 64 + s * 8);
        CP_ASYNC(d,       Bh + gb);
        CP_ASYNC(d + STB, Bl + gb);
    }
}

__global__ void __launch_bounds__(256, 2) hm_scores_sweep()
{
    extern __shared__ __half sm[];
    const int tid = threadIdx.x, w = tid >> 5, lane = tid & 31;
    const int bid = blockIdx.x;                 // 0..1023
    const int zz = bid >> 3;
    const int mode = zz >= 64;
    const int z = zz & 63, b = z >> 4, n = z & 15;
    const int i0 = (bid & 7) * 128;
    const int wm = (w & 1) * 64, wn = (w >> 1) * 32;
    const uint32_t sb = smem_u32(sm);
    const int lr = lane & 7, li = lane >> 3;

    const __half* A  = mode ? g_QV : g_QU;
    const __half* Bh = mode ? g_Rh : g_Kh;
    const __half* Bl = mode ? g_Rl : g_Kl;
    __half* Out = mode ? g_BD : g_AC;

    const int jc0 = mode ? max(0, 7 - (i0 >> 7)) : 0;

    // load A tile (resident) + first B chunk in group 0
#pragma unroll
    for (int p = 0; p < 4; p++) {
        int ch = tid + p * 256;
        int r = ch >> 3, s = ch & 7;
        uint32_t d = sb + (uint32_t)(r * SLD + s * 8) * 2;
        size_t ga = ((size_t)(i0 + r) * 4 + b) * 1024 + n * 64 + s * 8;
        CP_ASYNC(d, A + ga);
    }
    sc_issue_B(sb, 0, jc0, tid, Bh, Bl, mode, b, n);
    CP_COMMIT();

    const size_t obase = (size_t)z * PLANE;
    for (int jc = jc0; jc < 16; jc++) {
        const int buf = (jc - jc0) & 1;
        if (jc + 1 < 16) {
            sc_issue_B(sb, buf ^ 1, jc + 1, tid, Bh, Bl, mode, b, n);
            CP_COMMIT();
            CP_WAIT1();
        } else {
            CP_WAIT0();
        }
        __syncthreads();

        float acc[4][4][4];
#pragma unroll
        for (int a = 0; a < 4; a++)
#pragma unroll
            for (int c = 0; c < 4; c++)
#pragma unroll
                for (int k = 0; k < 4; k++) acc[a][c][k] = 0.f;

        const uint32_t bB = sb + STB + buf * 2 * STB;
#pragma unroll
        for (int ks = 0; ks < 4; ks++) {
            uint32_t ahf[4][4];
            const uint32_t acol = (uint32_t)(ks * 16 + (li >> 1) * 8) * 2;
            const uint32_t arow0 = (uint32_t)(wm + (li & 1) * 8 + lr);
#pragma unroll
            for (int mt = 0; mt < 4; mt++) {
                uint32_t ao = sb + (arow0 + mt * 16) * (SLD * 2) + acol;
                ldsm4(ahf[mt], ao);
            }
            uint32_t bhf[2][4], blf[2][4];
            const uint32_t bcol = (uint32_t)(ks * 16 + (li & 1) * 8) * 2;
            const uint32_t brow0 = (uint32_t)(wn + (li >> 1) * 8 + lr);
#pragma unroll
            for (int nb = 0; nb < 2; nb++) {
                uint32_t bo = bB + (brow0 + nb * 16) * (SLD * 2) + bcol;
                ldsm4(bhf[nb], bo);
                ldsm4(blf[nb], bo + STB);
            }
#pragma unroll
            for (int mt = 0; mt < 4; mt++)
#pragma unroll
                for (int nt = 0; nt < 4; nt++) {
                    const uint32_t* bh = &bhf[nt >> 1][(nt & 1) * 2];
                    const uint32_t* bl = &blf[nt >> 1][(nt & 1) * 2];
                    mma16816h(acc[mt][nt], ahf[mt], bh);
                    mma16816h(acc[mt][nt], ahf[mt], bl);
                }
        }

        const int j0 = jc * 128;
#pragma unroll
        for (int mt = 0; mt < 4; mt++) {
            int row = i0 + wm + mt * 16 + (lane >> 2);
            __half* r0 = Out + obase + (size_t)row * 2048 + j0 + wn;
            __half* r8 = r0 + (size_t)8 * 2048;
#pragma unroll
            for (int nt = 0; nt < 4; nt++) {
                int col = nt * 8 + (lane & 3) * 2;
                *(__half2*)(r0 + col) = __halves2half2(
                    __float2half_rn(acc[mt][nt][0]), __float2half_rn(acc[mt][nt][1]));
                *(__half2*)(r8 + col) = __halves2half2(
                    __float2half_rn(acc[mt][nt][2]), __float2half_rn(acc[mt][nt][3]));
            }
        }
        __syncthreads();
    }
}

// ---------------------------------------------------------------------------
// Softmax over the 16-head axis, parallelized: 4 lanes x 4 heads each,
// butterfly shfl reductions. Each thread: 4 j (one uint2) x 4 n.
// ---------------------------------------------------------------------------
__global__ void softmax_heads(const float* __restrict__ amask)
{
    const int tid = threadIdx.x;
    const int w = tid >> 5, lane = tid & 31;
    const int j4 = blockIdx.x * 64 + w * 8 + (lane >> 2);   // 0..511
    const int j  = j4 * 4;
    const int nq = lane & 3;                                // heads nq*4..nq*4+3
    const int i  = blockIdx.y;
    const int b  = blockIdx.z;
    const int ioff = 1023 - i;
    const float* amrow = amask + (size_t)(i >> 8) * 1024;
    const size_t base = ((size_t)b * 16 * 1024 + i) * 2048;

    float s[4][4];
    float mx[4] = {-1e30f, -1e30f, -1e30f, -1e30f};
#pragma unroll
    for (int nn = 0; nn < 4; nn++) {
        const int n = nq * 4 + nn;
        const __half* ACn = g_AC + base + (size_t)n * PLANE;
        uint2 raw = *(const uint2*)(ACn + j);
        __half2 a01 = *(__half2*)&raw.x;
        __half2 a23 = *(__half2*)&raw.y;
        float a[4] = { __low2float(a01), __high2float(a01),
                       __low2float(a23), __high2float(a23) };
        const __half* BDn = g_BD + base + (size_t)n * PLANE;
#pragma unroll
        for (int e = 0; e < 4; e++) {
            int l = j + e + ioff;
            float bd = (l < 2048) ? __half2float(BDn[l]) : 0.f;
            float val = (a[e] + bd) * 0.125f;
            int jp = ((j + e) * 64 + b * 16 + n) & 2047;
            float m = (jp < 1024) ? 1.f : amrow[jp - 1024];
            val -= (1.f - m) * 1e9f;
            s[nn][e] = val;
            mx[e] = fmaxf(mx[e], val);
        }
    }
#pragma unroll
    for (int e = 0; e < 4; e++) {
        mx[e] = fmaxf(mx[e], __shfl_xor_sync(0xFFFFFFFFu, mx[e], 1));
        mx[e] = fmaxf(mx[e], __shfl_xor_sync(0xFFFFFFFFu, mx[e], 2));
    }
    float sum[4] = {0.f, 0.f, 0.f, 0.f};
#pragma unroll
    for (int nn = 0; nn < 4; nn++)
#pragma unroll
        for (int e = 0; e < 4; e++) {
            s[nn][e] = __expf(s[nn][e] - mx[e]);
            sum[e] += s[nn][e];
        }
#pragma unroll
    for (int e = 0; e < 4; e++) {
        sum[e] += __shfl_xor_sync(0xFFFFFFFFu, sum[e], 1);
        sum[e] += __shfl_xor_sync(0xFFFFFFFFu, sum[e], 2);
    }
    float inv[4] = {1.f/sum[0], 1.f/sum[1], 1.f/sum[2], 1.f/sum[3]};
#pragma unroll
    for (int nn = 0; nn < 4; nn++) {
        const int n = nq * 4 + nn;
        __half2 p0 = __halves2half2(__float2half_rn(s[nn][0] * inv[0]),
                                    __float2half_rn(s[nn][1] * inv[1]));
        __half2 p1 = __halves2half2(__float2half_rn(s[nn][2] * inv[2]),
                                    __float2half_rn(s[nn][3] * inv[3]));
        size_t el = base + (size_t)n * PLANE + j;
        *(uint2*)(g_ATT + el) = make_uint2(*(const uint32_t*)&p0,
                                           *(const uint32_t*)&p1);
    }
}

// ---------------------------------------------------------------------------
// HMMA attn@V, fp16 2-term: A·Vh + A·Vl. Writes O1 single fp16.
// 3-stage pipeline. buf: ATT 18432 + Vh/l 2x9216 = 36864; x3 = 110592 B
// ---------------------------------------------------------------------------
#define VTB 9216
#define ABUF 36864

__device__ __forceinline__ void attnv_issue(
    uint32_t sb, int buf, int c, int tid, int i0, int b, int n, size_t zbase)
{
    const uint32_t base = sb + buf * ABUF;
#pragma unroll
    for (int p = 0; p < 4; p++) {
        int ch = tid + p * 256;          // 0..1023
        int r = ch >> 3, s = ch & 7;
        uint32_t d = base + (uint32_t)(r * SLD + s * 8) * 2;
        size_t g = zbase + (size_t)(i0 + r) * 2048 + c * 64 + s * 8;
        CP_ASYNC(d, g_ATT + g);
    }
#pragma unroll
    for (int p = 0; p < 2; p++) {
        int ch = tid + p * 256;          // 0..511
        int r = ch >> 3, s = ch & 7;
        uint32_t d = base + STB + (uint32_t)(r * SLD + s * 8) * 2;
        size_t g = ((size_t)(c * 64 + r) * 4 + b) * 1024 + n * 64 + s * 8;
        CP_ASYNC(d,       g_Vh + g);
        CP_ASYNC(d + VTB, g_Vl + g);
    }
}

__global__ void __launch_bounds__(256, 2) hm_attnv()
{
    extern __shared__ __half sm[];
    const int tid = threadIdx.x, w = tid >> 5, lane = tid & 31;
    const int z = blockIdx.y, b = z >> 4, n = z & 15;
    const int i0 = blockIdx.x * 128;
    const int wm = (w & 3) * 32, wn = (w >> 2) * 32;
    const size_t zbase = (size_t)z * PLANE;
    const uint32_t sb = smem_u32(sm);
    const int lr = lane & 7, li = lane >> 3;

    float acc[2][4][4];
#pragma unroll
    for (int a = 0; a < 2; a++)
#pragma unroll
        for (int c = 0; c < 4; c++)
#pragma unroll
            for (int k = 0; k < 4; k++) acc[a][c][k] = 0.f;

    attnv_issue(sb, 0, 0, tid, i0, b, n, zbase);
    CP_COMMIT();
    attnv_issue(sb, 1, 1, tid, i0, b, n, zbase);
    CP_COMMIT();

    int bcur = 0, bnext = 2;
    for (int c = 0; c < 32; c++) {
        __syncthreads();
        if (c + 2 < 32) {
            attnv_issue(sb, bnext, c + 2, tid, i0, b, n, zbase);
            CP_COMMIT();
            CP_WAIT2();
        } else if (c + 1 < 32) {
            CP_WAIT1();
        } else {
            CP_WAIT0();
        }
        __syncthreads();

        const uint32_t bb = sb + bcur * ABUF;
#pragma unroll
        for (int ks = 0; ks < 4; ks++) {
            uint32_t ahf[2][4];
            const uint32_t acol = (uint32_t)(ks * 16 + (li >> 1) * 8) * 2;
            const uint32_t arow0 = (uint32_t)(wm + (li & 1) * 8 + lr);
#pragma unroll
            for (int mt = 0; mt < 2; mt++) {
                uint32_t ao = bb + (arow0 + mt * 16) * (SLD * 2) + acol;
                ldsm4(ahf[mt], ao);
            }
            uint32_t bhf[2][4], blf[2][4];
            const uint32_t vrow0 = (uint32_t)(ks * 16 + (li & 1) * 8 + lr);
#pragma unroll
            for (int nb = 0; nb < 2; nb++) {
                uint32_t vcol = (uint32_t)(wn + nb * 16 + (li >> 1) * 8) * 2;
                uint32_t bo = bb + STB + vrow0 * (SLD * 2) + vcol;
                ldsm4t(bhf[nb], bo);
                ldsm4t(blf[nb], bo + VTB);
            }
#pragma unroll
            for (int mt = 0; mt < 2; mt++)
#pragma unroll
                for (int nt = 0; nt < 4; nt++) {
                    const uint32_t* bh = &bhf[nt >> 1][(nt & 1) * 2];
                    const uint32_t* bl = &blf[nt >> 1][(nt & 1) * 2];
                    mma16816h(acc[mt][nt], ahf[mt], bh);
                    mma16816h(acc[mt][nt], ahf[mt], bl);
                }
        }
        bcur = (bcur == 2) ? 0 : bcur + 1;
        bnext = (bnext == 2) ? 0 : bnext + 1;
    }

#pragma unroll
    for (int mt = 0; mt < 2; mt++) {
        int i = i0 + wm + mt * 16 + (lane >> 2);
#pragma unroll
        for (int half = 0; half < 2; half++) {
            size_t rbase = ((size_t)(i + half * 8) * 4 + b) * 1024 + n * 64;
#pragma unroll
            for (int nt = 0; nt < 4; nt++) {
                int col = wn + nt * 8 + (lane & 3) * 2;
                size_t d = (rbase + col) >> 1;
                ((__half2*)g_O1)[d] = __halves2half2(
                    __float2half_rn(acc[mt][nt][half*2+0]),
                    __float2half_rn(acc[mt][nt][half*2+1]));
            }
        }
    }
}

// ---------------------------------------------------------------------------
__global__ void write_mems(const float4* __restrict__ mems,
                           const float4* __restrict__ out,
                           float4* __restrict__ dst)
{
    int idx = blockIdx.x * blockDim.x + threadIdx.x;
    int row = idx >> 8, c = idx & 255;
    int b = row >> 11, pos = row & 2047;
    float4 v;
    if (pos < 1024) v = mems[idx];
    else            v = out[(((size_t)b * 1024) + (pos - 1024)) * 256 + c];
    dst[idx] = v;
}

// ---------------------------------------------------------------------------
extern "C" void kernel_launch(void* const* d_in, const int* in_sizes, int n_in,
                              void* d_out, int out_size)
{
    const float* TE    = (const float*)d_in[0];
    const float* REL   = (const float*)d_in[1];
    const float* MEMS  = (const float*)d_in[2];
    const float* AMASK = (const float*)d_in[3];
    const float* Wq = (const float*)d_in[4],  *bq = (const float*)d_in[5];
    const float* Wk = (const float*)d_in[6],  *bk = (const float*)d_in[7];
    const float* Wv = (const float*)d_in[8],  *bv = (const float*)d_in[9];
    const float* Wr = (const float*)d_in[10], *br = (const float*)d_in[11];
    const float* Wo = (const float*)d_in[12], *bo = (const float*)d_in[13];
    const float* u  = (const float*)d_in[14];
    const float* v  = (const float*)d_in[15];
    float* out = (float*)d_out;

    const int G_SMEM = 3 * GBUF;      // 73728
    const int S_SMEM = 5 * STB;       // 92160 (A + 2x(Bh+Bl))
    const int A_SMEM = 3 * ABUF;      // 110592
    cudaFuncSetAttribute(hm_proj_fused,   cudaFuncAttributeMaxDynamicSharedMemorySize, G_SMEM);
    cudaFuncSetAttribute(hm_gemm_o,       cudaFuncAttributeMaxDynamicSharedMemorySize, G_SMEM);
    cudaFuncSetAttribute(hm_scores_sweep, cudaFuncAttributeMaxDynamicSharedMemorySize, S_SMEM);
    cudaFuncSetAttribute(hm_attnv,        cudaFuncAttributeMaxDynamicSharedMemorySize, A_SMEM);

    __half *pREL, *pWh, *pWl;
    cudaGetSymbolAddress((void**)&pREL, g_REL);
    cudaGetSymbolAddress((void**)&pWh,  g_Wh);
    cudaGetSymbolAddress((void**)&pWl,  g_Wl);

    // 1. input conversions (fp16): KV gather, REL, weights hi/lo
    gather_kv_h<<<8192, 256>>>((const float4*)TE, (const float4*)MEMS);
    tohalf<<<2048, 256>>>((const float4*)REL, (__half2*)pREL, 524288);
    split5_w<<<dim3(1024, 5), 256>>>((const float4*)Wq, (const float4*)Wk, (const float4*)Wv,
                                     (const float4*)Wr, (const float4*)Wo,
                                     (__half2*)pWh, (__half2*)pWl);

    // 2. all four projections in ONE launch (wave-packed, 3-stage, fp16 2-term)
    hm_proj_fused<<<1408, 256, G_SMEM>>>(bq, bk, bv, br, u, v);

    // 3. j-sweep score GEMMs (AC + BD, pipelined, BD band-skip)
    hm_scores_sweep<<<1024, 256, S_SMEM>>>();

    // 4. rel-shift + mask + softmax over heads -> ATT (fp16), head-parallel
    softmax_heads<<<dim3(8, 1024, 4), 256>>>(AMASK);

    // 5. attn @ V (fp16 2-term, 3-stage) -> O1 single fp16
    hm_attnv<<<dim3(8, 64), 256, A_SMEM>>>();

    // 6. O projection -> d_out (fp32)
    hm_gemm_o<<<dim3(8, 32), 256, G_SMEM>>>(bo, out);

    // 7. mems_new
    if (out_size >= 12582912)
        write_mems<<<8192, 256>>>((const float4*)MEMS, (const float4*)out,
                                  (float4*)(out + 4194304));
}

// round 17
// speedup vs baseline: 2.0183x; 1.1270x over previous
#include <cuda_runtime.h>
#include <cuda_fp16.h>
#include <stdint.h>
#include <math.h>

// ---------------------------------------------------------------------------
// Problem constants: B=4, S=1024, H=1024, HEADS=16, HEAD_D=64, K=2048
// ---------------------------------------------------------------------------
#define PLANE 2097152ull   // 1024*2048

// ---------------- scratch ----------------
__device__ __half g_AC [(size_t)64 * PLANE];                 // fp16 score planes
__device__ __half g_BD [(size_t)64 * PLANE];
__device__ __half g_ATT[(size_t)64 * PLANE];                 // attn, single fp16

__device__ __half g_KV [(size_t)8192*1024];                  // single fp16
__device__ __half g_REL[(size_t)2048*1024];                  // single fp16
__device__ __half g_Wh [(size_t)5*1024*1024], g_Wl [(size_t)5*1024*1024];
__device__ __half g_QU [(size_t)4096*1024];                  // single fp16
__device__ __half g_QV [(size_t)4096*1024];                  // single fp16
__device__ __half g_K  [(size_t)8192*1024];                  // single fp16
__device__ __half g_R  [(size_t)2048*1024];                  // single fp16
__device__ __half g_V  [(size_t)8192*1024];                  // single fp16
__device__ __half g_O1 [(size_t)4096*1024];                  // single fp16

// ---------------------------------------------------------------------------
// Low-level helpers (sm_80-compatible: ldmatrix / mma.sync / cp.async)
// ---------------------------------------------------------------------------
__device__ __forceinline__ uint32_t smem_u32(const void* p) {
    uint32_t a;
    asm("{ .reg .u64 t; cvta.to.shared.u64 t, %1; cvt.u32.u64 %0, t; }"
        : "=r"(a) : "l"(p));
    return a;
}
__device__ __forceinline__ void ldsm4(uint32_t* r, uint32_t a) {
    asm volatile("ldmatrix.sync.aligned.m8n8.x4.shared.b16 {%0,%1,%2,%3}, [%4];"
        : "=r"(r[0]), "=r"(r[1]), "=r"(r[2]), "=r"(r[3]) : "r"(a));
}
__device__ __forceinline__ void ldsm4t(uint32_t* r, uint32_t a) {
    asm volatile("ldmatrix.sync.aligned.m8n8.x4.trans.shared.b16 {%0,%1,%2,%3}, [%4];"
        : "=r"(r[0]), "=r"(r[1]), "=r"(r[2]), "=r"(r[3]) : "r"(a));
}
__device__ __forceinline__ void mma16816h(float* c, const uint32_t* a, const uint32_t* b) {
    asm volatile(
        "mma.sync.aligned.m16n8k16.row.col.f32.f16.f16.f32 "
        "{%0,%1,%2,%3}, {%4,%5,%6,%7}, {%8,%9}, {%0,%1,%2,%3};"
        : "+f"(c[0]), "+f"(c[1]), "+f"(c[2]), "+f"(c[3])
        : "r"(a[0]), "r"(a[1]), "r"(a[2]), "r"(a[3]), "r"(b[0]), "r"(b[1]));
}
#define CP_ASYNC(dst, src) \
    asm volatile("cp.async.cg.shared.global [%0], [%1], 16;" :: "r"(dst), "l"(src))
#define CP_COMMIT() asm volatile("cp.async.commit_group;" ::: "memory")
#define CP_WAIT2()  asm volatile("cp.async.wait_group 2;" ::: "memory")
#define CP_WAIT1()  asm volatile("cp.async.wait_group 1;" ::: "memory")
#define CP_WAIT0()  asm volatile("cp.async.wait_group 0;" ::: "memory")

// GEMM tile swizzle: 64B rows (4 x 16B chunks), chunk permuted by row.
#define GSWZ(r) ((((r) ^ ((r) >> 2))) & 3)

__device__ __forceinline__ void split2h(float x, float y,
                                        __half2& h, __half2& l) {
    __half hx = __float2half_rn(x), hy = __float2half_rn(y);
    h = __halves2half2(hx, hy);
    l = __halves2half2(__float2half_rn(x - __half2float(hx)),
                       __float2half_rn(y - __half2float(hy)));
}

// ---------------------------------------------------------------------------
// fp32 -> single fp16 (generic)
// ---------------------------------------------------------------------------
__global__ void tohalf(const float4* __restrict__ in,
                       __half2* __restrict__ out, int n4)
{
    int i = blockIdx.x * blockDim.x + threadIdx.x;
    if (i >= n4) return;
    float4 x = in[i];
    out[i*2+0] = __halves2half2(__float2half_rn(x.x), __float2half_rn(x.y));
    out[i*2+1] = __halves2half2(__float2half_rn(x.z), __float2half_rn(x.w));
}

// split 5 weight matrices to fp16 hi/lo in one launch
__global__ void split5_w(const float4* w0, const float4* w1, const float4* w2,
                         const float4* w3, const float4* w4,
                         __half2* __restrict__ hi, __half2* __restrict__ lo)
{
    const float4* srcs[5] = {w0, w1, w2, w3, w4};
    int which = blockIdx.y;
    int i = blockIdx.x * blockDim.x + threadIdx.x;      // 0..262143
    float4 x = srcs[which][i];
    size_t d = (size_t)which * 524288 + (size_t)i * 2;
    __half2 h0, l0, h1, l1;
    split2h(x.x, x.y, h0, l0);
    split2h(x.z, x.w, h1, l1);
    hi[d] = h0; hi[d+1] = h1;
    lo[d] = l0; lo[d+1] = l1;
}

// gather kv_in (natural flat order row = b*2048+j) -> single fp16
__global__ void gather_kv_h(const float4* __restrict__ te,
                            const float4* __restrict__ mems)
{
    int idx = blockIdx.x * blockDim.x + threadIdx.x;    // 8192*256
    int row = idx >> 8, c = idx & 255;
    int b = row >> 11, j = row & 2047;
    float4 x;
    if (j < 1024) x = te  [((size_t)b * 1024 + j) * 256 + c];
    else          x = mems[((size_t)b * 2048 + (j - 1024)) * 256 + c];
    ((__half2*)g_KV)[idx*2+0] = __halves2half2(__float2half_rn(x.x), __float2half_rn(x.y));
    ((__half2*)g_KV)[idx*2+1] = __halves2half2(__float2half_rn(x.z), __float2half_rn(x.w));
}

// ---------------------------------------------------------------------------
// fp16 2-term HMMA GEMM core, 3-stage cp.async pipeline, swizzled tiles.
// C = A @ (Wh+Wl)^T + bias; A single fp16, W fp16 hi/lo; 2 MMAs per k-step.
// Epilogue modes: 0 = fp32+bias -> C; 1 = bias, single fp16 -> o1;
//                 2 = bias+u -> o1 (fp16), bias+v -> o2 (fp16).
// ---------------------------------------------------------------------------
#define GTB 8192
#define GBUF 24576

__device__ __forceinline__ void gemm_issue(
    uint32_t sb, int buf, int c, int tid,
    const __half* A, const __half* Wh, const __half* Wl,
    int m0, int n0, int remapA)
{
    const int k0 = c * 32;
    const uint32_t base = sb + buf * GBUF;
#pragma unroll
    for (int p = 0; p < 2; p++) {
        int ch = tid + p * 256;
        int r = ch >> 2, s = ch & 3;
        uint32_t d = base + (uint32_t)(r * 64 + ((s ^ GSWZ(r)) << 4));
        int arow = m0 + r;
        if (remapA) arow += (arow >> 10) << 10;
        size_t ga = (size_t)arow * 1024 + k0 + s * 8;
        size_t gw = (size_t)(n0 + r) * 1024 + k0 + s * 8;
        CP_ASYNC(d,         A  + ga);
        CP_ASYNC(d + GTB,   Wh + gw);
        CP_ASYNC(d + 2*GTB, Wl + gw);
    }
}

__device__ __forceinline__ void gemm_body(
    const __half* A, const __half* Wh, const __half* Wl,
    const float* bias, float* C,
    void* o1, void* o2,
    const float* addu, const float* addv,
    int mode, int remapA, int m0, int n0, __half* sm)
{
    const int tid = threadIdx.x, w = tid >> 5, lane = tid & 31;
    const int wm = (w & 1) * 64, wn = (w >> 1) * 32;
    const uint32_t sb = smem_u32(sm);
    const int lr = lane & 7, li = lane >> 3;

    float acc[4][4][4];
#pragma unroll
    for (int a = 0; a < 4; a++)
#pragma unroll
        for (int b = 0; b < 4; b++)
#pragma unroll
            for (int k = 0; k < 4; k++) acc[a][b][k] = 0.f;

    gemm_issue(sb, 0, 0, tid, A, Wh, Wl, m0, n0, remapA);
    CP_COMMIT();
    gemm_issue(sb, 1, 1, tid, A, Wh, Wl, m0, n0, remapA);
    CP_COMMIT();

    int bnext = 2, bcur = 0;
    for (int c = 0; c < 32; c++) {
        __syncthreads();
        if (c + 2 < 32) {
            gemm_issue(sb, bnext, c + 2, tid, A, Wh, Wl, m0, n0, remapA);
            CP_COMMIT();
            CP_WAIT2();
        } else if (c + 1 < 32) {
            CP_WAIT1();
        } else {
            CP_WAIT0();
        }
        __syncthreads();

        const uint32_t bb = sb + bcur * GBUF;
#pragma unroll
        for (int ks = 0; ks < 2; ks++) {
            const int sA = ks * 2 + (li >> 1);
            const int sB = ks * 2 + (li & 1);
            uint32_t ahf[4][4];
            const int arow0 = wm + (li & 1) * 8 + lr;
#pragma unroll
            for (int mt = 0; mt < 4; mt++) {
                int rowA = arow0 + mt * 16;
                uint32_t ao = bb + (uint32_t)(rowA * 64 + ((sA ^ GSWZ(rowA)) << 4));
                ldsm4(ahf[mt], ao);
            }
            uint32_t whf[2][4], wlf[2][4];
            const int brow0 = wn + (li >> 1) * 8 + lr;
#pragma unroll
            for (int nb = 0; nb < 2; nb++) {
                int rowB = brow0 + nb * 16;
                uint32_t bo = bb + GTB + (uint32_t)(rowB * 64 + ((sB ^ GSWZ(rowB)) << 4));
                ldsm4(whf[nb], bo);
                ldsm4(wlf[nb], bo + GTB);
            }
#pragma unroll
            for (int mt = 0; mt < 4; mt++)
#pragma unroll
                for (int nt = 0; nt < 4; nt++) {
                    const uint32_t* wh = &whf[nt >> 1][(nt & 1) * 2];
                    const uint32_t* wl = &wlf[nt >> 1][(nt & 1) * 2];
                    mma16816h(acc[mt][nt], ahf[mt], wh);
                    mma16816h(acc[mt][nt], ahf[mt], wl);
                }
        }
        bcur = (bcur == 2) ? 0 : bcur + 1;
        bnext = (bnext == 2) ? 0 : bnext + 1;
    }

#pragma unroll
    for (int mt = 0; mt < 4; mt++) {
        int m = m0 + wm + mt * 16 + (lane >> 2);
#pragma unroll
        for (int half = 0; half < 2; half++) {
            size_t mrow = (size_t)(m + half * 8);
#pragma unroll
            for (int nt = 0; nt < 4; nt++) {
                int col = wn + nt * 8 + (lane & 3) * 2;
                int cg = n0 + col;
                float x = acc[mt][nt][half*2+0] + bias[cg];
                float y = acc[mt][nt][half*2+1] + bias[cg+1];
                size_t d = (mrow * 1024 + cg) >> 1;
                if (mode == 0) {
                    *(float2*)(C + mrow * 1024 + cg) = make_float2(x, y);
                } else if (mode == 1) {
                    ((__half2*)o1)[d] = __halves2half2(
                        __float2half_rn(x), __float2half_rn(y));
                } else {
                    ((__half2*)o1)[d] = __halves2half2(
                        __float2half_rn(x + addu[cg]), __float2half_rn(y + addu[cg+1]));
                    ((__half2*)o2)[d] = __halves2half2(
                        __float2half_rn(x + addv[cg]), __float2half_rn(y + addv[cg+1]));
                }
            }
        }
    }
}

// Fused Q/K/V/R projection launch: flat blockIdx.x in [0, 1408)
__global__ void __launch_bounds__(256, 2) hm_proj_fused(
    const float* __restrict__ bq, const float* __restrict__ bk,
    const float* __restrict__ bv, const float* __restrict__ br,
    const float* __restrict__ u,  const float* __restrict__ v)
{
    extern __shared__ __half sm[];
    const size_t WSZ = (size_t)1024 * 1024;
    const int bid = blockIdx.x;

    if (bid < 512) {                        // K projection: M=8192
        int l = bid;
        gemm_body(g_KV, g_Wh + 1*WSZ, g_Wl + 1*WSZ, bk, nullptr,
                  g_K, nullptr, nullptr, nullptr,
                  1, 0, (l >> 3) * 128, (l & 7) * 128, sm);
    } else if (bid < 1024) {                // V projection: M=8192
        int l = bid - 512;
        gemm_body(g_KV, g_Wh + 2*WSZ, g_Wl + 2*WSZ, bv, nullptr,
                  g_V, nullptr, nullptr, nullptr,
                  1, 0, (l >> 3) * 128, (l & 7) * 128, sm);
    } else if (bid < 1280) {                // Q projection: M=4096, dual, remap
        int l = bid - 1024;
        gemm_body(g_KV, g_Wh + 0*WSZ, g_Wl + 0*WSZ, bq, nullptr,
                  g_QU, g_QV, u, v,
                  2, 1, (l >> 3) * 128, (l & 7) * 128, sm);
    } else {                                // R projection: M=2048
        int l = bid - 1280;
        gemm_body(g_REL, g_Wh + 3*WSZ, g_Wl + 3*WSZ, br, nullptr,
                  g_R, nullptr, nullptr, nullptr,
                  1, 0, (l >> 3) * 128, (l & 7) * 128, sm);
    }
}

// O projection (depends on attnv output)
__global__ void __launch_bounds__(256, 2) hm_gemm_o(
    const float* __restrict__ bo, float* __restrict__ C)
{
    extern __shared__ __half sm[];
    const size_t WSZ = (size_t)1024 * 1024;
    gemm_body(g_O1, g_Wh + 4*WSZ, g_Wl + 4*WSZ, bo, C,
              nullptr, nullptr, nullptr, nullptr,
              0, 0, blockIdx.y * 128, blockIdx.x * 128, sm);
}

// ---------------------------------------------------------------------------
// j-sweep scores kernel: one CTA = (zz, i-tile), sweeps 16 j-tiles with a
// 2-deep single-fp16 B pipeline; A tile resident. 1 MMA per k-step (B single).
//   mode0 (AC): C[i,j] = (q+u)[i,b,n,:]·k[j,b,n,:]
//   mode1 (BD): C[i,l] = (q+v)[i,b,n,:]·kr[l,n,:]; tiles i0/128+jc < 7 skipped.
// smem: A 18432 + 2 bufs x 18432 = 55296 B -> 2 CTA/SM.
// ---------------------------------------------------------------------------
#define SLD 72
#define STB 18432

__device__ __forceinline__ void sc_issue_B(
    uint32_t sb, int buf, int jc, int tid,
    const __half* B, int mode, int b, int n)
{
    const int j0 = jc * 128;
    const uint32_t base = sb + STB + buf * STB;
#pragma unroll
    for (int p = 0; p < 4; p++) {
        int ch = tid + p * 256;          // 0..1023
        int r = ch >> 3, s = ch & 7;
        uint32_t d = base + (uint32_t)(r * SLD + s * 8) * 2;
        size_t gb = mode ? ((size_t)(j0 + r) * 1024 + n * 64 + s * 8)
                         : (((size_t)(j0 + r) * 4 + b) * 1024 + n * 64 + s * 8);
        CP_ASYNC(d, B + gb);
    }
}

__global__ void __launch_bounds__(256, 2) hm_scores_sweep()
{
    extern __shared__ __half sm[];
    const int tid = threadIdx.x, w = tid >> 5, lane = tid & 31;
    const int bid = blockIdx.x;                 // 0..1023
    const int zz = bid >> 3;
    const int mode = zz >= 64;
    const int z = zz & 63, b = z >> 4, n = z & 15;
    const int i0 = (bid & 7) * 128;
    const int wm = (w & 1) * 64, wn = (w >> 1) * 32;
    const uint32_t sb = smem_u32(sm);
    const int lr = lane & 7, li = lane >> 3;

    const __half* A = mode ? g_QV : g_QU;
    const __half* B = mode ? g_R  : g_K;
    __half* Out = mode ? g_BD : g_AC;

    const int jc0 = mode ? max(0, 7 - (i0 >> 7)) : 0;

    // load A tile (resident) + first B tile in group 0
#pragma unroll
    for (int p = 0; p < 4; p++) {
        int ch = tid + p * 256;
        int r = ch >> 3, s = ch & 7;
        uint32_t d = sb + (uint32_t)(r * SLD + s * 8) * 2;
        size_t ga = ((size_t)(i0 + r) * 4 + b) * 1024 + n * 64 + s * 8;
        CP_ASYNC(d, A + ga);
    }
    sc_issue_B(sb, 0, jc0, tid, B, mode, b, n);
    CP_COMMIT();

    const size_t obase = (size_t)z * PLANE;
    for (int jc = jc0; jc < 16; jc++) {
        const int buf = (jc - jc0) & 1;
        if (jc + 1 < 16) {
            sc_issue_B(sb, buf ^ 1, jc + 1, tid, B, mode, b, n);
            CP_COMMIT();
            CP_WAIT1();
        } else {
            CP_WAIT0();
        }
        __syncthreads();

        float acc[4][4][4];
#pragma unroll
        for (int a = 0; a < 4; a++)
#pragma unroll
            for (int c = 0; c < 4; c++)
#pragma unroll
                for (int k = 0; k < 4; k++) acc[a][c][k] = 0.f;

        const uint32_t bB = sb + STB + buf * STB;
#pragma unroll
        for (int ks = 0; ks < 4; ks++) {
            uint32_t ahf[4][4];
            const uint32_t acol = (uint32_t)(ks * 16 + (li >> 1) * 8) * 2;
            const uint32_t arow0 = (uint32_t)(wm + (li & 1) * 8 + lr);
#pragma unroll
            for (int mt = 0; mt < 4; mt++) {
                uint32_t ao = sb + (arow0 + mt * 16) * (SLD * 2) + acol;
                ldsm4(ahf[mt], ao);
            }
            uint32_t bhf[2][4];
            const uint32_t bcol = (uint32_t)(ks * 16 + (li & 1) * 8) * 2;
            const uint32_t brow0 = (uint32_t)(wn + (li >> 1) * 8 + lr);
#pragma unroll
            for (int nb = 0; nb < 2; nb++) {
                uint32_t bo = bB + (brow0 + nb * 16) * (SLD * 2) + bcol;
                ldsm4(bhf[nb], bo);
            }
#pragma unroll
            for (int mt = 0; mt < 4; mt++)
#pragma unroll
                for (int nt = 0; nt < 4; nt++) {
                    const uint32_t* bh = &bhf[nt >> 1][(nt & 1) * 2];
                    mma16816h(acc[mt][nt], ahf[mt], bh);
                }
        }

        const int j0 = jc * 128;
#pragma unroll
        for (int mt = 0; mt < 4; mt++) {
            int row = i0 + wm + mt * 16 + (lane >> 2);
            __half* r0 = Out + obase + (size_t)row * 2048 + j0 + wn;
            __half* r8 = r0 + (size_t)8 * 2048;
#pragma unroll
            for (int nt = 0; nt < 4; nt++) {
                int col = nt * 8 + (lane & 3) * 2;
                *(__half2*)(r0 + col) = __halves2half2(
                    __float2half_rn(acc[mt][nt][0]), __float2half_rn(acc[mt][nt][1]));
                *(__half2*)(r8 + col) = __halves2half2(
                    __float2half_rn(acc[mt][nt][2]), __float2half_rn(acc[mt][nt][3]));
            }
        }
        __syncthreads();
    }
}

// ---------------------------------------------------------------------------
// Softmax over the 16-head axis, parallelized: 4 lanes x 4 heads each,
// butterfly shfl reductions.
// ---------------------------------------------------------------------------
__global__ void softmax_heads(const float* __restrict__ amask)
{
    const int tid = threadIdx.x;
    const int w = tid >> 5, lane = tid & 31;
    const int j4 = blockIdx.x * 64 + w * 8 + (lane >> 2);   // 0..511
    const int j  = j4 * 4;
    const int nq = lane & 3;
    const int i  = blockIdx.y;
    const int b  = blockIdx.z;
    const int ioff = 1023 - i;
    const float* amrow = amask + (size_t)(i >> 8) * 1024;
    const size_t base = ((size_t)b * 16 * 1024 + i) * 2048;

    float s[4][4];
    float mx[4] = {-1e30f, -1e30f, -1e30f, -1e30f};
#pragma unroll
    for (int nn = 0; nn < 4; nn++) {
        const int n = nq * 4 + nn;
        const __half* ACn = g_AC + base + (size_t)n * PLANE;
        uint2 raw = *(const uint2*)(ACn + j);
        __half2 a01 = *(__half2*)&raw.x;
        __half2 a23 = *(__half2*)&raw.y;
        float a[4] = { __low2float(a01), __high2float(a01),
                       __low2float(a23), __high2float(a23) };
        const __half* BDn = g_BD + base + (size_t)n * PLANE;
#pragma unroll
        for (int e = 0; e < 4; e++) {
            int l = j + e + ioff;
            float bd = (l < 2048) ? __half2float(BDn[l]) : 0.f;
            float val = (a[e] + bd) * 0.125f;
            int jp = ((j + e) * 64 + b * 16 + n) & 2047;
            float m = (jp < 1024) ? 1.f : amrow[jp - 1024];
            val -= (1.f - m) * 1e9f;
            s[nn][e] = val;
            mx[e] = fmaxf(mx[e], val);
        }
    }
#pragma unroll
    for (int e = 0; e < 4; e++) {
        mx[e] = fmaxf(mx[e], __shfl_xor_sync(0xFFFFFFFFu, mx[e], 1));
        mx[e] = fmaxf(mx[e], __shfl_xor_sync(0xFFFFFFFFu, mx[e], 2));
    }
    float sum[4] = {0.f, 0.f, 0.f, 0.f};
#pragma unroll
    for (int nn = 0; nn < 4; nn++)
#pragma unroll
        for (int e = 0; e < 4; e++) {
            s[nn][e] = __expf(s[nn][e] - mx[e]);
            sum[e] += s[nn][e];
        }
#pragma unroll
    for (int e = 0; e < 4; e++) {
        sum[e] += __shfl_xor_sync(0xFFFFFFFFu, sum[e], 1);
        sum[e] += __shfl_xor_sync(0xFFFFFFFFu, sum[e], 2);
    }
    float inv[4] = {1.f/sum[0], 1.f/sum[1], 1.f/sum[2], 1.f/sum[3]};
#pragma unroll
    for (int nn = 0; nn < 4; nn++) {
        const int n = nq * 4 + nn;
        __half2 p0 = __halves2half2(__float2half_rn(s[nn][0] * inv[0]),
                                    __float2half_rn(s[nn][1] * inv[1]));
        __half2 p1 = __halves2half2(__float2half_rn(s[nn][2] * inv[2]),
                                    __float2half_rn(s[nn][3] * inv[3]));
        size_t el = base + (size_t)n * PLANE + j;
        *(uint2*)(g_ATT + el) = make_uint2(*(const uint32_t*)&p0,
                                           *(const uint32_t*)&p1);
    }
}

// ---------------------------------------------------------------------------
// HMMA attn@V, single-fp16 both sides: 1 MMA per k-step. Writes O1 fp16.
// 3-stage pipeline. buf: ATT 18432 + V 9216 = 27648; x3 = 82944 B
// ---------------------------------------------------------------------------
#define ABUF 27648

__device__ __forceinline__ void attnv_issue(
    uint32_t sb, int buf, int c, int tid, int i0, int b, int n, size_t zbase)
{
    const uint32_t base = sb + buf * ABUF;
#pragma unroll
    for (int p = 0; p < 4; p++) {
        int ch = tid + p * 256;          // 0..1023
        int r = ch >> 3, s = ch & 7;
        uint32_t d = base + (uint32_t)(r * SLD + s * 8) * 2;
        size_t g = zbase + (size_t)(i0 + r) * 2048 + c * 64 + s * 8;
        CP_ASYNC(d, g_ATT + g);
    }
#pragma unroll
    for (int p = 0; p < 2; p++) {
        int ch = tid + p * 256;          // 0..511
        int r = ch >> 3, s = ch & 7;
        uint32_t d = base + STB + (uint32_t)(r * SLD + s * 8) * 2;
        size_t g = ((size_t)(c * 64 + r) * 4 + b) * 1024 + n * 64 + s * 8;
        CP_ASYNC(d, g_V + g);
    }
}

__global__ void __launch_bounds__(256, 2) hm_attnv()
{
    extern __shared__ __half sm[];
    const int tid = threadIdx.x, w = tid >> 5, lane = tid & 31;
    const int z = blockIdx.y, b = z >> 4, n = z & 15;
    const int i0 = blockIdx.x * 128;
    const int wm = (w & 3) * 32, wn = (w >> 2) * 32;
    const size_t zbase = (size_t)z * PLANE;
    const uint32_t sb = smem_u32(sm);
    const int lr = lane & 7, li = lane >> 3;

    float acc[2][4][4];
#pragma unroll
    for (int a = 0; a < 2; a++)
#pragma unroll
        for (int c = 0; c < 4; c++)
#pragma unroll
            for (int k = 0; k < 4; k++) acc[a][c][k] = 0.f;

    attnv_issue(sb, 0, 0, tid, i0, b, n, zbase);
    CP_COMMIT();
    attnv_issue(sb, 1, 1, tid, i0, b, n, zbase);
    CP_COMMIT();

    int bcur = 0, bnext = 2;
    for (int c = 0; c < 32; c++) {
        __syncthreads();
        if (c + 2 < 32) {
            attnv_issue(sb, bnext, c + 2, tid, i0, b, n, zbase);
            CP_COMMIT();
            CP_WAIT2();
        } else if (c + 1 < 32) {
            CP_WAIT1();
        } else {
            CP_WAIT0();
        }
        __syncthreads();

        const uint32_t bb = sb + bcur * ABUF;
#pragma unroll
        for (int ks = 0; ks < 4; ks++) {
            uint32_t ahf[2][4];
            const uint32_t acol = (uint32_t)(ks * 16 + (li >> 1) * 8) * 2;
            const uint32_t arow0 = (uint32_t)(wm + (li & 1) * 8 + lr);
#pragma unroll
            for (int mt = 0; mt < 2; mt++) {
                uint32_t ao = bb + (arow0 + mt * 16) * (SLD * 2) + acol;
                ldsm4(ahf[mt], ao);
            }
            uint32_t bhf[2][4];
            const uint32_t vrow0 = (uint32_t)(ks * 16 + (li & 1) * 8 + lr);
#pragma unroll
            for (int nb = 0; nb < 2; nb++) {
                uint32_t vcol = (uint32_t)(wn + nb * 16 + (li >> 1) * 8) * 2;
                uint32_t bo = bb + STB + vrow0 * (SLD * 2) + vcol;
                ldsm4t(bhf[nb], bo);
            }
#pragma unroll
            for (int mt = 0; mt < 2; mt++)
#pragma unroll
                for (int nt = 0; nt < 4; nt++) {
                    const uint32_t* bh = &bhf[nt >> 1][(nt & 1) * 2];
                    mma16816h(acc[mt][nt], ahf[mt], bh);
                }
        }
        bcur = (bcur == 2) ? 0 : bcur + 1;
        bnext = (bnext == 2) ? 0 : bnext + 1;
    }

#pragma unroll
    for (int mt = 0; mt < 2; mt++) {
        int i = i0 + wm + mt * 16 + (lane >> 2);
#pragma unroll
        for (int half = 0; half < 2; half++) {
            size_t rbase = ((size_t)(i + half * 8) * 4 + b) * 1024 + n * 64;
#pragma unroll
            for (int nt = 0; nt < 4; nt++) {
                int col = wn + nt * 8 + (lane & 3) * 2;
                size_t d = (rbase + col) >> 1;
                ((__half2*)g_O1)[d] = __halves2half2(
                    __float2half_rn(acc[mt][nt][half*2+0]),
                    __float2half_rn(acc[mt][nt][half*2+1]));
            }
        }
    }
}

// ---------------------------------------------------------------------------
__global__ void write_mems(const float4* __restrict__ mems,
                           const float4* __restrict__ out,
                           float4* __restrict__ dst)
{
    int idx = blockIdx.x * blockDim.x + threadIdx.x;
    int row = idx >> 8, c = idx & 255;
    int b = row >> 11, pos = row & 2047;
    float4 v;
    if (pos < 1024) v = mems[idx];
    else            v = out[(((size_t)b * 1024) + (pos - 1024)) * 256 + c];
    dst[idx] = v;
}

// ---------------------------------------------------------------------------
extern "C" void kernel_launch(void* const* d_in, const int* in_sizes, int n_in,
                              void* d_out, int out_size)
{
    const float* TE    = (const float*)d_in[0];
    const float* REL   = (const float*)d_in[1];
    const float* MEMS  = (const float*)d_in[2];
    const float* AMASK = (const float*)d_in[3];
    const float* Wq = (const float*)d_in[4],  *bq = (const float*)d_in[5];
    const float* Wk = (const float*)d_in[6],  *bk = (const float*)d_in[7];
    const float* Wv = (const float*)d_in[8],  *bv = (const float*)d_in[9];
    const float* Wr = (const float*)d_in[10], *br = (const float*)d_in[11];
    const float* Wo = (const float*)d_in[12], *bo = (const float*)d_in[13];
    const float* u  = (const float*)d_in[14];
    const float* v  = (const float*)d_in[15];
    float* out = (float*)d_out;

    const int G_SMEM = 3 * GBUF;      // 73728
    const int S_SMEM = 3 * STB;       // 55296 (A + 2xB)
    const int A_SMEM = 3 * ABUF;      // 82944
    cudaFuncSetAttribute(hm_proj_fused,   cudaFuncAttributeMaxDynamicSharedMemorySize, G_SMEM);
    cudaFuncSetAttribute(hm_gemm_o,       cudaFuncAttributeMaxDynamicSharedMemorySize, G_SMEM);
    cudaFuncSetAttribute(hm_scores_sweep, cudaFuncAttributeMaxDynamicSharedMemorySize, S_SMEM);
    cudaFuncSetAttribute(hm_attnv,        cudaFuncAttributeMaxDynamicSharedMemorySize, A_SMEM);

    __half *pREL, *pWh, *pWl;
    cudaGetSymbolAddress((void**)&pREL, g_REL);
    cudaGetSymbolAddress((void**)&pWh,  g_Wh);
    cudaGetSymbolAddress((void**)&pWl,  g_Wl);

    // 1. input conversions (fp16): KV gather, REL, weights hi/lo
    gather_kv_h<<<8192, 256>>>((const float4*)TE, (const float4*)MEMS);
    tohalf<<<2048, 256>>>((const float4*)REL, (__half2*)pREL, 524288);
    split5_w<<<dim3(1024, 5), 256>>>((const float4*)Wq, (const float4*)Wk, (const float4*)Wv,
                                     (const float4*)Wr, (const float4*)Wo,
                                     (__half2*)pWh, (__half2*)pWl);

    // 2. all four projections in ONE launch (wave-packed, 3-stage, fp16 2-term)
    hm_proj_fused<<<1408, 256, G_SMEM>>>(bq, bk, bv, br, u, v);

    // 3. j-sweep score GEMMs (single-fp16 B, 1 MMA/k-step, BD band-skip)
    hm_scores_sweep<<<1024, 256, S_SMEM>>>();

    // 4. rel-shift + mask + softmax over heads -> ATT (fp16), head-parallel
    softmax_heads<<<dim3(8, 1024, 4), 256>>>(AMASK);

    // 5. attn @ V (single-fp16, 1 MMA/k-step, 3-stage) -> O1 fp16
    hm_attnv<<<dim3(8, 64), 256, A_SMEM>>>();

    // 6. O projection -> d_out (fp32)
    hm_gemm_o<<<dim3(8, 32), 256, G_SMEM>>>(bo, out);

    // 7. mems_new
    if (out_size >= 12582912)
        write_mems<<<8192, 256>>>((const float4*)MEMS, (const float4*)out,
                                  (float4*)(out + 4194304));
}